// round 6
// baseline (speedup 1.0000x reference)
#include <cuda_runtime.h>
#include <cuda_bf16.h>
#include <cstdint>

// Problem constants (fixed shapes per reference setup_inputs)
#define Bn      8
#define Nn      8192
#define Cn      64
#define NP      2048
#define NS      32
#define CIN     67
#define H1n     64
#define H2n     128
#define RADIUS2 0.01f

// Scratch (allocation-free rule: __device__ globals)
__device__ int    g_idx[Bn * NP * NS];              // 2 MB
__device__ float  g_featT[(size_t)Bn * Nn * Cn];    // 16 MB, (B,N,C)
__device__ float4 g_xyz4[Bn * Nn];                  // 1 MB packed xyz

typedef unsigned long long ull;

// ---------------------------------------------------------------------------
// tf32 / mma / ldmatrix helpers
// ---------------------------------------------------------------------------
__device__ __forceinline__ unsigned f2tf32(float f)
{
    unsigned u;
    asm("cvt.rna.tf32.f32 %0, %1;" : "=r"(u) : "f"(f));
    return u;
}

__device__ __forceinline__ void mma_tf32(float c[4], const unsigned a[4], const unsigned b[2])
{
    asm volatile(
        "mma.sync.aligned.m16n8k8.row.col.f32.tf32.tf32.f32 "
        "{%0,%1,%2,%3}, {%4,%5,%6,%7}, {%8,%9}, {%0,%1,%2,%3};"
        : "+f"(c[0]), "+f"(c[1]), "+f"(c[2]), "+f"(c[3])
        : "r"(a[0]), "r"(a[1]), "r"(a[2]), "r"(a[3]), "r"(b[0]), "r"(b[1]));
}

__device__ __forceinline__ void ldsm4(unsigned r[4], unsigned addr)
{
    asm volatile("ldmatrix.sync.aligned.m8n8.x4.shared.b16 {%0,%1,%2,%3}, [%4];"
                 : "=r"(r[0]), "=r"(r[1]), "=r"(r[2]), "=r"(r[3]) : "r"(addr));
}

// ---------------------------------------------------------------------------
// Kernel 0: pack xyz (B,N,3) -> float4 (w=0) for 1-LDG ball query
// ---------------------------------------------------------------------------
__global__ void pack_kernel(const float* __restrict__ xyz, float4* __restrict__ p)
{
    int t = blockIdx.x * blockDim.x + threadIdx.x;
    if (t < Bn * Nn)
        p[t] = make_float4(xyz[t * 3 + 0], xyz[t * 3 + 1], xyz[t * 3 + 2], 0.0f);
}

// ---------------------------------------------------------------------------
// Kernel 1: ball query (one warp per query) + fused new_xyz copy.
// ---------------------------------------------------------------------------
__global__ void bq_kernel(const float4* __restrict__ xyz4, int* __restrict__ out_idx,
                          float* __restrict__ out)
{
    int warp = (blockIdx.x * blockDim.x + threadIdx.x) >> 5;
    int lane = threadIdx.x & 31;
    if (warp >= Bn * NP) return;
    int b = warp / NP;
    int s = warp - b * NP;

    const float4* xb = xyz4 + (size_t)b * Nn;
    float4 qp = __ldg(&xb[s]);

    if (lane < 3) {
        float v = (lane == 0) ? qp.x : (lane == 1) ? qp.y : qp.z;
        out[(size_t)warp * 3 + lane] = v;
    }

    int* outp = out_idx + (size_t)warp * NS;
    int cnt = 0;
    int first_idx = 0;

    for (int base = 0; base < Nn; base += 32) {
        int i = base + lane;
        float4 p = __ldg(&xb[i]);
        float dx = p.x - qp.x, dy = p.y - qp.y, dz = p.z - qp.z;
        float d2 = dx * dx + dy * dy + dz * dz;
        unsigned bits = __ballot_sync(0xffffffffu, d2 < RADIUS2);
        if (bits) {
            if (cnt == 0) first_idx = base + __ffs(bits) - 1;
            if ((bits >> lane) & 1u) {
                int pos = cnt + __popc(bits & ((1u << lane) - 1u));
                if (pos < NS) outp[pos] = i;
            }
            cnt += __popc(bits);
            if (cnt >= NS) break;
        }
    }
    if (cnt < NS) {
        int slot = cnt + lane;
        if (slot < NS) outp[slot] = first_idx;
    }
}

// ---------------------------------------------------------------------------
// Kernel 2: transpose features (B,C,N) -> (B,N,C) so gathers are contiguous.
// ---------------------------------------------------------------------------
__global__ void transpose_kernel(const float* __restrict__ f, float* __restrict__ ft)
{
    __shared__ float tile[32][33];
    int b  = blockIdx.z;
    int c0 = blockIdx.y * 32;
    int n0 = blockIdx.x * 32;
    int tx = threadIdx.x, ty = threadIdx.y;

    const float* fb = f + (size_t)b * Cn * Nn;
    tile[ty][tx] = fb[(size_t)(c0 + ty) * Nn + (n0 + tx)];
    __syncthreads();
    ft[(size_t)b * Nn * Cn + (size_t)(n0 + ty) * Cn + (c0 + tx)] = tile[tx][ty];
}

// ---------------------------------------------------------------------------
// Kernel 3: fused group + MLP(67->64->128) + max; tf32 mma + ldmatrix.
//
// Block: 256 threads = 8 warps; warp w owns query w (32 rows).
// smem (32-bit words):
//   A   [256][76]  row-major tf32 (k 0..66 data, 67..75 zero); per-warp
//                  aliased by h1 [row][k 0..63] between layers.
//   W1s [64][76]   [o][k] tf32, zero-padded
//   W2s [128][68]  [o][k] tf32, zero-padded
//   b1s[64], b2s[128] f32
// ldmatrix conflict check (16B-chunk group = (words/4) mod 8):
//   A/W1 stride 76: 19r mod 8 = {0,3,6,1,4,7,2,5} distinct. W2 stride 68:
//   17r mod 8 = r. All conflict-free.
// ---------------------------------------------------------------------------
#define A_STR   76
#define W1_STR  76
#define W2_STR  68
#define A_OFF   0
#define W1_OFF  (256 * A_STR)               // 19456
#define W2_OFF  (W1_OFF + 64 * W1_STR)      // 24320
#define B1_OFF  (W2_OFF + 128 * W2_STR)     // 33024
#define B2_OFF  (B1_OFF + 64)
#define SMEM_WORDS (B2_OFF + 128)           // 33216 words = 132864 B

__global__ __launch_bounds__(256, 1) void mlp_kernel(
    const float* __restrict__ xyz,
    const int*   __restrict__ idx,
    const float* __restrict__ W1,
    const float* __restrict__ b1,
    const float* __restrict__ W2,
    const float* __restrict__ b2,
    float* __restrict__ out)
{
    extern __shared__ unsigned sm[];
    unsigned* A   = sm + A_OFF;
    unsigned* w1s = sm + W1_OFF;
    unsigned* w2s = sm + W2_OFF;
    float* b1s = (float*)(sm + B1_OFF);
    float* b2s = (float*)(sm + B2_OFF);

    const unsigned smb = (unsigned)__cvta_generic_to_shared(sm);

    const int tid  = threadIdx.x;
    const int lane = tid & 31;
    const int q    = tid >> 5;
    const int kk   = lane & 3;
    const int r    = lane >> 2;

    // ---- stage weights ----
    for (int i = tid; i < 64 * W1_STR; i += 256) {
        int o = i / W1_STR, k = i - o * W1_STR;
        w1s[i] = (k < CIN) ? f2tf32(__ldg(&W1[o * CIN + k])) : 0u;
    }
    for (int i = tid; i < 128 * W2_STR; i += 256) {
        int o = i / W2_STR, k = i - o * W2_STR;
        w2s[i] = (k < H1n) ? f2tf32(__ldg(&W2[o * H1n + k])) : 0u;
    }
    if (tid < 64)  b1s[tid] = b1[tid];
    if (tid < 128) b2s[tid] = b2[tid];

    // ---- stage A tile: one row per thread, row-major ----
    {
        const int gq = blockIdx.x * 8 + q;
        const int b  = gq >> 11;            // NP = 2048
        const int s  = gq & (NP - 1);
        const int id = idx[(size_t)gq * NS + lane];
        const float* xb = xyz + (size_t)b * Nn * 3;

        unsigned* arow = A + tid * A_STR;
        arow[0] = f2tf32(__ldg(&xb[id * 3 + 0]) - __ldg(&xb[s * 3 + 0]));
        arow[1] = f2tf32(__ldg(&xb[id * 3 + 1]) - __ldg(&xb[s * 3 + 1]));
        arow[2] = f2tf32(__ldg(&xb[id * 3 + 2]) - __ldg(&xb[s * 3 + 2]));
        const float4* fp = (const float4*)(g_featT + ((size_t)b * Nn + id) * Cn);
        #pragma unroll
        for (int k4 = 0; k4 < 16; k4++) {
            float4 v = __ldg(&fp[k4]);
            arow[3 + 4 * k4 + 0] = f2tf32(v.x);
            arow[3 + 4 * k4 + 1] = f2tf32(v.y);
            arow[3 + 4 * k4 + 2] = f2tf32(v.z);
            arow[3 + 4 * k4 + 3] = f2tf32(v.w);
        }
        #pragma unroll
        for (int k = 67; k < 76; k++) arow[k] = 0u;
    }
    __syncthreads();

    const int rowbase = q * 32;

    // ldmatrix lane address offsets
    const int a_row = (lane & 7) + ((lane >> 3) & 1) * 8;   // within 16-row tile
    const int a_col = (lane >> 4) * 4;                      // k half
    const int b_row = (lane & 7) + ((lane >> 4) & 1) * 8;   // within 16 n-rows
    const int b_col = ((lane >> 3) & 1) * 4;

    const unsigned aBase0 = smb + (unsigned)((A_OFF + (rowbase + a_row) * A_STR + a_col) * 4);
    const unsigned aBase1 = aBase0 + 16 * A_STR * 4;
    const unsigned w1Base = smb + (unsigned)((W1_OFF + b_row * W1_STR + b_col) * 4);
    const unsigned w2Base = smb + (unsigned)((W2_OFF + b_row * W2_STR + b_col) * 4);

    // ---- Layer 1: c1 = A . W1^T + b1 ----
    float c1[2][8][4];
    #pragma unroll
    for (int nt = 0; nt < 8; nt++) {
        float blo = b1s[nt * 8 + 2 * kk];
        float bhi = b1s[nt * 8 + 2 * kk + 1];
        #pragma unroll
        for (int mt = 0; mt < 2; mt++) {
            c1[mt][nt][0] = blo; c1[mt][nt][1] = bhi;
            c1[mt][nt][2] = blo; c1[mt][nt][3] = bhi;
        }
    }

    #pragma unroll
    for (int kg = 0; kg < 9; kg++) {
        unsigned a0[4], a1[4];
        ldsm4(a0, aBase0 + kg * 32);
        ldsm4(a1, aBase1 + kg * 32);
        #pragma unroll
        for (int p = 0; p < 4; p++) {
            unsigned bf[4];
            ldsm4(bf, w1Base + (unsigned)(16 * p * W1_STR * 4) + kg * 32);
            mma_tf32(c1[0][2 * p],     a0, bf);       // bf[0],bf[1]
            mma_tf32(c1[0][2 * p + 1], a0, bf + 2);
            mma_tf32(c1[1][2 * p],     a1, bf);
            mma_tf32(c1[1][2 * p + 1], a1, bf + 2);
        }
    }
    __syncwarp();

    // ---- store relu(h1) row-major into warp-local A rows (alias) ----
    #pragma unroll
    for (int mt = 0; mt < 2; mt++)
        #pragma unroll
        for (int nt = 0; nt < 8; nt++)
            #pragma unroll
            for (int i = 0; i < 2; i++) {
                int row = rowbase + mt * 16 + r + 8 * i;
                unsigned lo = f2tf32(fmaxf(c1[mt][nt][2 * i + 0], 0.0f));
                unsigned hi = f2tf32(fmaxf(c1[mt][nt][2 * i + 1], 0.0f));
                ull p = (ull)lo | ((ull)hi << 32);
                *(ull*)&A[row * A_STR + nt * 8 + 2 * kk] = p;
            }
    __syncwarp();

    // ---- Layer 2: c2 = h1 . W2^T + b2 ----
    float c2[2][16][4];
    #pragma unroll
    for (int nt = 0; nt < 16; nt++) {
        float blo = b2s[nt * 8 + 2 * kk];
        float bhi = b2s[nt * 8 + 2 * kk + 1];
        #pragma unroll
        for (int mt = 0; mt < 2; mt++) {
            c2[mt][nt][0] = blo; c2[mt][nt][1] = bhi;
            c2[mt][nt][2] = blo; c2[mt][nt][3] = bhi;
        }
    }

    #pragma unroll
    for (int kg = 0; kg < 8; kg++) {
        unsigned a0[4], a1[4];
        ldsm4(a0, aBase0 + kg * 32);
        ldsm4(a1, aBase1 + kg * 32);
        #pragma unroll
        for (int p = 0; p < 8; p++) {
            unsigned bf[4];
            ldsm4(bf, w2Base + (unsigned)(16 * p * W2_STR * 4) + kg * 32);
            mma_tf32(c2[0][2 * p],     a0, bf);
            mma_tf32(c2[0][2 * p + 1], a0, bf + 2);
            mma_tf32(c2[1][2 * p],     a1, bf);
            mma_tf32(c2[1][2 * p + 1], a1, bf + 2);
        }
    }

    // ---- max over 32 rows + relu + write ----
    {
        const int gq = blockIdx.x * 8 + q;
        const int b  = gq >> 11;
        const int s  = gq & (NP - 1);
        float* op_base = out + (Bn * NP * 3) + (size_t)b * H2n * NP + s;

        #pragma unroll
        for (int nt = 0; nt < 16; nt++)
            #pragma unroll
            for (int j = 0; j < 2; j++) {
                float v = fmaxf(fmaxf(c2[0][nt][j], c2[0][nt][j + 2]),
                                fmaxf(c2[1][nt][j], c2[1][nt][j + 2]));
                v = fmaxf(v, __shfl_xor_sync(0xffffffffu, v, 4));
                v = fmaxf(v, __shfl_xor_sync(0xffffffffu, v, 8));
                v = fmaxf(v, __shfl_xor_sync(0xffffffffu, v, 16));
                if (r == 0) {
                    int col = nt * 8 + 2 * kk + j;
                    op_base[(size_t)col * NP] = fmaxf(v, 0.0f);
                }
            }
    }
}

// ---------------------------------------------------------------------------
extern "C" void kernel_launch(void* const* d_in, const int* in_sizes, int n_in,
                              void* d_out, int out_size)
{
    const float* xyz      = (const float*)d_in[0];
    const float* features = (const float*)d_in[1];
    const float* W1       = (const float*)d_in[2];
    const float* b1       = (const float*)d_in[3];
    const float* W2       = (const float*)d_in[4];
    const float* b2       = (const float*)d_in[5];
    float* out = (float*)d_out;

    static bool attr_set = false;
    if (!attr_set) {
        cudaFuncSetAttribute(mlp_kernel, cudaFuncAttributeMaxDynamicSharedMemorySize,
                             SMEM_WORDS * (int)sizeof(unsigned));
        attr_set = true;
    }

    int*    idxp;
    float*  ftp;
    float4* x4p;
    cudaGetSymbolAddress((void**)&idxp, g_idx);
    cudaGetSymbolAddress((void**)&ftp, g_featT);
    cudaGetSymbolAddress((void**)&x4p, g_xyz4);

    // 0) pack xyz -> float4
    pack_kernel<<<(Bn * Nn + 255) / 256, 256>>>(xyz, x4p);
    // 1) transpose features (B,C,N)->(B,N,C)
    {
        dim3 blk(32, 32, 1);
        dim3 grd(Nn / 32, Cn / 32, Bn);
        transpose_kernel<<<grd, blk>>>(features, ftp);
    }
    // 2) ball query + new_xyz copy
    {
        int warps = Bn * NP;
        int threads = 256;
        int blocks = (warps * 32 + threads - 1) / threads;
        bq_kernel<<<blocks, threads>>>(x4p, idxp, out);
    }
    // 3) fused group + MLP + max (tf32 mma + ldmatrix)
    {
        int blocks = (Bn * NP) / 8;
        mlp_kernel<<<blocks, 256, SMEM_WORDS * (int)sizeof(unsigned)>>>(
            xyz, idxp, W1, b1, W2, b2, out);
    }
}

// round 7
// speedup vs baseline: 1.1130x; 1.1130x over previous
#include <cuda_runtime.h>
#include <cuda_bf16.h>
#include <cstdint>

// Problem constants (fixed shapes per reference setup_inputs)
#define Bn      8
#define Nn      8192
#define Cn      64
#define NP      2048
#define NS      32
#define CIN     67
#define H1n     64
#define H2n     128
#define RADIUS2 0.01f

// Scratch (allocation-free rule: __device__ globals)
__device__ int    g_idx[Bn * NP * NS];              // 2 MB
__device__ float  g_featT[(size_t)Bn * Nn * Cn];    // 16 MB, (B,N,C)
__device__ float4 g_xyz4[Bn * Nn];                  // 1 MB packed xyz

typedef unsigned long long ull;

// ---------------------------------------------------------------------------
// tf32 / mma / ldmatrix helpers
// ---------------------------------------------------------------------------
__device__ __forceinline__ unsigned f2tf32(float f)
{
    unsigned u;
    asm("cvt.rna.tf32.f32 %0, %1;" : "=r"(u) : "f"(f));
    return u;
}

__device__ __forceinline__ void mma_tf32(float c[4], const unsigned a[4], const unsigned b[2])
{
    asm volatile(
        "mma.sync.aligned.m16n8k8.row.col.f32.tf32.tf32.f32 "
        "{%0,%1,%2,%3}, {%4,%5,%6,%7}, {%8,%9}, {%0,%1,%2,%3};"
        : "+f"(c[0]), "+f"(c[1]), "+f"(c[2]), "+f"(c[3])
        : "r"(a[0]), "r"(a[1]), "r"(a[2]), "r"(a[3]), "r"(b[0]), "r"(b[1]));
}

__device__ __forceinline__ void ldsm4(unsigned r[4], unsigned addr)
{
    asm volatile("ldmatrix.sync.aligned.m8n8.x4.shared.b16 {%0,%1,%2,%3}, [%4];"
                 : "=r"(r[0]), "=r"(r[1]), "=r"(r[2]), "=r"(r[3]) : "r"(addr));
}

// ---------------------------------------------------------------------------
// Kernel 0: pack xyz (B,N,3) -> float4 (w=0) for 1-LDG ball query
// ---------------------------------------------------------------------------
__global__ void pack_kernel(const float* __restrict__ xyz, float4* __restrict__ p)
{
    int t = blockIdx.x * blockDim.x + threadIdx.x;
    if (t < Bn * Nn)
        p[t] = make_float4(xyz[t * 3 + 0], xyz[t * 3 + 1], xyz[t * 3 + 2], 0.0f);
}

// ---------------------------------------------------------------------------
// Kernel 1: ball query (one warp per query) + fused new_xyz copy.
// ---------------------------------------------------------------------------
__global__ void bq_kernel(const float4* __restrict__ xyz4, int* __restrict__ out_idx,
                          float* __restrict__ out)
{
    int warp = (blockIdx.x * blockDim.x + threadIdx.x) >> 5;
    int lane = threadIdx.x & 31;
    if (warp >= Bn * NP) return;
    int b = warp / NP;
    int s = warp - b * NP;

    const float4* xb = xyz4 + (size_t)b * Nn;
    float4 qp = __ldg(&xb[s]);

    if (lane < 3) {
        float v = (lane == 0) ? qp.x : (lane == 1) ? qp.y : qp.z;
        out[(size_t)warp * 3 + lane] = v;
    }

    int* outp = out_idx + (size_t)warp * NS;
    int cnt = 0;
    int first_idx = 0;

    for (int base = 0; base < Nn; base += 32) {
        int i = base + lane;
        float4 p = __ldg(&xb[i]);
        float dx = p.x - qp.x, dy = p.y - qp.y, dz = p.z - qp.z;
        float d2 = dx * dx + dy * dy + dz * dz;
        unsigned bits = __ballot_sync(0xffffffffu, d2 < RADIUS2);
        if (bits) {
            if (cnt == 0) first_idx = base + __ffs(bits) - 1;
            if ((bits >> lane) & 1u) {
                int pos = cnt + __popc(bits & ((1u << lane) - 1u));
                if (pos < NS) outp[pos] = i;
            }
            cnt += __popc(bits);
            if (cnt >= NS) break;
        }
    }
    if (cnt < NS) {
        int slot = cnt + lane;
        if (slot < NS) outp[slot] = first_idx;
    }
}

// ---------------------------------------------------------------------------
// Kernel 2: transpose features (B,C,N) -> (B,N,C) so gathers are contiguous.
// ---------------------------------------------------------------------------
__global__ void transpose_kernel(const float* __restrict__ f, float* __restrict__ ft)
{
    __shared__ float tile[32][33];
    int b  = blockIdx.z;
    int c0 = blockIdx.y * 32;
    int n0 = blockIdx.x * 32;
    int tx = threadIdx.x, ty = threadIdx.y;

    const float* fb = f + (size_t)b * Cn * Nn;
    tile[ty][tx] = fb[(size_t)(c0 + ty) * Nn + (n0 + tx)];
    __syncthreads();
    ft[(size_t)b * Nn * Cn + (size_t)(n0 + ty) * Cn + (c0 + tx)] = tile[tx][ty];
}

// ---------------------------------------------------------------------------
// Kernel 3: fused group + MLP(67->64->128) + max; tf32 mma + ldmatrix.
//
// Block: 512 threads = 16 warps; warp w owns query w (32 rows).
// Layer 2 split into two 64-output halves to cap live accumulators
// (128-reg budget for 512 threads/CTA).
//
// smem (32-bit words):
//   A   [512][76]  row-major tf32 (k 0..66 data, 67..75 zero); per-warp
//                  aliased by h1 [row][k 0..63] between layers.
//   W1s [64][76]   [o][k] tf32, zero-padded
//   W2s [128][68]  [o][k] tf32, zero-padded
//   b1s[64], b2s[128] f32
// ldmatrix 16B-chunk groups: stride76 -> 19r mod 8 distinct; stride68 -> r.
// ---------------------------------------------------------------------------
#define A_STR   76
#define W1_STR  76
#define W2_STR  68
#define A_OFF   0
#define W1_OFF  (512 * A_STR)               // 38912
#define W2_OFF  (W1_OFF + 64 * W1_STR)      // 43776
#define B1_OFF  (W2_OFF + 128 * W2_STR)     // 52480
#define B2_OFF  (B1_OFF + 64)
#define SMEM_WORDS (B2_OFF + 128)           // 52672 words = 210688 B

__global__ __launch_bounds__(512, 1) void mlp_kernel(
    const float* __restrict__ xyz,
    const int*   __restrict__ idx,
    const float* __restrict__ W1,
    const float* __restrict__ b1,
    const float* __restrict__ W2,
    const float* __restrict__ b2,
    float* __restrict__ out)
{
    extern __shared__ unsigned sm[];
    unsigned* A   = sm + A_OFF;
    unsigned* w1s = sm + W1_OFF;
    unsigned* w2s = sm + W2_OFF;
    float* b1s = (float*)(sm + B1_OFF);
    float* b2s = (float*)(sm + B2_OFF);

    const unsigned smb = (unsigned)__cvta_generic_to_shared(sm);

    const int tid  = threadIdx.x;
    const int lane = tid & 31;
    const int q    = tid >> 5;          // warp == query in block (0..15)
    const int kk   = lane & 3;
    const int r    = lane >> 2;

    // ---- stage weights ----
    for (int i = tid; i < 64 * W1_STR; i += 512) {
        int o = i / W1_STR, k = i - o * W1_STR;
        w1s[i] = (k < CIN) ? f2tf32(__ldg(&W1[o * CIN + k])) : 0u;
    }
    for (int i = tid; i < 128 * W2_STR; i += 512) {
        int o = i / W2_STR, k = i - o * W2_STR;
        w2s[i] = (k < H1n) ? f2tf32(__ldg(&W2[o * H1n + k])) : 0u;
    }
    if (tid < 64)  b1s[tid] = b1[tid];
    if (tid >= 128 && tid < 256) b2s[tid - 128] = b2[tid - 128];

    // ---- stage A tile: one row per thread, row-major ----
    {
        const int gq = blockIdx.x * 16 + q;
        const int b  = gq >> 11;            // NP = 2048
        const int s  = gq & (NP - 1);
        const int id = idx[(size_t)gq * NS + lane];
        const float* xb = xyz + (size_t)b * Nn * 3;

        unsigned* arow = A + tid * A_STR;
        arow[0] = f2tf32(__ldg(&xb[id * 3 + 0]) - __ldg(&xb[s * 3 + 0]));
        arow[1] = f2tf32(__ldg(&xb[id * 3 + 1]) - __ldg(&xb[s * 3 + 1]));
        arow[2] = f2tf32(__ldg(&xb[id * 3 + 2]) - __ldg(&xb[s * 3 + 2]));
        const float4* fp = (const float4*)(g_featT + ((size_t)b * Nn + id) * Cn);
        #pragma unroll
        for (int k4 = 0; k4 < 16; k4++) {
            float4 v = __ldg(&fp[k4]);
            arow[3 + 4 * k4 + 0] = f2tf32(v.x);
            arow[3 + 4 * k4 + 1] = f2tf32(v.y);
            arow[3 + 4 * k4 + 2] = f2tf32(v.z);
            arow[3 + 4 * k4 + 3] = f2tf32(v.w);
        }
        #pragma unroll
        for (int k = 67; k < 76; k++) arow[k] = 0u;
    }
    __syncthreads();

    const int rowbase = q * 32;

    // ldmatrix lane address offsets
    const int a_row = (lane & 7) + ((lane >> 3) & 1) * 8;
    const int a_col = (lane >> 4) * 4;
    const int b_row = (lane & 7) + ((lane >> 4) & 1) * 8;
    const int b_col = ((lane >> 3) & 1) * 4;

    const unsigned aBase0 = smb + (unsigned)((A_OFF + (rowbase + a_row) * A_STR + a_col) * 4);
    const unsigned aBase1 = aBase0 + 16 * A_STR * 4;
    const unsigned w1Base = smb + (unsigned)((W1_OFF + b_row * W1_STR + b_col) * 4);
    const unsigned w2Base = smb + (unsigned)((W2_OFF + b_row * W2_STR + b_col) * 4);

    // ---- Layer 1: c1 = A . W1^T + b1 ----
    float c1[2][8][4];
    #pragma unroll
    for (int nt = 0; nt < 8; nt++) {
        float blo = b1s[nt * 8 + 2 * kk];
        float bhi = b1s[nt * 8 + 2 * kk + 1];
        #pragma unroll
        for (int mt = 0; mt < 2; mt++) {
            c1[mt][nt][0] = blo; c1[mt][nt][1] = bhi;
            c1[mt][nt][2] = blo; c1[mt][nt][3] = bhi;
        }
    }

    #pragma unroll
    for (int kg = 0; kg < 9; kg++) {
        unsigned a0[4], a1[4];
        ldsm4(a0, aBase0 + kg * 32);
        ldsm4(a1, aBase1 + kg * 32);
        #pragma unroll
        for (int p = 0; p < 4; p++) {
            unsigned bf[4];
            ldsm4(bf, w1Base + (unsigned)(16 * p * W1_STR * 4) + kg * 32);
            mma_tf32(c1[0][2 * p],     a0, bf);
            mma_tf32(c1[0][2 * p + 1], a0, bf + 2);
            mma_tf32(c1[1][2 * p],     a1, bf);
            mma_tf32(c1[1][2 * p + 1], a1, bf + 2);
        }
    }
    __syncwarp();

    // ---- store relu(h1) row-major into warp-local A rows (alias) ----
    #pragma unroll
    for (int mt = 0; mt < 2; mt++)
        #pragma unroll
        for (int nt = 0; nt < 8; nt++)
            #pragma unroll
            for (int i = 0; i < 2; i++) {
                int row = rowbase + mt * 16 + r + 8 * i;
                unsigned lo = f2tf32(fmaxf(c1[mt][nt][2 * i + 0], 0.0f));
                unsigned hi = f2tf32(fmaxf(c1[mt][nt][2 * i + 1], 0.0f));
                ull pk = (ull)lo | ((ull)hi << 32);
                *(ull*)&A[row * A_STR + nt * 8 + 2 * kk] = pk;
            }
    __syncwarp();

    // ---- Layer 2 in two 64-output halves (register pressure) ----
    const int gq = blockIdx.x * 16 + q;
    const int bb = gq >> 11;
    const int ss = gq & (NP - 1);
    float* op_base = out + (Bn * NP * 3) + (size_t)bb * H2n * NP + ss;

    #pragma unroll
    for (int h = 0; h < 2; h++) {
        float c2[2][8][4];
        #pragma unroll
        for (int nt = 0; nt < 8; nt++) {
            int o = h * 64 + nt * 8;
            float blo = b2s[o + 2 * kk];
            float bhi = b2s[o + 2 * kk + 1];
            #pragma unroll
            for (int mt = 0; mt < 2; mt++) {
                c2[mt][nt][0] = blo; c2[mt][nt][1] = bhi;
                c2[mt][nt][2] = blo; c2[mt][nt][3] = bhi;
            }
        }

        #pragma unroll
        for (int kg = 0; kg < 8; kg++) {
            unsigned a0[4], a1[4];
            ldsm4(a0, aBase0 + kg * 32);
            ldsm4(a1, aBase1 + kg * 32);
            #pragma unroll
            for (int p = 0; p < 4; p++) {
                unsigned bf[4];
                ldsm4(bf, w2Base + (unsigned)(16 * (h * 4 + p) * W2_STR * 4) + kg * 32);
                mma_tf32(c2[0][2 * p],     a0, bf);
                mma_tf32(c2[0][2 * p + 1], a0, bf + 2);
                mma_tf32(c2[1][2 * p],     a1, bf);
                mma_tf32(c2[1][2 * p + 1], a1, bf + 2);
            }
        }

        // max over 32 rows + relu + write this half
        #pragma unroll
        for (int nt = 0; nt < 8; nt++)
            #pragma unroll
            for (int j = 0; j < 2; j++) {
                float v = fmaxf(fmaxf(c2[0][nt][j], c2[0][nt][j + 2]),
                                fmaxf(c2[1][nt][j], c2[1][nt][j + 2]));
                v = fmaxf(v, __shfl_xor_sync(0xffffffffu, v, 4));
                v = fmaxf(v, __shfl_xor_sync(0xffffffffu, v, 8));
                v = fmaxf(v, __shfl_xor_sync(0xffffffffu, v, 16));
                if (r == 0) {
                    int col = h * 64 + nt * 8 + 2 * kk + j;
                    op_base[(size_t)col * NP] = fmaxf(v, 0.0f);
                }
            }
    }
}

// ---------------------------------------------------------------------------
extern "C" void kernel_launch(void* const* d_in, const int* in_sizes, int n_in,
                              void* d_out, int out_size)
{
    const float* xyz      = (const float*)d_in[0];
    const float* features = (const float*)d_in[1];
    const float* W1       = (const float*)d_in[2];
    const float* b1       = (const float*)d_in[3];
    const float* W2       = (const float*)d_in[4];
    const float* b2       = (const float*)d_in[5];
    float* out = (float*)d_out;

    static bool attr_set = false;
    if (!attr_set) {
        cudaFuncSetAttribute(mlp_kernel, cudaFuncAttributeMaxDynamicSharedMemorySize,
                             SMEM_WORDS * (int)sizeof(unsigned));
        attr_set = true;
    }

    int*    idxp;
    float*  ftp;
    float4* x4p;
    cudaGetSymbolAddress((void**)&idxp, g_idx);
    cudaGetSymbolAddress((void**)&ftp, g_featT);
    cudaGetSymbolAddress((void**)&x4p, g_xyz4);

    // 0) pack xyz -> float4
    pack_kernel<<<(Bn * Nn + 255) / 256, 256>>>(xyz, x4p);
    // 1) transpose features (B,C,N)->(B,N,C)
    {
        dim3 blk(32, 32, 1);
        dim3 grd(Nn / 32, Cn / 32, Bn);
        transpose_kernel<<<grd, blk>>>(features, ftp);
    }
    // 2) ball query + new_xyz copy
    {
        int warps = Bn * NP;
        int threads = 256;
        int blocks = (warps * 32 + threads - 1) / threads;
        bq_kernel<<<blocks, threads>>>(x4p, idxp, out);
    }
    // 3) fused group + MLP + max (tf32 mma + ldmatrix, 16 warps/CTA)
    {
        int blocks = (Bn * NP) / 16;
        mlp_kernel<<<blocks, 512, SMEM_WORDS * (int)sizeof(unsigned)>>>(
            xyz, idxp, W1, b1, W2, b2, out);
    }
}

// round 8
// speedup vs baseline: 1.3571x; 1.2193x over previous
#include <cuda_runtime.h>
#include <cuda_fp16.h>
#include <cstdint>

// Problem constants (fixed shapes per reference setup_inputs)
#define Bn      8
#define Nn      8192
#define Cn      64
#define NP      2048
#define NS      32
#define CIN     67
#define H1n     64
#define H2n     128
#define RADIUS2 0.01f

// Scratch (allocation-free rule: __device__ globals)
__device__ int    g_idx[Bn * NP * NS];                 // 2 MB
__device__ __half g_featTh[(size_t)Bn * Nn * Cn];      // 8 MB, (B,N,C) fp16
__device__ float4 g_xyz4[Bn * Nn];                     // 1 MB packed xyz

typedef unsigned long long ull;

// ---------------------------------------------------------------------------
// fp16 mma / ldmatrix helpers
// ---------------------------------------------------------------------------
__device__ __forceinline__ void mma_f16(float c[4], const unsigned a[4],
                                        unsigned b0, unsigned b1)
{
    asm volatile(
        "mma.sync.aligned.m16n8k16.row.col.f32.f16.f16.f32 "
        "{%0,%1,%2,%3}, {%4,%5,%6,%7}, {%8,%9}, {%0,%1,%2,%3};"
        : "+f"(c[0]), "+f"(c[1]), "+f"(c[2]), "+f"(c[3])
        : "r"(a[0]), "r"(a[1]), "r"(a[2]), "r"(a[3]), "r"(b0), "r"(b1));
}

__device__ __forceinline__ void ldsm4(unsigned r[4], unsigned addr)
{
    asm volatile("ldmatrix.sync.aligned.m8n8.x4.shared.b16 {%0,%1,%2,%3}, [%4];"
                 : "=r"(r[0]), "=r"(r[1]), "=r"(r[2]), "=r"(r[3]) : "r"(addr));
}

__device__ __forceinline__ unsigned h2pack(float lo, float hi)
{
    __half2 h = __floats2half2_rn(lo, hi);
    return *(unsigned*)&h;
}

// ---------------------------------------------------------------------------
// Kernel 0: pack xyz (B,N,3) -> float4 (w=0) for 1-LDG ball query
// ---------------------------------------------------------------------------
__global__ void pack_kernel(const float* __restrict__ xyz, float4* __restrict__ p)
{
    int t = blockIdx.x * blockDim.x + threadIdx.x;
    if (t < Bn * Nn)
        p[t] = make_float4(xyz[t * 3 + 0], xyz[t * 3 + 1], xyz[t * 3 + 2], 0.0f);
}

// ---------------------------------------------------------------------------
// Kernel 1: ball query (one warp per query) + fused new_xyz copy.
// ---------------------------------------------------------------------------
__global__ void bq_kernel(const float4* __restrict__ xyz4, int* __restrict__ out_idx,
                          float* __restrict__ out)
{
    int warp = (blockIdx.x * blockDim.x + threadIdx.x) >> 5;
    int lane = threadIdx.x & 31;
    if (warp >= Bn * NP) return;
    int b = warp / NP;
    int s = warp - b * NP;

    const float4* xb = xyz4 + (size_t)b * Nn;
    float4 qp = __ldg(&xb[s]);

    if (lane < 3) {
        float v = (lane == 0) ? qp.x : (lane == 1) ? qp.y : qp.z;
        out[(size_t)warp * 3 + lane] = v;
    }

    int* outp = out_idx + (size_t)warp * NS;
    int cnt = 0;
    int first_idx = 0;

    for (int base = 0; base < Nn; base += 32) {
        int i = base + lane;
        float4 p = __ldg(&xb[i]);
        float dx = p.x - qp.x, dy = p.y - qp.y, dz = p.z - qp.z;
        float d2 = dx * dx + dy * dy + dz * dz;
        unsigned bits = __ballot_sync(0xffffffffu, d2 < RADIUS2);
        if (bits) {
            if (cnt == 0) first_idx = base + __ffs(bits) - 1;
            if ((bits >> lane) & 1u) {
                int pos = cnt + __popc(bits & ((1u << lane) - 1u));
                if (pos < NS) outp[pos] = i;
            }
            cnt += __popc(bits);
            if (cnt >= NS) break;
        }
    }
    if (cnt < NS) {
        int slot = cnt + lane;
        if (slot < NS) outp[slot] = first_idx;
    }
}

// ---------------------------------------------------------------------------
// Kernel 2: transpose features (B,C,N) f32 -> (B,N,C) fp16.
// ---------------------------------------------------------------------------
__global__ void transpose_kernel(const float* __restrict__ f, __half* __restrict__ ft)
{
    __shared__ float tile[32][33];
    int b  = blockIdx.z;
    int c0 = blockIdx.y * 32;
    int n0 = blockIdx.x * 32;
    int tx = threadIdx.x, ty = threadIdx.y;

    const float* fb = f + (size_t)b * Cn * Nn;
    tile[ty][tx] = fb[(size_t)(c0 + ty) * Nn + (n0 + tx)];
    __syncthreads();
    ft[(size_t)b * Nn * Cn + (size_t)(n0 + ty) * Cn + (c0 + tx)] =
        __float2half_rn(tile[tx][ty]);
}

// ---------------------------------------------------------------------------
// Kernel 3: fused group + MLP(67->64->128) + max; fp16 m16n8k16 mma.
//
// Block: 512 threads = 16 warps; warp w owns query w (32 rows).
// A columns PERMUTED: cols 0..63 = features, 64..66 = rel xyz (W1 staged with
// matching column permutation). Layer 2 split into two 64-out halves
// (128-reg budget at 512 thr/CTA).
//
// smem (halfs):
//   A   [512][88]  row-major fp16 (k 0..66 data, 67..87 zero); per-warp
//                  aliased by h1 [row][k 0..63] between layers.
//   W1s [64][88]   [o][k] fp16 (permuted cols), zero-padded to k=88
//   W2s [128][72]  [o][k] fp16, zero-padded
//   b1s[64] f32, b2s[128] f32 (after half region)
// ldmatrix phase conflict check (row-stride bytes /16 mod 8 odd):
//   A/W1: 176B -> 11r mod 8 distinct; W2: 144B -> 9r mod 8 distinct.
// ---------------------------------------------------------------------------
#define A_STR   88
#define W1_STR  88
#define W2_STR  72
#define A_OFF   0
#define W1_OFF  (512 * A_STR)               // 45056 halfs
#define W2_OFF  (W1_OFF + 64 * W1_STR)      // 50688
#define HALF_END (W2_OFF + 128 * W2_STR)    // 59904 halfs = 119808 B
#define SMEM_BYTES (HALF_END * 2 + (64 + 128) * 4)   // 120576 B

__global__ __launch_bounds__(512, 1) void mlp_kernel(
    const float* __restrict__ xyz,
    const int*   __restrict__ idx,
    const float* __restrict__ W1,
    const float* __restrict__ b1,
    const float* __restrict__ W2,
    const float* __restrict__ b2,
    float* __restrict__ out)
{
    extern __shared__ __half smh[];
    __half* Ah  = smh + A_OFF;
    __half* w1s = smh + W1_OFF;
    __half* w2s = smh + W2_OFF;
    float* b1s = (float*)(smh + HALF_END);
    float* b2s = b1s + 64;

    const unsigned smb = (unsigned)__cvta_generic_to_shared(smh);

    const int tid  = threadIdx.x;
    const int lane = tid & 31;
    const int q    = tid >> 5;          // warp == query in block (0..15)
    const int kk   = lane & 3;
    const int r    = lane >> 2;

    // ---- stage weights (fp16; W1 columns permuted: feat 0..63, rel 64..66) ----
    for (int i = tid; i < 64 * W1_STR; i += 512) {
        int o = i / W1_STR, k = i - o * W1_STR;
        float w = 0.0f;
        if (k < CIN) {
            int src = (k < 64) ? (k + 3) : (k - 64);
            w = __ldg(&W1[o * CIN + src]);
        }
        w1s[i] = __float2half_rn(w);
    }
    for (int i = tid; i < 128 * W2_STR; i += 512) {
        int o = i / W2_STR, k = i - o * W2_STR;
        w2s[i] = __float2half_rn((k < H1n) ? __ldg(&W2[o * H1n + k]) : 0.0f);
    }
    if (tid < 64)  b1s[tid] = b1[tid];
    if (tid >= 128 && tid < 256) b2s[tid - 128] = b2[tid - 128];

    // ---- stage A tile: one row per thread ----
    {
        const int gq = blockIdx.x * 16 + q;
        const int b  = gq >> 11;            // NP = 2048
        const int s  = gq & (NP - 1);
        const int id = idx[(size_t)gq * NS + lane];
        const float* xb = xyz + (size_t)b * Nn * 3;

        __half* arow = Ah + tid * A_STR;
        // features (already fp16): 64 halfs = 16 aligned 8B copies
        const ull* src = (const ull*)(g_featTh + ((size_t)b * Nn + id) * Cn);
        ull* dst = (ull*)arow;
        #pragma unroll
        for (int j = 0; j < 16; j++) dst[j] = __ldg(&src[j]);
        // rel xyz at cols 64..66
        arow[64] = __float2half_rn(__ldg(&xb[id * 3 + 0]) - __ldg(&xb[s * 3 + 0]));
        arow[65] = __float2half_rn(__ldg(&xb[id * 3 + 1]) - __ldg(&xb[s * 3 + 1]));
        arow[66] = __float2half_rn(__ldg(&xb[id * 3 + 2]) - __ldg(&xb[s * 3 + 2]));
        #pragma unroll
        for (int k = 67; k < A_STR; k++) arow[k] = __ushort_as_half(0);
    }
    __syncthreads();

    const int rowbase = q * 32;

    // ldmatrix lane addressing (same pattern for A and B, non-trans):
    // row' = lane & 15, chunk = (lane>>4)*8 halfs
    const int rr = lane & 15;
    const int ch = (lane >> 4) * 8;

    const unsigned aBase0 = smb + (unsigned)(((rowbase + rr) * A_STR + ch) * 2);
    const unsigned aBase1 = aBase0 + 16 * A_STR * 2;
    const unsigned w1Base = smb + (unsigned)((W1_OFF + rr * W1_STR + ch) * 2);
    const unsigned w2Base = smb + (unsigned)((W2_OFF + rr * W2_STR + ch) * 2);

    // ---- Layer 1: c1 = A . W1^T + b1  (K=80 -> 5 k-groups) ----
    float c1[2][8][4];
    #pragma unroll
    for (int nt = 0; nt < 8; nt++) {
        float blo = b1s[nt * 8 + 2 * kk];
        float bhi = b1s[nt * 8 + 2 * kk + 1];
        #pragma unroll
        for (int mt = 0; mt < 2; mt++) {
            c1[mt][nt][0] = blo; c1[mt][nt][1] = bhi;
            c1[mt][nt][2] = blo; c1[mt][nt][3] = bhi;
        }
    }

    #pragma unroll
    for (int kg = 0; kg < 5; kg++) {
        unsigned a0[4], a1[4];
        ldsm4(a0, aBase0 + kg * 32);
        ldsm4(a1, aBase1 + kg * 32);
        #pragma unroll
        for (int p = 0; p < 4; p++) {           // n-chunks of 16
            unsigned bf[4];
            ldsm4(bf, w1Base + (unsigned)(16 * p * W1_STR * 2) + kg * 32);
            mma_f16(c1[0][2 * p],     a0, bf[0], bf[2]);
            mma_f16(c1[0][2 * p + 1], a0, bf[1], bf[3]);
            mma_f16(c1[1][2 * p],     a1, bf[0], bf[2]);
            mma_f16(c1[1][2 * p + 1], a1, bf[1], bf[3]);
        }
    }
    __syncwarp();

    // ---- store relu(h1) fp16 into warp-local A rows (cols 0..63) ----
    #pragma unroll
    for (int mt = 0; mt < 2; mt++)
        #pragma unroll
        for (int nt = 0; nt < 8; nt++)
            #pragma unroll
            for (int i = 0; i < 2; i++) {
                int row = rowbase + mt * 16 + r + 8 * i;
                unsigned pk = h2pack(fmaxf(c1[mt][nt][2 * i + 0], 0.0f),
                                     fmaxf(c1[mt][nt][2 * i + 1], 0.0f));
                *(unsigned*)&Ah[row * A_STR + nt * 8 + 2 * kk] = pk;
            }
    __syncwarp();

    // ---- Layer 2 in two 64-output halves (K=64 -> 4 k-groups) ----
    const int gq = blockIdx.x * 16 + q;
    const int bb = gq >> 11;
    const int ss = gq & (NP - 1);
    float* op_base = out + (Bn * NP * 3) + (size_t)bb * H2n * NP + ss;

    #pragma unroll
    for (int h = 0; h < 2; h++) {
        float c2[2][8][4];
        #pragma unroll
        for (int nt = 0; nt < 8; nt++) {
            int o = h * 64 + nt * 8;
            float blo = b2s[o + 2 * kk];
            float bhi = b2s[o + 2 * kk + 1];
            #pragma unroll
            for (int mt = 0; mt < 2; mt++) {
                c2[mt][nt][0] = blo; c2[mt][nt][1] = bhi;
                c2[mt][nt][2] = blo; c2[mt][nt][3] = bhi;
            }
        }

        #pragma unroll
        for (int kg = 0; kg < 4; kg++) {
            unsigned a0[4], a1[4];
            ldsm4(a0, aBase0 + kg * 32);
            ldsm4(a1, aBase1 + kg * 32);
            #pragma unroll
            for (int p = 0; p < 4; p++) {
                unsigned bf[4];
                ldsm4(bf, w2Base + (unsigned)(16 * (h * 4 + p) * W2_STR * 2) + kg * 32);
                mma_f16(c2[0][2 * p],     a0, bf[0], bf[2]);
                mma_f16(c2[0][2 * p + 1], a0, bf[1], bf[3]);
                mma_f16(c2[1][2 * p],     a1, bf[0], bf[2]);
                mma_f16(c2[1][2 * p + 1], a1, bf[1], bf[3]);
            }
        }

        // max over 32 rows + relu + write this half
        #pragma unroll
        for (int nt = 0; nt < 8; nt++)
            #pragma unroll
            for (int j = 0; j < 2; j++) {
                float v = fmaxf(fmaxf(c2[0][nt][j], c2[0][nt][j + 2]),
                                fmaxf(c2[1][nt][j], c2[1][nt][j + 2]));
                v = fmaxf(v, __shfl_xor_sync(0xffffffffu, v, 4));
                v = fmaxf(v, __shfl_xor_sync(0xffffffffu, v, 8));
                v = fmaxf(v, __shfl_xor_sync(0xffffffffu, v, 16));
                if (r == 0) {
                    int col = h * 64 + nt * 8 + 2 * kk + j;
                    op_base[(size_t)col * NP] = fmaxf(v, 0.0f);
                }
            }
    }
}

// ---------------------------------------------------------------------------
extern "C" void kernel_launch(void* const* d_in, const int* in_sizes, int n_in,
                              void* d_out, int out_size)
{
    const float* xyz      = (const float*)d_in[0];
    const float* features = (const float*)d_in[1];
    const float* W1       = (const float*)d_in[2];
    const float* b1       = (const float*)d_in[3];
    const float* W2       = (const float*)d_in[4];
    const float* b2       = (const float*)d_in[5];
    float* out = (float*)d_out;

    static bool attr_set = false;
    if (!attr_set) {
        cudaFuncSetAttribute(mlp_kernel, cudaFuncAttributeMaxDynamicSharedMemorySize,
                             SMEM_BYTES);
        attr_set = true;
    }

    int*    idxp;
    __half* fthp;
    float4* x4p;
    cudaGetSymbolAddress((void**)&idxp, g_idx);
    cudaGetSymbolAddress((void**)&fthp, g_featTh);
    cudaGetSymbolAddress((void**)&x4p, g_xyz4);

    // 0) pack xyz -> float4
    pack_kernel<<<(Bn * Nn + 255) / 256, 256>>>(xyz, x4p);
    // 1) transpose features (B,C,N) f32 -> (B,N,C) fp16
    {
        dim3 blk(32, 32, 1);
        dim3 grd(Nn / 32, Cn / 32, Bn);
        transpose_kernel<<<grd, blk>>>(features, fthp);
    }
    // 2) ball query + new_xyz copy
    {
        int warps = Bn * NP;
        int threads = 256;
        int blocks = (warps * 32 + threads - 1) / threads;
        bq_kernel<<<blocks, threads>>>(x4p, idxp, out);
    }
    // 3) fused group + MLP + max (fp16 mma, 16 warps/CTA)
    {
        int blocks = (Bn * NP) / 16;
        mlp_kernel<<<blocks, 512, SMEM_BYTES>>>(xyz, idxp, W1, b1, W2, b2, out);
    }
}

// round 9
// speedup vs baseline: 1.9070x; 1.4052x over previous
#include <cuda_runtime.h>
#include <cuda_fp16.h>
#include <cstdint>

// Problem constants (fixed shapes per reference setup_inputs)
#define Bn      8
#define Nn      8192
#define Cn      64
#define NP      2048
#define NS      32
#define CIN     67
#define H1n     64
#define H2n     128
#define RADIUS2 0.01f

#define GRID    8
#define NCELL   (GRID * GRID * GRID)     // 512 per batch
#define CAND_MAX 288

// Scratch (allocation-free rule: __device__ globals)
__device__ int    g_idx[Bn * NP * NS];                 // 2 MB
__device__ __half g_featTh[(size_t)Bn * Nn * Cn];      // 8 MB, (B,N,C) fp16
__device__ float4 g_pts[Bn * Nn];                      // 1 MB cell-sorted pts
__device__ int    g_cellCount[Bn * NCELL];
__device__ int    g_cellStart[Bn * NCELL];
__device__ int    g_cursor[Bn * NCELL];

typedef unsigned long long ull;

// ---------------------------------------------------------------------------
// fp16 mma / ldmatrix helpers
// ---------------------------------------------------------------------------
__device__ __forceinline__ void mma_f16(float c[4], const unsigned a[4],
                                        unsigned b0, unsigned b1)
{
    asm volatile(
        "mma.sync.aligned.m16n8k16.row.col.f32.f16.f16.f32 "
        "{%0,%1,%2,%3}, {%4,%5,%6,%7}, {%8,%9}, {%0,%1,%2,%3};"
        : "+f"(c[0]), "+f"(c[1]), "+f"(c[2]), "+f"(c[3])
        : "r"(a[0]), "r"(a[1]), "r"(a[2]), "r"(a[3]), "r"(b0), "r"(b1));
}

__device__ __forceinline__ void ldsm4(unsigned r[4], unsigned addr)
{
    asm volatile("ldmatrix.sync.aligned.m8n8.x4.shared.b16 {%0,%1,%2,%3}, [%4];"
                 : "=r"(r[0]), "=r"(r[1]), "=r"(r[2]), "=r"(r[3]) : "r"(addr));
}

__device__ __forceinline__ unsigned h2pack(float lo, float hi)
{
    __half2 h = __floats2half2_rn(lo, hi);
    return *(unsigned*)&h;
}

__device__ __forceinline__ int cell_of(float x, float y, float z)
{
    int cx = min(GRID - 1, max(0, (int)(x * (float)GRID)));
    int cy = min(GRID - 1, max(0, (int)(y * (float)GRID)));
    int cz = min(GRID - 1, max(0, (int)(z * (float)GRID)));
    return cx + GRID * (cy + GRID * cz);
}

// ---------------------------------------------------------------------------
// Binning kernels
// ---------------------------------------------------------------------------
__global__ void bin_zero_kernel(int* __restrict__ count)
{
    int t = blockIdx.x * blockDim.x + threadIdx.x;
    if (t < Bn * NCELL) count[t] = 0;
}

__global__ void bin_count_kernel(const float* __restrict__ xyz, int* __restrict__ count)
{
    int t = blockIdx.x * blockDim.x + threadIdx.x;
    if (t >= Bn * Nn) return;
    int b = t >> 13;                       // Nn = 8192
    float x = xyz[t * 3 + 0], y = xyz[t * 3 + 1], z = xyz[t * 3 + 2];
    atomicAdd(&count[b * NCELL + cell_of(x, y, z)], 1);
}

__global__ void bin_scan_kernel(const int* __restrict__ count,
                                int* __restrict__ start, int* __restrict__ cursor)
{
    __shared__ int sc[NCELL];
    int b = blockIdx.x, t = threadIdx.x;   // 512 threads
    int c0 = count[b * NCELL + t];
    sc[t] = c0;
    __syncthreads();
    #pragma unroll
    for (int off = 1; off < NCELL; off <<= 1) {
        int v = (t >= off) ? sc[t - off] : 0;
        __syncthreads();
        sc[t] += v;
        __syncthreads();
    }
    int excl = sc[t] - c0;
    start[b * NCELL + t]  = excl;
    cursor[b * NCELL + t] = excl;
}

__global__ void bin_scatter_kernel(const float* __restrict__ xyz,
                                   int* __restrict__ cursor, float4* __restrict__ pts)
{
    int t = blockIdx.x * blockDim.x + threadIdx.x;
    if (t >= Bn * Nn) return;
    int b = t >> 13;
    int n = t & (Nn - 1);
    float x = xyz[t * 3 + 0], y = xyz[t * 3 + 1], z = xyz[t * 3 + 2];
    int pos = atomicAdd(&cursor[b * NCELL + cell_of(x, y, z)], 1);
    pts[(size_t)b * Nn + pos] = make_float4(x, y, z, __int_as_float(n));
}

// ---------------------------------------------------------------------------
// Kernel 1: grid ball query (warp per query) + fused new_xyz copy.
// Output set = min(count,32) smallest in-ball indices (order/dup-free w.r.t.
// downstream max). Fallback to exact linear scan on buffer overflow.
// ---------------------------------------------------------------------------
__global__ __launch_bounds__(512) void bq_grid_kernel(
    const float*  __restrict__ xyz,
    const float4* __restrict__ pts,
    const int*    __restrict__ cellStart,
    const int*    __restrict__ cellCount,
    int* __restrict__ out_idx, float* __restrict__ out)
{
    __shared__ int cbuf[16 * CAND_MAX];
    const int warp = threadIdx.x >> 5;
    const int lane = threadIdx.x & 31;
    const int gq   = blockIdx.x * 16 + warp;
    const int b    = gq >> 11;              // NP = 2048
    const int s    = gq & (NP - 1);

    const float qx = __ldg(&xyz[((size_t)b * Nn + s) * 3 + 0]);
    const float qy = __ldg(&xyz[((size_t)b * Nn + s) * 3 + 1]);
    const float qz = __ldg(&xyz[((size_t)b * Nn + s) * 3 + 2]);

    if (lane < 3) {
        float v = (lane == 0) ? qx : (lane == 1) ? qy : qz;
        out[(size_t)gq * 3 + lane] = v;
    }

    int* buf  = cbuf + warp * CAND_MAX;
    int* outp = out_idx + (size_t)gq * NS;

    const int cx = min(GRID - 1, max(0, (int)(qx * (float)GRID)));
    const int cy = min(GRID - 1, max(0, (int)(qy * (float)GRID)));
    const int cz = min(GRID - 1, max(0, (int)(qz * (float)GRID)));

    int K = 0;
    const float4* pb = pts + (size_t)b * Nn;

    for (int zz = max(cz - 1, 0); zz <= min(cz + 1, GRID - 1); zz++)
        for (int yy = max(cy - 1, 0); yy <= min(cy + 1, GRID - 1); yy++)
            for (int xx = max(cx - 1, 0); xx <= min(cx + 1, GRID - 1); xx++) {
                int c   = b * NCELL + xx + GRID * (yy + GRID * zz);
                int st  = __ldg(&cellStart[c]);
                int cnt = __ldg(&cellCount[c]);
                for (int p0 = 0; p0 < cnt; p0 += 32) {
                    int p  = p0 + lane;
                    int pp = min(p, cnt - 1);
                    float4 pt = __ldg(&pb[st + pp]);
                    float dx = pt.x - qx, dy = pt.y - qy, dz = pt.z - qz;
                    float d2 = dx * dx + dy * dy + dz * dz;
                    bool in = (p < cnt) && (d2 < RADIUS2);
                    unsigned m = __ballot_sync(0xffffffffu, in);
                    int pos = K + __popc(m & ((1u << lane) - 1u));
                    if (in && pos < CAND_MAX) buf[pos] = __float_as_int(pt.w);
                    K += __popc(m);
                }
            }

    if (K <= NS) {
        // all candidates; pad with buf[0] (in-set duplicate, max-invariant)
        outp[lane] = buf[(lane < K) ? lane : 0];
    } else if (K <= CAND_MAX) {
        // select 32 smallest via iterated warp-min extraction
        int loc[(CAND_MAX + 31) / 32];
        #pragma unroll
        for (int j = 0; j < (CAND_MAX + 31) / 32; j++) {
            int p = lane + 32 * j;
            loc[j] = (p < K) ? buf[p] : 0x7fffffff;
        }
        int lmin = 0x7fffffff;
        #pragma unroll
        for (int j = 0; j < (CAND_MAX + 31) / 32; j++) lmin = min(lmin, loc[j]);

        int outv = 0;
        for (int i = 0; i < NS; i++) {
            int m = lmin;
            m = min(m, __shfl_xor_sync(0xffffffffu, m, 16));
            m = min(m, __shfl_xor_sync(0xffffffffu, m, 8));
            m = min(m, __shfl_xor_sync(0xffffffffu, m, 4));
            m = min(m, __shfl_xor_sync(0xffffffffu, m, 2));
            m = min(m, __shfl_xor_sync(0xffffffffu, m, 1));
            if (lane == i) outv = m;
            if (lmin == m) {                 // unique winner (indices distinct)
                int nm = 0x7fffffff;
                #pragma unroll
                for (int j = 0; j < (CAND_MAX + 31) / 32; j++) {
                    if (loc[j] == m) loc[j] = 0x7fffffff;
                    nm = min(nm, loc[j]);
                }
                lmin = nm;
            }
        }
        outp[lane] = outv;
    } else {
        // exact fallback: ordered linear scan (reference semantics)
        int cnt = 0, first_idx = 0;
        const float* xb = xyz + (size_t)b * Nn * 3;
        for (int base = 0; base < Nn; base += 32) {
            int i = base + lane;
            float dx = __ldg(&xb[i * 3 + 0]) - qx;
            float dy = __ldg(&xb[i * 3 + 1]) - qy;
            float dz = __ldg(&xb[i * 3 + 2]) - qz;
            float d2 = dx * dx + dy * dy + dz * dz;
            unsigned bits = __ballot_sync(0xffffffffu, d2 < RADIUS2);
            if (bits) {
                if (cnt == 0) first_idx = base + __ffs(bits) - 1;
                if ((bits >> lane) & 1u) {
                    int pos = cnt + __popc(bits & ((1u << lane) - 1u));
                    if (pos < NS) outp[pos] = i;
                }
                cnt += __popc(bits);
                if (cnt >= NS) break;
            }
        }
        if (cnt < NS) {
            int slot = cnt + lane;
            if (slot < NS) outp[slot] = first_idx;
        }
    }
}

// ---------------------------------------------------------------------------
// Kernel 2: transpose features (B,C,N) f32 -> (B,N,C) fp16.
// ---------------------------------------------------------------------------
__global__ void transpose_kernel(const float* __restrict__ f, __half* __restrict__ ft)
{
    __shared__ float tile[32][33];
    int b  = blockIdx.z;
    int c0 = blockIdx.y * 32;
    int n0 = blockIdx.x * 32;
    int tx = threadIdx.x, ty = threadIdx.y;

    const float* fb = f + (size_t)b * Cn * Nn;
    tile[ty][tx] = fb[(size_t)(c0 + ty) * Nn + (n0 + tx)];
    __syncthreads();
    ft[(size_t)b * Nn * Cn + (size_t)(n0 + ty) * Cn + (c0 + tx)] =
        __float2half_rn(tile[tx][ty]);
}

// ---------------------------------------------------------------------------
// Kernel 3: fused group + MLP(67->64->128) + max; fp16 m16n8k16 mma.
// (identical to R8 passing version)
// ---------------------------------------------------------------------------
#define A_STR   88
#define W1_STR  88
#define W2_STR  72
#define A_OFF   0
#define W1_OFF  (512 * A_STR)
#define W2_OFF  (W1_OFF + 64 * W1_STR)
#define HALF_END (W2_OFF + 128 * W2_STR)
#define SMEM_BYTES (HALF_END * 2 + (64 + 128) * 4)

__global__ __launch_bounds__(512, 1) void mlp_kernel(
    const float* __restrict__ xyz,
    const int*   __restrict__ idx,
    const float* __restrict__ W1,
    const float* __restrict__ b1,
    const float* __restrict__ W2,
    const float* __restrict__ b2,
    float* __restrict__ out)
{
    extern __shared__ __half smh[];
    __half* Ah  = smh + A_OFF;
    __half* w1s = smh + W1_OFF;
    __half* w2s = smh + W2_OFF;
    float* b1s = (float*)(smh + HALF_END);
    float* b2s = b1s + 64;

    const unsigned smb = (unsigned)__cvta_generic_to_shared(smh);

    const int tid  = threadIdx.x;
    const int lane = tid & 31;
    const int q    = tid >> 5;
    const int kk   = lane & 3;
    const int r    = lane >> 2;

    for (int i = tid; i < 64 * W1_STR; i += 512) {
        int o = i / W1_STR, k = i - o * W1_STR;
        float w = 0.0f;
        if (k < CIN) {
            int src = (k < 64) ? (k + 3) : (k - 64);
            w = __ldg(&W1[o * CIN + src]);
        }
        w1s[i] = __float2half_rn(w);
    }
    for (int i = tid; i < 128 * W2_STR; i += 512) {
        int o = i / W2_STR, k = i - o * W2_STR;
        w2s[i] = __float2half_rn((k < H1n) ? __ldg(&W2[o * H1n + k]) : 0.0f);
    }
    if (tid < 64)  b1s[tid] = b1[tid];
    if (tid >= 128 && tid < 256) b2s[tid - 128] = b2[tid - 128];

    {
        const int gq = blockIdx.x * 16 + q;
        const int b  = gq >> 11;
        const int s  = gq & (NP - 1);
        const int id = idx[(size_t)gq * NS + lane];
        const float* xb = xyz + (size_t)b * Nn * 3;

        __half* arow = Ah + tid * A_STR;
        const ull* src = (const ull*)(g_featTh + ((size_t)b * Nn + id) * Cn);
        ull* dst = (ull*)arow;
        #pragma unroll
        for (int j = 0; j < 16; j++) dst[j] = __ldg(&src[j]);
        arow[64] = __float2half_rn(__ldg(&xb[id * 3 + 0]) - __ldg(&xb[s * 3 + 0]));
        arow[65] = __float2half_rn(__ldg(&xb[id * 3 + 1]) - __ldg(&xb[s * 3 + 1]));
        arow[66] = __float2half_rn(__ldg(&xb[id * 3 + 2]) - __ldg(&xb[s * 3 + 2]));
        #pragma unroll
        for (int k = 67; k < A_STR; k++) arow[k] = __ushort_as_half(0);
    }
    __syncthreads();

    const int rowbase = q * 32;
    const int rr = lane & 15;
    const int ch = (lane >> 4) * 8;

    const unsigned aBase0 = smb + (unsigned)(((rowbase + rr) * A_STR + ch) * 2);
    const unsigned aBase1 = aBase0 + 16 * A_STR * 2;
    const unsigned w1Base = smb + (unsigned)((W1_OFF + rr * W1_STR + ch) * 2);
    const unsigned w2Base = smb + (unsigned)((W2_OFF + rr * W2_STR + ch) * 2);

    float c1[2][8][4];
    #pragma unroll
    for (int nt = 0; nt < 8; nt++) {
        float blo = b1s[nt * 8 + 2 * kk];
        float bhi = b1s[nt * 8 + 2 * kk + 1];
        #pragma unroll
        for (int mt = 0; mt < 2; mt++) {
            c1[mt][nt][0] = blo; c1[mt][nt][1] = bhi;
            c1[mt][nt][2] = blo; c1[mt][nt][3] = bhi;
        }
    }

    #pragma unroll
    for (int kg = 0; kg < 5; kg++) {
        unsigned a0[4], a1[4];
        ldsm4(a0, aBase0 + kg * 32);
        ldsm4(a1, aBase1 + kg * 32);
        #pragma unroll
        for (int p = 0; p < 4; p++) {
            unsigned bf[4];
            ldsm4(bf, w1Base + (unsigned)(16 * p * W1_STR * 2) + kg * 32);
            mma_f16(c1[0][2 * p],     a0, bf[0], bf[2]);
            mma_f16(c1[0][2 * p + 1], a0, bf[1], bf[3]);
            mma_f16(c1[1][2 * p],     a1, bf[0], bf[2]);
            mma_f16(c1[1][2 * p + 1], a1, bf[1], bf[3]);
        }
    }
    __syncwarp();

    #pragma unroll
    for (int mt = 0; mt < 2; mt++)
        #pragma unroll
        for (int nt = 0; nt < 8; nt++)
            #pragma unroll
            for (int i = 0; i < 2; i++) {
                int row = rowbase + mt * 16 + r + 8 * i;
                unsigned pk = h2pack(fmaxf(c1[mt][nt][2 * i + 0], 0.0f),
                                     fmaxf(c1[mt][nt][2 * i + 1], 0.0f));
                *(unsigned*)&Ah[row * A_STR + nt * 8 + 2 * kk] = pk;
            }
    __syncwarp();

    const int gq = blockIdx.x * 16 + q;
    const int bb = gq >> 11;
    const int ss = gq & (NP - 1);
    float* op_base = out + (Bn * NP * 3) + (size_t)bb * H2n * NP + ss;

    #pragma unroll
    for (int h = 0; h < 2; h++) {
        float c2[2][8][4];
        #pragma unroll
        for (int nt = 0; nt < 8; nt++) {
            int o = h * 64 + nt * 8;
            float blo = b2s[o + 2 * kk];
            float bhi = b2s[o + 2 * kk + 1];
            #pragma unroll
            for (int mt = 0; mt < 2; mt++) {
                c2[mt][nt][0] = blo; c2[mt][nt][1] = bhi;
                c2[mt][nt][2] = blo; c2[mt][nt][3] = bhi;
            }
        }

        #pragma unroll
        for (int kg = 0; kg < 4; kg++) {
            unsigned a0[4], a1[4];
            ldsm4(a0, aBase0 + kg * 32);
            ldsm4(a1, aBase1 + kg * 32);
            #pragma unroll
            for (int p = 0; p < 4; p++) {
                unsigned bf[4];
                ldsm4(bf, w2Base + (unsigned)(16 * (h * 4 + p) * W2_STR * 2) + kg * 32);
                mma_f16(c2[0][2 * p],     a0, bf[0], bf[2]);
                mma_f16(c2[0][2 * p + 1], a0, bf[1], bf[3]);
                mma_f16(c2[1][2 * p],     a1, bf[0], bf[2]);
                mma_f16(c2[1][2 * p + 1], a1, bf[1], bf[3]);
            }
        }

        #pragma unroll
        for (int nt = 0; nt < 8; nt++)
            #pragma unroll
            for (int j = 0; j < 2; j++) {
                float v = fmaxf(fmaxf(c2[0][nt][j], c2[0][nt][j + 2]),
                                fmaxf(c2[1][nt][j], c2[1][nt][j + 2]));
                v = fmaxf(v, __shfl_xor_sync(0xffffffffu, v, 4));
                v = fmaxf(v, __shfl_xor_sync(0xffffffffu, v, 8));
                v = fmaxf(v, __shfl_xor_sync(0xffffffffu, v, 16));
                if (r == 0) {
                    int col = h * 64 + nt * 8 + 2 * kk + j;
                    op_base[(size_t)col * NP] = fmaxf(v, 0.0f);
                }
            }
    }
}

// ---------------------------------------------------------------------------
extern "C" void kernel_launch(void* const* d_in, const int* in_sizes, int n_in,
                              void* d_out, int out_size)
{
    const float* xyz      = (const float*)d_in[0];
    const float* features = (const float*)d_in[1];
    const float* W1       = (const float*)d_in[2];
    const float* b1       = (const float*)d_in[3];
    const float* W2       = (const float*)d_in[4];
    const float* b2       = (const float*)d_in[5];
    float* out = (float*)d_out;

    static bool attr_set = false;
    if (!attr_set) {
        cudaFuncSetAttribute(mlp_kernel, cudaFuncAttributeMaxDynamicSharedMemorySize,
                             SMEM_BYTES);
        attr_set = true;
    }

    int*    idxp;   cudaGetSymbolAddress((void**)&idxp, g_idx);
    __half* fthp;   cudaGetSymbolAddress((void**)&fthp, g_featTh);
    float4* ptsp;   cudaGetSymbolAddress((void**)&ptsp, g_pts);
    int*    cntp;   cudaGetSymbolAddress((void**)&cntp, g_cellCount);
    int*    stp;    cudaGetSymbolAddress((void**)&stp,  g_cellStart);
    int*    curp;   cudaGetSymbolAddress((void**)&curp, g_cursor);

    // binning pipeline
    bin_zero_kernel<<<(Bn * NCELL + 255) / 256, 256>>>(cntp);
    bin_count_kernel<<<(Bn * Nn + 255) / 256, 256>>>(xyz, cntp);
    bin_scan_kernel<<<Bn, NCELL>>>(cntp, stp, curp);
    bin_scatter_kernel<<<(Bn * Nn + 255) / 256, 256>>>(xyz, curp, ptsp);

    // transpose features (B,C,N) f32 -> (B,N,C) fp16
    {
        dim3 blk(32, 32, 1);
        dim3 grd(Nn / 32, Cn / 32, Bn);
        transpose_kernel<<<grd, blk>>>(features, fthp);
    }
    // grid ball query + new_xyz copy (16 warps/block)
    bq_grid_kernel<<<(Bn * NP) / 16, 512>>>(xyz, ptsp, stp, cntp, idxp, out);
    // fused group + MLP + max (fp16 mma, 16 warps/CTA)
    mlp_kernel<<<(Bn * NP) / 16, 512, SMEM_BYTES>>>(xyz, idxp, W1, b1, W2, b2, out);
}

// round 10
// speedup vs baseline: 2.0163x; 1.0573x over previous
#include <cuda_runtime.h>
#include <cuda_fp16.h>
#include <cstdint>

// Problem constants (fixed shapes per reference setup_inputs)
#define Bn      8
#define Nn      8192
#define Cn      64
#define NP      2048
#define NS      32
#define CIN     67
#define H1n     64
#define H2n     128
#define RADIUS2 0.01f

#define GRID    8
#define NCELL   (GRID * GRID * GRID)     // 512 per batch
#define CAND_MAX 288

// Scratch (allocation-free rule: __device__ globals)
__device__ int    g_idx[Bn * NP * NS];                 // 2 MB
__device__ __half g_featTh[(size_t)Bn * Nn * Cn];      // 8 MB, (B,N,C) fp16
__device__ float4 g_pts[Bn * Nn];                      // 1 MB cell-sorted pts
__device__ int    g_cellCount[Bn * NCELL];
__device__ int    g_cellStart[Bn * NCELL];
__device__ int    g_cursor[Bn * NCELL];

typedef unsigned long long ull;

// ---------------------------------------------------------------------------
// fp16 mma / ldmatrix helpers
// ---------------------------------------------------------------------------
__device__ __forceinline__ void mma_f16(float c[4], const unsigned a[4],
                                        unsigned b0, unsigned b1)
{
    asm volatile(
        "mma.sync.aligned.m16n8k16.row.col.f32.f16.f16.f32 "
        "{%0,%1,%2,%3}, {%4,%5,%6,%7}, {%8,%9}, {%0,%1,%2,%3};"
        : "+f"(c[0]), "+f"(c[1]), "+f"(c[2]), "+f"(c[3])
        : "r"(a[0]), "r"(a[1]), "r"(a[2]), "r"(a[3]), "r"(b0), "r"(b1));
}

__device__ __forceinline__ void ldsm4(unsigned* r, unsigned addr)
{
    asm volatile("ldmatrix.sync.aligned.m8n8.x4.shared.b16 {%0,%1,%2,%3}, [%4];"
                 : "=r"(r[0]), "=r"(r[1]), "=r"(r[2]), "=r"(r[3]) : "r"(addr));
}

__device__ __forceinline__ unsigned h2pack(float lo, float hi)
{
    __half2 h = __floats2half2_rn(lo, hi);
    return *(unsigned*)&h;
}

__device__ __forceinline__ int cell_of(float x, float y, float z)
{
    int cx = min(GRID - 1, max(0, (int)(x * (float)GRID)));
    int cy = min(GRID - 1, max(0, (int)(y * (float)GRID)));
    int cz = min(GRID - 1, max(0, (int)(z * (float)GRID)));
    return cx + GRID * (cy + GRID * cz);
}

// ---------------------------------------------------------------------------
// Binning kernels
// ---------------------------------------------------------------------------
__global__ void bin_zero_kernel(int* __restrict__ count)
{
    int t = blockIdx.x * blockDim.x + threadIdx.x;
    if (t < Bn * NCELL) count[t] = 0;
}

__global__ void bin_count_kernel(const float* __restrict__ xyz, int* __restrict__ count)
{
    int t = blockIdx.x * blockDim.x + threadIdx.x;
    if (t >= Bn * Nn) return;
    int b = t >> 13;                       // Nn = 8192
    float x = xyz[t * 3 + 0], y = xyz[t * 3 + 1], z = xyz[t * 3 + 2];
    atomicAdd(&count[b * NCELL + cell_of(x, y, z)], 1);
}

__global__ void bin_scan_kernel(const int* __restrict__ count,
                                int* __restrict__ start, int* __restrict__ cursor)
{
    __shared__ int sc[NCELL];
    int b = blockIdx.x, t = threadIdx.x;   // 512 threads
    int c0 = count[b * NCELL + t];
    sc[t] = c0;
    __syncthreads();
    #pragma unroll
    for (int off = 1; off < NCELL; off <<= 1) {
        int v = (t >= off) ? sc[t - off] : 0;
        __syncthreads();
        sc[t] += v;
        __syncthreads();
    }
    int excl = sc[t] - c0;
    start[b * NCELL + t]  = excl;
    cursor[b * NCELL + t] = excl;
}

__global__ void bin_scatter_kernel(const float* __restrict__ xyz,
                                   int* __restrict__ cursor, float4* __restrict__ pts)
{
    int t = blockIdx.x * blockDim.x + threadIdx.x;
    if (t >= Bn * Nn) return;
    int b = t >> 13;
    int n = t & (Nn - 1);
    float x = xyz[t * 3 + 0], y = xyz[t * 3 + 1], z = xyz[t * 3 + 2];
    int pos = atomicAdd(&cursor[b * NCELL + cell_of(x, y, z)], 1);
    pts[(size_t)b * Nn + pos] = make_float4(x, y, z, __int_as_float(n));
}

// ---------------------------------------------------------------------------
// Kernel 1: grid ball query (warp per query) + fused new_xyz copy.
// ---------------------------------------------------------------------------
__global__ __launch_bounds__(512) void bq_grid_kernel(
    const float*  __restrict__ xyz,
    const float4* __restrict__ pts,
    const int*    __restrict__ cellStart,
    const int*    __restrict__ cellCount,
    int* __restrict__ out_idx, float* __restrict__ out)
{
    __shared__ int cbuf[16 * CAND_MAX];
    const int warp = threadIdx.x >> 5;
    const int lane = threadIdx.x & 31;
    const int gq   = blockIdx.x * 16 + warp;
    const int b    = gq >> 11;              // NP = 2048
    const int s    = gq & (NP - 1);

    const float qx = __ldg(&xyz[((size_t)b * Nn + s) * 3 + 0]);
    const float qy = __ldg(&xyz[((size_t)b * Nn + s) * 3 + 1]);
    const float qz = __ldg(&xyz[((size_t)b * Nn + s) * 3 + 2]);

    if (lane < 3) {
        float v = (lane == 0) ? qx : (lane == 1) ? qy : qz;
        out[(size_t)gq * 3 + lane] = v;
    }

    int* buf  = cbuf + warp * CAND_MAX;
    int* outp = out_idx + (size_t)gq * NS;

    const int cx = min(GRID - 1, max(0, (int)(qx * (float)GRID)));
    const int cy = min(GRID - 1, max(0, (int)(qy * (float)GRID)));
    const int cz = min(GRID - 1, max(0, (int)(qz * (float)GRID)));

    int K = 0;
    const float4* pb = pts + (size_t)b * Nn;

    for (int zz = max(cz - 1, 0); zz <= min(cz + 1, GRID - 1); zz++)
        for (int yy = max(cy - 1, 0); yy <= min(cy + 1, GRID - 1); yy++)
            for (int xx = max(cx - 1, 0); xx <= min(cx + 1, GRID - 1); xx++) {
                int c   = b * NCELL + xx + GRID * (yy + GRID * zz);
                int st  = __ldg(&cellStart[c]);
                int cnt = __ldg(&cellCount[c]);
                for (int p0 = 0; p0 < cnt; p0 += 32) {
                    int p  = p0 + lane;
                    int pp = min(p, cnt - 1);
                    float4 pt = __ldg(&pb[st + pp]);
                    float dx = pt.x - qx, dy = pt.y - qy, dz = pt.z - qz;
                    float d2 = dx * dx + dy * dy + dz * dz;
                    bool in = (p < cnt) && (d2 < RADIUS2);
                    unsigned m = __ballot_sync(0xffffffffu, in);
                    int pos = K + __popc(m & ((1u << lane) - 1u));
                    if (in && pos < CAND_MAX) buf[pos] = __float_as_int(pt.w);
                    K += __popc(m);
                }
            }

    if (K <= NS) {
        outp[lane] = buf[(lane < K) ? lane : 0];
    } else if (K <= CAND_MAX) {
        int loc[(CAND_MAX + 31) / 32];
        #pragma unroll
        for (int j = 0; j < (CAND_MAX + 31) / 32; j++) {
            int p = lane + 32 * j;
            loc[j] = (p < K) ? buf[p] : 0x7fffffff;
        }
        int lmin = 0x7fffffff;
        #pragma unroll
        for (int j = 0; j < (CAND_MAX + 31) / 32; j++) lmin = min(lmin, loc[j]);

        int outv = 0;
        for (int i = 0; i < NS; i++) {
            int m = lmin;
            m = min(m, __shfl_xor_sync(0xffffffffu, m, 16));
            m = min(m, __shfl_xor_sync(0xffffffffu, m, 8));
            m = min(m, __shfl_xor_sync(0xffffffffu, m, 4));
            m = min(m, __shfl_xor_sync(0xffffffffu, m, 2));
            m = min(m, __shfl_xor_sync(0xffffffffu, m, 1));
            if (lane == i) outv = m;
            if (lmin == m) {
                int nm = 0x7fffffff;
                #pragma unroll
                for (int j = 0; j < (CAND_MAX + 31) / 32; j++) {
                    if (loc[j] == m) loc[j] = 0x7fffffff;
                    nm = min(nm, loc[j]);
                }
                lmin = nm;
            }
        }
        outp[lane] = outv;
    } else {
        int cnt = 0, first_idx = 0;
        const float* xb = xyz + (size_t)b * Nn * 3;
        for (int base = 0; base < Nn; base += 32) {
            int i = base + lane;
            float dx = __ldg(&xb[i * 3 + 0]) - qx;
            float dy = __ldg(&xb[i * 3 + 1]) - qy;
            float dz = __ldg(&xb[i * 3 + 2]) - qz;
            float d2 = dx * dx + dy * dy + dz * dz;
            unsigned bits = __ballot_sync(0xffffffffu, d2 < RADIUS2);
            if (bits) {
                if (cnt == 0) first_idx = base + __ffs(bits) - 1;
                if ((bits >> lane) & 1u) {
                    int pos = cnt + __popc(bits & ((1u << lane) - 1u));
                    if (pos < NS) outp[pos] = i;
                }
                cnt += __popc(bits);
                if (cnt >= NS) break;
            }
        }
        if (cnt < NS) {
            int slot = cnt + lane;
            if (slot < NS) outp[slot] = first_idx;
        }
    }
}

// ---------------------------------------------------------------------------
// Kernel 2: transpose features (B,C,N) f32 -> (B,N,C) fp16.
// ---------------------------------------------------------------------------
__global__ void transpose_kernel(const float* __restrict__ f, __half* __restrict__ ft)
{
    __shared__ float tile[32][33];
    int b  = blockIdx.z;
    int c0 = blockIdx.y * 32;
    int n0 = blockIdx.x * 32;
    int tx = threadIdx.x, ty = threadIdx.y;

    const float* fb = f + (size_t)b * Cn * Nn;
    tile[ty][tx] = fb[(size_t)(c0 + ty) * Nn + (n0 + tx)];
    __syncthreads();
    ft[(size_t)b * Nn * Cn + (size_t)(n0 + ty) * Cn + (c0 + tx)] =
        __float2half_rn(tile[tx][ty]);
}

// ---------------------------------------------------------------------------
// Kernel 3: fused group + MLP(67->64->128) + max; fp16 m16n8k16 mma.
// 256 threads = 8 warps = 8 queries; 2 CTAs co-resident per SM so one CTA's
// staging/barrier overlaps the other's MMA. L2 A-fragments hoisted to regs.
// ---------------------------------------------------------------------------
#define A_STR   88
#define W1_STR  88
#define W2_STR  72
#define A_OFF   0
#define W1_OFF  (256 * A_STR)               // 22528 halfs
#define W2_OFF  (W1_OFF + 64 * W1_STR)      // 28160
#define HALF_END (W2_OFF + 128 * W2_STR)    // 37376 halfs = 74752 B
#define SMEM_BYTES (HALF_END * 2 + (64 + 128) * 4)   // 75520 B

__global__ __launch_bounds__(256, 2) void mlp_kernel(
    const float* __restrict__ xyz,
    const int*   __restrict__ idx,
    const float* __restrict__ W1,
    const float* __restrict__ b1,
    const float* __restrict__ W2,
    const float* __restrict__ b2,
    float* __restrict__ out)
{
    extern __shared__ __half smh[];
    __half* Ah  = smh + A_OFF;
    __half* w1s = smh + W1_OFF;
    __half* w2s = smh + W2_OFF;
    float* b1s = (float*)(smh + HALF_END);
    float* b2s = b1s + 64;

    const unsigned smb = (unsigned)__cvta_generic_to_shared(smh);

    const int tid  = threadIdx.x;
    const int lane = tid & 31;
    const int q    = tid >> 5;          // warp == query in block (0..7)
    const int kk   = lane & 3;
    const int r    = lane >> 2;

    // ---- stage weights (fp16; W1 columns permuted: feat 0..63, rel 64..66) ----
    for (int i = tid; i < 64 * W1_STR; i += 256) {
        int o = i / W1_STR, k = i - o * W1_STR;
        float w = 0.0f;
        if (k < CIN) {
            int src = (k < 64) ? (k + 3) : (k - 64);
            w = __ldg(&W1[o * CIN + src]);
        }
        w1s[i] = __float2half_rn(w);
    }
    for (int i = tid; i < 128 * W2_STR; i += 256) {
        int o = i / W2_STR, k = i - o * W2_STR;
        w2s[i] = __float2half_rn((k < H1n) ? __ldg(&W2[o * H1n + k]) : 0.0f);
    }
    if (tid < 64)  b1s[tid] = b1[tid];
    if (tid >= 128 && tid < 256) b2s[tid - 128] = b2[tid - 128];

    // ---- stage A tile: one row per thread ----
    {
        const int gq = blockIdx.x * 8 + q;
        const int b  = gq >> 11;            // NP = 2048
        const int s  = gq & (NP - 1);
        const int id = idx[(size_t)gq * NS + lane];
        const float* xb = xyz + (size_t)b * Nn * 3;

        __half* arow = Ah + tid * A_STR;
        const ull* src = (const ull*)(g_featTh + ((size_t)b * Nn + id) * Cn);
        ull* dst = (ull*)arow;
        #pragma unroll
        for (int j = 0; j < 16; j++) dst[j] = __ldg(&src[j]);
        arow[64] = __float2half_rn(__ldg(&xb[id * 3 + 0]) - __ldg(&xb[s * 3 + 0]));
        arow[65] = __float2half_rn(__ldg(&xb[id * 3 + 1]) - __ldg(&xb[s * 3 + 1]));
        arow[66] = __float2half_rn(__ldg(&xb[id * 3 + 2]) - __ldg(&xb[s * 3 + 2]));
        #pragma unroll
        for (int k = 67; k < A_STR; k++) arow[k] = __ushort_as_half(0);
    }
    __syncthreads();

    const int rowbase = q * 32;
    const int rr = lane & 15;
    const int ch = (lane >> 4) * 8;

    const unsigned aBase0 = smb + (unsigned)(((rowbase + rr) * A_STR + ch) * 2);
    const unsigned aBase1 = aBase0 + 16 * A_STR * 2;
    const unsigned w1Base = smb + (unsigned)((W1_OFF + rr * W1_STR + ch) * 2);
    const unsigned w2Base = smb + (unsigned)((W2_OFF + rr * W2_STR + ch) * 2);

    // ---- Layer 1: c1 = A . W1^T + b1  (K=80 -> 5 k-groups) ----
    float c1[2][8][4];
    #pragma unroll
    for (int nt = 0; nt < 8; nt++) {
        float blo = b1s[nt * 8 + 2 * kk];
        float bhi = b1s[nt * 8 + 2 * kk + 1];
        #pragma unroll
        for (int mt = 0; mt < 2; mt++) {
            c1[mt][nt][0] = blo; c1[mt][nt][1] = bhi;
            c1[mt][nt][2] = blo; c1[mt][nt][3] = bhi;
        }
    }

    #pragma unroll
    for (int kg = 0; kg < 5; kg++) {
        unsigned a0[4], a1[4];
        ldsm4(a0, aBase0 + kg * 32);
        ldsm4(a1, aBase1 + kg * 32);
        #pragma unroll
        for (int p = 0; p < 4; p++) {
            unsigned bf[4];
            ldsm4(bf, w1Base + (unsigned)(16 * p * W1_STR * 2) + kg * 32);
            mma_f16(c1[0][2 * p],     a0, bf[0], bf[2]);
            mma_f16(c1[0][2 * p + 1], a0, bf[1], bf[3]);
            mma_f16(c1[1][2 * p],     a1, bf[0], bf[2]);
            mma_f16(c1[1][2 * p + 1], a1, bf[1], bf[3]);
        }
    }
    __syncwarp();

    // ---- store relu(h1) fp16 into warp-local A rows (cols 0..63) ----
    #pragma unroll
    for (int mt = 0; mt < 2; mt++)
        #pragma unroll
        for (int nt = 0; nt < 8; nt++)
            #pragma unroll
            for (int i = 0; i < 2; i++) {
                int row = rowbase + mt * 16 + r + 8 * i;
                unsigned pk = h2pack(fmaxf(c1[mt][nt][2 * i + 0], 0.0f),
                                     fmaxf(c1[mt][nt][2 * i + 1], 0.0f));
                *(unsigned*)&Ah[row * A_STR + nt * 8 + 2 * kk] = pk;
            }
    __syncwarp();

    // ---- hoist L2 A fragments (K=64 -> 4 k-groups) into registers ----
    unsigned afrag[4][8];
    #pragma unroll
    for (int kg = 0; kg < 4; kg++) {
        ldsm4(&afrag[kg][0], aBase0 + kg * 32);
        ldsm4(&afrag[kg][4], aBase1 + kg * 32);
    }

    const int gq = blockIdx.x * 8 + q;
    const int bb = gq >> 11;
    const int ss = gq & (NP - 1);
    float* op_base = out + (Bn * NP * 3) + (size_t)bb * H2n * NP + ss;

    #pragma unroll
    for (int h = 0; h < 2; h++) {
        float c2[2][8][4];
        #pragma unroll
        for (int nt = 0; nt < 8; nt++) {
            int o = h * 64 + nt * 8;
            float blo = b2s[o + 2 * kk];
            float bhi = b2s[o + 2 * kk + 1];
            #pragma unroll
            for (int mt = 0; mt < 2; mt++) {
                c2[mt][nt][0] = blo; c2[mt][nt][1] = bhi;
                c2[mt][nt][2] = blo; c2[mt][nt][3] = bhi;
            }
        }

        #pragma unroll
        for (int kg = 0; kg < 4; kg++) {
            #pragma unroll
            for (int p = 0; p < 4; p++) {
                unsigned bf[4];
                ldsm4(bf, w2Base + (unsigned)(16 * (h * 4 + p) * W2_STR * 2) + kg * 32);
                mma_f16(c2[0][2 * p],     &afrag[kg][0], bf[0], bf[2]);
                mma_f16(c2[0][2 * p + 1], &afrag[kg][0], bf[1], bf[3]);
                mma_f16(c2[1][2 * p],     &afrag[kg][4], bf[0], bf[2]);
                mma_f16(c2[1][2 * p + 1], &afrag[kg][4], bf[1], bf[3]);
            }
        }

        #pragma unroll
        for (int nt = 0; nt < 8; nt++)
            #pragma unroll
            for (int j = 0; j < 2; j++) {
                float v = fmaxf(fmaxf(c2[0][nt][j], c2[0][nt][j + 2]),
                                fmaxf(c2[1][nt][j], c2[1][nt][j + 2]));
                v = fmaxf(v, __shfl_xor_sync(0xffffffffu, v, 4));
                v = fmaxf(v, __shfl_xor_sync(0xffffffffu, v, 8));
                v = fmaxf(v, __shfl_xor_sync(0xffffffffu, v, 16));
                if (r == 0) {
                    int col = h * 64 + nt * 8 + 2 * kk + j;
                    op_base[(size_t)col * NP] = fmaxf(v, 0.0f);
                }
            }
    }
}

// ---------------------------------------------------------------------------
extern "C" void kernel_launch(void* const* d_in, const int* in_sizes, int n_in,
                              void* d_out, int out_size)
{
    const float* xyz      = (const float*)d_in[0];
    const float* features = (const float*)d_in[1];
    const float* W1       = (const float*)d_in[2];
    const float* b1       = (const float*)d_in[3];
    const float* W2       = (const float*)d_in[4];
    const float* b2       = (const float*)d_in[5];
    float* out = (float*)d_out;

    static bool init_done = false;
    static cudaStream_t s2;
    static cudaEvent_t eFork, eJoin;
    if (!init_done) {
        cudaFuncSetAttribute(mlp_kernel, cudaFuncAttributeMaxDynamicSharedMemorySize,
                             SMEM_BYTES);
        cudaStreamCreateWithFlags(&s2, cudaStreamNonBlocking);
        cudaEventCreateWithFlags(&eFork, cudaEventDisableTiming);
        cudaEventCreateWithFlags(&eJoin, cudaEventDisableTiming);
        init_done = true;
    }

    int*    idxp;   cudaGetSymbolAddress((void**)&idxp, g_idx);
    __half* fthp;   cudaGetSymbolAddress((void**)&fthp, g_featTh);
    float4* ptsp;   cudaGetSymbolAddress((void**)&ptsp, g_pts);
    int*    cntp;   cudaGetSymbolAddress((void**)&cntp, g_cellCount);
    int*    stp;    cudaGetSymbolAddress((void**)&stp,  g_cellStart);
    int*    curp;   cudaGetSymbolAddress((void**)&curp, g_cursor);

    // Fork: transpose (depends only on features) runs on s2 concurrently with
    // the binning + ball-query chain on the main stream.
    cudaEventRecord(eFork, 0);
    cudaStreamWaitEvent(s2, eFork, 0);
    {
        dim3 blk(32, 32, 1);
        dim3 grd(Nn / 32, Cn / 32, Bn);
        transpose_kernel<<<grd, blk, 0, s2>>>(features, fthp);
    }
    cudaEventRecord(eJoin, s2);

    // Main stream: binning pipeline + grid ball query
    bin_zero_kernel<<<(Bn * NCELL + 255) / 256, 256>>>(cntp);
    bin_count_kernel<<<(Bn * Nn + 255) / 256, 256>>>(xyz, cntp);
    bin_scan_kernel<<<Bn, NCELL>>>(cntp, stp, curp);
    bin_scatter_kernel<<<(Bn * Nn + 255) / 256, 256>>>(xyz, curp, ptsp);
    bq_grid_kernel<<<(Bn * NP) / 16, 512>>>(xyz, ptsp, stp, cntp, idxp, out);

    // Join: mlp needs both idx (main) and featTh (s2)
    cudaStreamWaitEvent(0, eJoin, 0);
    mlp_kernel<<<(Bn * NP) / 8, 256, SMEM_BYTES>>>(xyz, idxp, W1, b1, W2, b2, out);
}

// round 11
// speedup vs baseline: 2.0500x; 1.0167x over previous
#include <cuda_runtime.h>
#include <cuda_fp16.h>
#include <cstdint>

// Problem constants (fixed shapes per reference setup_inputs)
#define Bn      8
#define Nn      8192
#define Cn      64
#define NP      2048
#define NS      32
#define CIN     67
#define H1n     64
#define H2n     128
#define RADIUS2 0.01f

#define GRID    8
#define NCELL   (GRID * GRID * GRID)     // 512 per batch
#define CAND_MAX 288
#define NCTA    296                      // persistent: 2 CTAs x 148 SMs

// Scratch (allocation-free rule: __device__ globals)
__device__ __half g_featTh[(size_t)Bn * Nn * Cn];      // 8 MB, (B,N,C) fp16
__device__ float4 g_pts[Bn * Nn];                      // 1 MB cell-sorted pts
__device__ int    g_cellCount[Bn * NCELL];
__device__ int    g_cellStart[Bn * NCELL];
__device__ int    g_cursor[Bn * NCELL];

typedef unsigned long long ull;

// ---------------------------------------------------------------------------
// fp16 mma / ldmatrix helpers
// ---------------------------------------------------------------------------
__device__ __forceinline__ void mma_f16(float c[4], const unsigned a[4],
                                        unsigned b0, unsigned b1)
{
    asm volatile(
        "mma.sync.aligned.m16n8k16.row.col.f32.f16.f16.f32 "
        "{%0,%1,%2,%3}, {%4,%5,%6,%7}, {%8,%9}, {%0,%1,%2,%3};"
        : "+f"(c[0]), "+f"(c[1]), "+f"(c[2]), "+f"(c[3])
        : "r"(a[0]), "r"(a[1]), "r"(a[2]), "r"(a[3]), "r"(b0), "r"(b1));
}

__device__ __forceinline__ void ldsm4(unsigned* r, unsigned addr)
{
    asm volatile("ldmatrix.sync.aligned.m8n8.x4.shared.b16 {%0,%1,%2,%3}, [%4];"
                 : "=r"(r[0]), "=r"(r[1]), "=r"(r[2]), "=r"(r[3]) : "r"(addr));
}

__device__ __forceinline__ unsigned h2pack(float lo, float hi)
{
    __half2 h = __floats2half2_rn(lo, hi);
    return *(unsigned*)&h;
}

__device__ __forceinline__ int cell_of(float x, float y, float z)
{
    int cx = min(GRID - 1, max(0, (int)(x * (float)GRID)));
    int cy = min(GRID - 1, max(0, (int)(y * (float)GRID)));
    int cz = min(GRID - 1, max(0, (int)(z * (float)GRID)));
    return cx + GRID * (cy + GRID * cz);
}

// ---------------------------------------------------------------------------
// Binning kernels
// ---------------------------------------------------------------------------
__global__ void bin_zero_kernel(int* __restrict__ count)
{
    int t = blockIdx.x * blockDim.x + threadIdx.x;
    if (t < Bn * NCELL) count[t] = 0;
}

__global__ void bin_count_kernel(const float* __restrict__ xyz, int* __restrict__ count)
{
    int t = blockIdx.x * blockDim.x + threadIdx.x;
    if (t >= Bn * Nn) return;
    int b = t >> 13;                       // Nn = 8192
    float x = xyz[t * 3 + 0], y = xyz[t * 3 + 1], z = xyz[t * 3 + 2];
    atomicAdd(&count[b * NCELL + cell_of(x, y, z)], 1);
}

__global__ void bin_scan_kernel(const int* __restrict__ count,
                                int* __restrict__ start, int* __restrict__ cursor)
{
    __shared__ int sc[NCELL];
    int b = blockIdx.x, t = threadIdx.x;   // 512 threads
    int c0 = count[b * NCELL + t];
    sc[t] = c0;
    __syncthreads();
    #pragma unroll
    for (int off = 1; off < NCELL; off <<= 1) {
        int v = (t >= off) ? sc[t - off] : 0;
        __syncthreads();
        sc[t] += v;
        __syncthreads();
    }
    int excl = sc[t] - c0;
    start[b * NCELL + t]  = excl;
    cursor[b * NCELL + t] = excl;
}

__global__ void bin_scatter_kernel(const float* __restrict__ xyz,
                                   int* __restrict__ cursor, float4* __restrict__ pts)
{
    int t = blockIdx.x * blockDim.x + threadIdx.x;
    if (t >= Bn * Nn) return;
    int b = t >> 13;
    int n = t & (Nn - 1);
    float x = xyz[t * 3 + 0], y = xyz[t * 3 + 1], z = xyz[t * 3 + 2];
    int pos = atomicAdd(&cursor[b * NCELL + cell_of(x, y, z)], 1);
    pts[(size_t)b * Nn + pos] = make_float4(x, y, z, __int_as_float(n));
}

// ---------------------------------------------------------------------------
// Kernel 2: transpose features (B,C,N) f32 -> (B,N,C) fp16.
// ---------------------------------------------------------------------------
__global__ void transpose_kernel(const float* __restrict__ f, __half* __restrict__ ft)
{
    __shared__ float tile[32][33];
    int b  = blockIdx.z;
    int c0 = blockIdx.y * 32;
    int n0 = blockIdx.x * 32;
    int tx = threadIdx.x, ty = threadIdx.y;

    const float* fb = f + (size_t)b * Cn * Nn;
    tile[ty][tx] = fb[(size_t)(c0 + ty) * Nn + (n0 + tx)];
    __syncthreads();
    ft[(size_t)b * Nn * Cn + (size_t)(n0 + ty) * Cn + (c0 + tx)] =
        __float2half_rn(tile[tx][ty]);
}

// ---------------------------------------------------------------------------
// FUSED persistent kernel: grid ball query + group + MLP + max.
// 256 threads = 8 warps; each warp independently streams queries
// (gq = globalwarp, += totalwarps). Weights staged ONCE per CTA; after that
// no block barriers — warps only __syncwarp on their own 32 rows.
// ---------------------------------------------------------------------------
#define A_STR   88
#define W1_STR  88
#define W2_STR  72
#define A_OFF   0
#define W1_OFF  (256 * A_STR)               // 22528 halfs
#define W2_OFF  (W1_OFF + 64 * W1_STR)      // 28160
#define HALF_END (W2_OFF + 128 * W2_STR)    // 37376 halfs = 74752 B
#define BIAS_BYTES ((64 + 128) * 4)
#define CBUF_OFF_B (HALF_END * 2 + BIAS_BYTES)           // byte offset of cbuf
#define SMEM_BYTES (CBUF_OFF_B + 8 * CAND_MAX * 4)       // + 9216 B = 93 KB tot

__global__ __launch_bounds__(256, 2) void fused_kernel(
    const float*  __restrict__ xyz,
    const float4* __restrict__ pts,
    const int*    __restrict__ cellStart,
    const int*    __restrict__ cellCount,
    const float*  __restrict__ W1,
    const float*  __restrict__ b1,
    const float*  __restrict__ W2,
    const float*  __restrict__ b2,
    float* __restrict__ out)
{
    extern __shared__ __half smh[];
    __half* Ah  = smh + A_OFF;
    __half* w1s = smh + W1_OFF;
    __half* w2s = smh + W2_OFF;
    float* b1s = (float*)(smh + HALF_END);
    float* b2s = b1s + 64;
    int*   cbuf = (int*)((char*)smh + CBUF_OFF_B);

    const unsigned smb = (unsigned)__cvta_generic_to_shared(smh);

    const int tid  = threadIdx.x;
    const int lane = tid & 31;
    const int q    = tid >> 5;
    const int kk   = lane & 3;
    const int r    = lane >> 2;

    // ---- stage weights ONCE (fp16; W1 cols permuted: feat 0..63, rel 64..66) ----
    for (int i = tid; i < 64 * W1_STR; i += 256) {
        int o = i / W1_STR, k = i - o * W1_STR;
        float w = 0.0f;
        if (k < CIN) {
            int src = (k < 64) ? (k + 3) : (k - 64);
            w = __ldg(&W1[o * CIN + src]);
        }
        w1s[i] = __float2half_rn(w);
    }
    for (int i = tid; i < 128 * W2_STR; i += 256) {
        int o = i / W2_STR, k = i - o * W2_STR;
        w2s[i] = __float2half_rn((k < H1n) ? __ldg(&W2[o * H1n + k]) : 0.0f);
    }
    if (tid < 64)  b1s[tid] = b1[tid];
    if (tid >= 128 && tid < 256) b2s[tid - 128] = b2[tid - 128];

    // zero-pad A cols 67..87 once (never overwritten: h1 uses 0..63, rel 64..66)
    {
        __half* arow = Ah + tid * A_STR;
        #pragma unroll
        for (int k = 67; k < A_STR; k++) arow[k] = __ushort_as_half(0);
    }
    __syncthreads();

    // ldmatrix lane addressing
    const int rowbase = q * 32;
    const int rr = lane & 15;
    const int ch = (lane >> 4) * 8;
    const unsigned aBase0 = smb + (unsigned)(((rowbase + rr) * A_STR + ch) * 2);
    const unsigned aBase1 = aBase0 + 16 * A_STR * 2;
    const unsigned w1Base = smb + (unsigned)((W1_OFF + rr * W1_STR + ch) * 2);
    const unsigned w2Base = smb + (unsigned)((W2_OFF + rr * W2_STR + ch) * 2);

    int* buf = cbuf + q * CAND_MAX;
    const int totwarps = NCTA * 8;
    const int gwarp = blockIdx.x * 8 + q;

    for (int gq = gwarp; gq < Bn * NP; gq += totwarps) {
        const int b = gq >> 11;              // NP = 2048
        const int s = gq & (NP - 1);

        // ================== per-warp grid ball query ==================
        const float qx = __ldg(&xyz[((size_t)b * Nn + s) * 3 + 0]);
        const float qy = __ldg(&xyz[((size_t)b * Nn + s) * 3 + 1]);
        const float qz = __ldg(&xyz[((size_t)b * Nn + s) * 3 + 2]);

        if (lane < 3) {
            float v = (lane == 0) ? qx : (lane == 1) ? qy : qz;
            out[(size_t)gq * 3 + lane] = v;
        }

        const int cx = min(GRID - 1, max(0, (int)(qx * (float)GRID)));
        const int cy = min(GRID - 1, max(0, (int)(qy * (float)GRID)));
        const int cz = min(GRID - 1, max(0, (int)(qz * (float)GRID)));

        int K = 0;
        const float4* pb = pts + (size_t)b * Nn;

        for (int zz = max(cz - 1, 0); zz <= min(cz + 1, GRID - 1); zz++)
            for (int yy = max(cy - 1, 0); yy <= min(cy + 1, GRID - 1); yy++)
                for (int xx = max(cx - 1, 0); xx <= min(cx + 1, GRID - 1); xx++) {
                    int c   = b * NCELL + xx + GRID * (yy + GRID * zz);
                    int st  = __ldg(&cellStart[c]);
                    int cnt = __ldg(&cellCount[c]);
                    for (int p0 = 0; p0 < cnt; p0 += 32) {
                        int p  = p0 + lane;
                        int pp = min(p, cnt - 1);
                        float4 pt = __ldg(&pb[st + pp]);
                        float dx = pt.x - qx, dy = pt.y - qy, dz = pt.z - qz;
                        float d2 = dx * dx + dy * dy + dz * dz;
                        bool in = (p < cnt) && (d2 < RADIUS2);
                        unsigned m = __ballot_sync(0xffffffffu, in);
                        int pos = K + __popc(m & ((1u << lane) - 1u));
                        if (in && pos < CAND_MAX) buf[pos] = __float_as_int(pt.w);
                        K += __popc(m);
                    }
                }
        __syncwarp();

        int myid;
        if (K <= NS) {
            myid = buf[(lane < K) ? lane : 0];
        } else if (K <= CAND_MAX) {
            int loc[(CAND_MAX + 31) / 32];
            #pragma unroll
            for (int j = 0; j < (CAND_MAX + 31) / 32; j++) {
                int p = lane + 32 * j;
                loc[j] = (p < K) ? buf[p] : 0x7fffffff;
            }
            int lmin = 0x7fffffff;
            #pragma unroll
            for (int j = 0; j < (CAND_MAX + 31) / 32; j++) lmin = min(lmin, loc[j]);

            myid = 0;
            for (int i = 0; i < NS; i++) {
                int m = lmin;
                m = min(m, __shfl_xor_sync(0xffffffffu, m, 16));
                m = min(m, __shfl_xor_sync(0xffffffffu, m, 8));
                m = min(m, __shfl_xor_sync(0xffffffffu, m, 4));
                m = min(m, __shfl_xor_sync(0xffffffffu, m, 2));
                m = min(m, __shfl_xor_sync(0xffffffffu, m, 1));
                if (lane == i) myid = m;
                if (lmin == m) {
                    int nm = 0x7fffffff;
                    #pragma unroll
                    for (int j = 0; j < (CAND_MAX + 31) / 32; j++) {
                        if (loc[j] == m) loc[j] = 0x7fffffff;
                        nm = min(nm, loc[j]);
                    }
                    lmin = nm;
                }
            }
        } else {
            // exact fallback: ordered linear scan into buf
            int cnt = 0, first_idx = 0;
            const float* xb = xyz + (size_t)b * Nn * 3;
            for (int base = 0; base < Nn; base += 32) {
                int i = base + lane;
                float dx = __ldg(&xb[i * 3 + 0]) - qx;
                float dy = __ldg(&xb[i * 3 + 1]) - qy;
                float dz = __ldg(&xb[i * 3 + 2]) - qz;
                float d2 = dx * dx + dy * dy + dz * dz;
                unsigned bits = __ballot_sync(0xffffffffu, d2 < RADIUS2);
                if (bits) {
                    if (cnt == 0) first_idx = base + __ffs(bits) - 1;
                    if ((bits >> lane) & 1u) {
                        int pos = cnt + __popc(bits & ((1u << lane) - 1u));
                        if (pos < NS) buf[pos] = i;
                    }
                    cnt += __popc(bits);
                    if (cnt >= NS) break;
                }
            }
            if (cnt < NS) {
                int slot = cnt + lane;
                if (slot < NS) buf[slot] = first_idx;
            }
            __syncwarp();
            myid = buf[lane];
        }

        // ================== stage A row (this thread's row = tid) ==================
        {
            const float* xb = xyz + (size_t)b * Nn * 3;
            __half* arow = Ah + tid * A_STR;
            const ull* src = (const ull*)(g_featTh + ((size_t)b * Nn + myid) * Cn);
            ull* dst = (ull*)arow;
            #pragma unroll
            for (int j = 0; j < 16; j++) dst[j] = __ldg(&src[j]);
            arow[64] = __float2half_rn(__ldg(&xb[myid * 3 + 0]) - qx);
            arow[65] = __float2half_rn(__ldg(&xb[myid * 3 + 1]) - qy);
            arow[66] = __float2half_rn(__ldg(&xb[myid * 3 + 2]) - qz);
        }
        __syncwarp();

        // ================== Layer 1 (K=80 -> 5 k-groups) ==================
        float c1[2][8][4];
        #pragma unroll
        for (int nt = 0; nt < 8; nt++) {
            float blo = b1s[nt * 8 + 2 * kk];
            float bhi = b1s[nt * 8 + 2 * kk + 1];
            #pragma unroll
            for (int mt = 0; mt < 2; mt++) {
                c1[mt][nt][0] = blo; c1[mt][nt][1] = bhi;
                c1[mt][nt][2] = blo; c1[mt][nt][3] = bhi;
            }
        }

        #pragma unroll
        for (int kg = 0; kg < 5; kg++) {
            unsigned a0[4], a1[4];
            ldsm4(a0, aBase0 + kg * 32);
            ldsm4(a1, aBase1 + kg * 32);
            #pragma unroll
            for (int p = 0; p < 4; p++) {
                unsigned bf[4];
                ldsm4(bf, w1Base + (unsigned)(16 * p * W1_STR * 2) + kg * 32);
                mma_f16(c1[0][2 * p],     a0, bf[0], bf[2]);
                mma_f16(c1[0][2 * p + 1], a0, bf[1], bf[3]);
                mma_f16(c1[1][2 * p],     a1, bf[0], bf[2]);
                mma_f16(c1[1][2 * p + 1], a1, bf[1], bf[3]);
            }
        }
        __syncwarp();

        // store relu(h1) fp16 into warp-local A rows (cols 0..63)
        #pragma unroll
        for (int mt = 0; mt < 2; mt++)
            #pragma unroll
            for (int nt = 0; nt < 8; nt++)
                #pragma unroll
                for (int i = 0; i < 2; i++) {
                    int row = rowbase + mt * 16 + r + 8 * i;
                    unsigned pk = h2pack(fmaxf(c1[mt][nt][2 * i + 0], 0.0f),
                                         fmaxf(c1[mt][nt][2 * i + 1], 0.0f));
                    *(unsigned*)&Ah[row * A_STR + nt * 8 + 2 * kk] = pk;
                }
        __syncwarp();

        // hoist L2 A fragments (K=64 -> 4 k-groups)
        unsigned afrag[4][8];
        #pragma unroll
        for (int kg = 0; kg < 4; kg++) {
            ldsm4(&afrag[kg][0], aBase0 + kg * 32);
            ldsm4(&afrag[kg][4], aBase1 + kg * 32);
        }

        float* op_base = out + (Bn * NP * 3) + (size_t)b * H2n * NP + s;

        #pragma unroll
        for (int h = 0; h < 2; h++) {
            float c2[2][8][4];
            #pragma unroll
            for (int nt = 0; nt < 8; nt++) {
                int o = h * 64 + nt * 8;
                float blo = b2s[o + 2 * kk];
                float bhi = b2s[o + 2 * kk + 1];
                #pragma unroll
                for (int mt = 0; mt < 2; mt++) {
                    c2[mt][nt][0] = blo; c2[mt][nt][1] = bhi;
                    c2[mt][nt][2] = blo; c2[mt][nt][3] = bhi;
                }
            }

            #pragma unroll
            for (int kg = 0; kg < 4; kg++) {
                #pragma unroll
                for (int p = 0; p < 4; p++) {
                    unsigned bf[4];
                    ldsm4(bf, w2Base + (unsigned)(16 * (h * 4 + p) * W2_STR * 2) + kg * 32);
                    mma_f16(c2[0][2 * p],     &afrag[kg][0], bf[0], bf[2]);
                    mma_f16(c2[0][2 * p + 1], &afrag[kg][0], bf[1], bf[3]);
                    mma_f16(c2[1][2 * p],     &afrag[kg][4], bf[0], bf[2]);
                    mma_f16(c2[1][2 * p + 1], &afrag[kg][4], bf[1], bf[3]);
                }
            }

            #pragma unroll
            for (int nt = 0; nt < 8; nt++)
                #pragma unroll
                for (int j = 0; j < 2; j++) {
                    float v = fmaxf(fmaxf(c2[0][nt][j], c2[0][nt][j + 2]),
                                    fmaxf(c2[1][nt][j], c2[1][nt][j + 2]));
                    v = fmaxf(v, __shfl_xor_sync(0xffffffffu, v, 4));
                    v = fmaxf(v, __shfl_xor_sync(0xffffffffu, v, 8));
                    v = fmaxf(v, __shfl_xor_sync(0xffffffffu, v, 16));
                    if (r == 0) {
                        int col = h * 64 + nt * 8 + 2 * kk + j;
                        op_base[(size_t)col * NP] = fmaxf(v, 0.0f);
                    }
                }
        }
        __syncwarp();   // h1/A reads done before next iteration restages
    }
}

// ---------------------------------------------------------------------------
extern "C" void kernel_launch(void* const* d_in, const int* in_sizes, int n_in,
                              void* d_out, int out_size)
{
    const float* xyz      = (const float*)d_in[0];
    const float* features = (const float*)d_in[1];
    const float* W1       = (const float*)d_in[2];
    const float* b1       = (const float*)d_in[3];
    const float* W2       = (const float*)d_in[4];
    const float* b2       = (const float*)d_in[5];
    float* out = (float*)d_out;

    static bool init_done = false;
    static cudaStream_t s2;
    static cudaEvent_t eFork, eJoin;
    if (!init_done) {
        cudaFuncSetAttribute(fused_kernel, cudaFuncAttributeMaxDynamicSharedMemorySize,
                             SMEM_BYTES);
        cudaStreamCreateWithFlags(&s2, cudaStreamNonBlocking);
        cudaEventCreateWithFlags(&eFork, cudaEventDisableTiming);
        cudaEventCreateWithFlags(&eJoin, cudaEventDisableTiming);
        init_done = true;
    }

    __half* fthp;   cudaGetSymbolAddress((void**)&fthp, g_featTh);
    float4* ptsp;   cudaGetSymbolAddress((void**)&ptsp, g_pts);
    int*    cntp;   cudaGetSymbolAddress((void**)&cntp, g_cellCount);
    int*    stp;    cudaGetSymbolAddress((void**)&stp,  g_cellStart);
    int*    curp;   cudaGetSymbolAddress((void**)&curp, g_cursor);

    // Fork: transpose (depends only on features) on s2, parallel to binning.
    cudaEventRecord(eFork, 0);
    cudaStreamWaitEvent(s2, eFork, 0);
    {
        dim3 blk(32, 32, 1);
        dim3 grd(Nn / 32, Cn / 32, Bn);
        transpose_kernel<<<grd, blk, 0, s2>>>(features, fthp);
    }
    cudaEventRecord(eJoin, s2);

    // Main stream: binning pipeline
    bin_zero_kernel<<<(Bn * NCELL + 255) / 256, 256>>>(cntp);
    bin_count_kernel<<<(Bn * Nn + 255) / 256, 256>>>(xyz, cntp);
    bin_scan_kernel<<<Bn, NCELL>>>(cntp, stp, curp);
    bin_scatter_kernel<<<(Bn * Nn + 255) / 256, 256>>>(xyz, curp, ptsp);

    // Join, then fused persistent ball-query + MLP + max
    cudaStreamWaitEvent(0, eJoin, 0);
    fused_kernel<<<NCTA, 256, SMEM_BYTES>>>(xyz, ptsp, stp, cntp,
                                            W1, b1, W2, b2, out);
}

// round 12
// speedup vs baseline: 2.5144x; 1.2266x over previous
#include <cuda_runtime.h>
#include <cuda_fp16.h>
#include <cstdint>

// Problem constants (fixed shapes per reference setup_inputs)
#define Bn      8
#define Nn      8192
#define Cn      64
#define NP      2048
#define NS      32
#define CIN     67
#define H1n     64
#define H2n     128
#define RADIUS2 0.01f

#define GRID    8
#define NCELL   (GRID * GRID * GRID)     // 512 per batch
#define CAND_MAX 288
#define NCTA    296                      // persistent: 2 CTAs x 148 SMs

// Scratch (allocation-free rule: __device__ globals)
__device__ __half g_featTh[(size_t)Bn * Nn * Cn];      // 8 MB, (B,N,C) fp16
__device__ float4 g_pts[Bn * Nn];                      // 1 MB cell-sorted pts
__device__ int    g_cellCount[Bn * NCELL];
__device__ int    g_cellStart[Bn * NCELL];
__device__ int    g_cursor[Bn * NCELL];

typedef unsigned long long ull;

// ---------------------------------------------------------------------------
// fp16 mma / ldmatrix helpers
// ---------------------------------------------------------------------------
__device__ __forceinline__ void mma_f16(float c[4], const unsigned a[4],
                                        unsigned b0, unsigned b1)
{
    asm volatile(
        "mma.sync.aligned.m16n8k16.row.col.f32.f16.f16.f32 "
        "{%0,%1,%2,%3}, {%4,%5,%6,%7}, {%8,%9}, {%0,%1,%2,%3};"
        : "+f"(c[0]), "+f"(c[1]), "+f"(c[2]), "+f"(c[3])
        : "r"(a[0]), "r"(a[1]), "r"(a[2]), "r"(a[3]), "r"(b0), "r"(b1));
}

__device__ __forceinline__ void ldsm4(unsigned* r, unsigned addr)
{
    asm volatile("ldmatrix.sync.aligned.m8n8.x4.shared.b16 {%0,%1,%2,%3}, [%4];"
                 : "=r"(r[0]), "=r"(r[1]), "=r"(r[2]), "=r"(r[3]) : "r"(addr));
}

__device__ __forceinline__ unsigned h2pack(float lo, float hi)
{
    __half2 h = __floats2half2_rn(lo, hi);
    return *(unsigned*)&h;
}

__device__ __forceinline__ int cell_of(float x, float y, float z)
{
    int cx = min(GRID - 1, max(0, (int)(x * (float)GRID)));
    int cy = min(GRID - 1, max(0, (int)(y * (float)GRID)));
    int cz = min(GRID - 1, max(0, (int)(z * (float)GRID)));
    return cx + GRID * (cy + GRID * cz);
}

// ---------------------------------------------------------------------------
// Binning kernels
// ---------------------------------------------------------------------------
__global__ void bin_zero_kernel(int* __restrict__ count)
{
    int t = blockIdx.x * blockDim.x + threadIdx.x;
    if (t < Bn * NCELL) count[t] = 0;
}

__global__ void bin_count_kernel(const float* __restrict__ xyz, int* __restrict__ count)
{
    int t = blockIdx.x * blockDim.x + threadIdx.x;
    if (t >= Bn * Nn) return;
    int b = t >> 13;                       // Nn = 8192
    float x = xyz[t * 3 + 0], y = xyz[t * 3 + 1], z = xyz[t * 3 + 2];
    atomicAdd(&count[b * NCELL + cell_of(x, y, z)], 1);
}

__global__ void bin_scan_kernel(const int* __restrict__ count,
                                int* __restrict__ start, int* __restrict__ cursor)
{
    __shared__ int sc[NCELL];
    int b = blockIdx.x, t = threadIdx.x;   // 512 threads
    int c0 = count[b * NCELL + t];
    sc[t] = c0;
    __syncthreads();
    #pragma unroll
    for (int off = 1; off < NCELL; off <<= 1) {
        int v = (t >= off) ? sc[t - off] : 0;
        __syncthreads();
        sc[t] += v;
        __syncthreads();
    }
    int excl = sc[t] - c0;
    start[b * NCELL + t]  = excl;
    cursor[b * NCELL + t] = excl;
}

__global__ void bin_scatter_kernel(const float* __restrict__ xyz,
                                   int* __restrict__ cursor, float4* __restrict__ pts)
{
    int t = blockIdx.x * blockDim.x + threadIdx.x;
    if (t >= Bn * Nn) return;
    int b = t >> 13;
    int n = t & (Nn - 1);
    float x = xyz[t * 3 + 0], y = xyz[t * 3 + 1], z = xyz[t * 3 + 2];
    int pos = atomicAdd(&cursor[b * NCELL + cell_of(x, y, z)], 1);
    pts[(size_t)b * Nn + pos] = make_float4(x, y, z, __int_as_float(n));
}

// ---------------------------------------------------------------------------
// Kernel 2: transpose features (B,C,N) f32 -> (B,N,C) fp16.
// ---------------------------------------------------------------------------
__global__ void transpose_kernel(const float* __restrict__ f, __half* __restrict__ ft)
{
    __shared__ float tile[32][33];
    int b  = blockIdx.z;
    int c0 = blockIdx.y * 32;
    int n0 = blockIdx.x * 32;
    int tx = threadIdx.x, ty = threadIdx.y;

    const float* fb = f + (size_t)b * Cn * Nn;
    tile[ty][tx] = fb[(size_t)(c0 + ty) * Nn + (n0 + tx)];
    __syncthreads();
    ft[(size_t)b * Nn * Cn + (size_t)(n0 + ty) * Cn + (c0 + tx)] =
        __float2half_rn(tile[tx][ty]);
}

// ---------------------------------------------------------------------------
// FUSED persistent kernel: grid ball query + group + MLP + max.
// 256 threads = 8 warps; each warp independently streams queries.
// R12: lane-parallel cell-descriptor prefetch + drop-max selection.
// ---------------------------------------------------------------------------
#define A_STR   88
#define W1_STR  88
#define W2_STR  72
#define A_OFF   0
#define W1_OFF  (256 * A_STR)               // 22528 halfs
#define W2_OFF  (W1_OFF + 64 * W1_STR)      // 28160
#define HALF_END (W2_OFF + 128 * W2_STR)    // 37376 halfs = 74752 B
#define BIAS_BYTES ((64 + 128) * 4)
#define CBUF_OFF_B (HALF_END * 2 + BIAS_BYTES)
#define SMEM_BYTES (CBUF_OFF_B + 8 * CAND_MAX * 4)

__global__ __launch_bounds__(256, 2) void fused_kernel(
    const float*  __restrict__ xyz,
    const float4* __restrict__ pts,
    const int*    __restrict__ cellStart,
    const int*    __restrict__ cellCount,
    const float*  __restrict__ W1,
    const float*  __restrict__ b1,
    const float*  __restrict__ W2,
    const float*  __restrict__ b2,
    float* __restrict__ out)
{
    extern __shared__ __half smh[];
    __half* Ah  = smh + A_OFF;
    __half* w1s = smh + W1_OFF;
    __half* w2s = smh + W2_OFF;
    float* b1s = (float*)(smh + HALF_END);
    float* b2s = b1s + 64;
    int*   cbuf = (int*)((char*)smh + CBUF_OFF_B);

    const unsigned smb = (unsigned)__cvta_generic_to_shared(smh);

    const int tid  = threadIdx.x;
    const int lane = tid & 31;
    const int q    = tid >> 5;
    const int kk   = lane & 3;
    const int r    = lane >> 2;

    // ---- stage weights ONCE (fp16; W1 cols permuted: feat 0..63, rel 64..66) ----
    for (int i = tid; i < 64 * W1_STR; i += 256) {
        int o = i / W1_STR, k = i - o * W1_STR;
        float w = 0.0f;
        if (k < CIN) {
            int src = (k < 64) ? (k + 3) : (k - 64);
            w = __ldg(&W1[o * CIN + src]);
        }
        w1s[i] = __float2half_rn(w);
    }
    for (int i = tid; i < 128 * W2_STR; i += 256) {
        int o = i / W2_STR, k = i - o * W2_STR;
        w2s[i] = __float2half_rn((k < H1n) ? __ldg(&W2[o * H1n + k]) : 0.0f);
    }
    if (tid < 64)  b1s[tid] = b1[tid];
    if (tid >= 128 && tid < 256) b2s[tid - 128] = b2[tid - 128];

    // zero-pad A cols 67..87 once
    {
        __half* arow = Ah + tid * A_STR;
        #pragma unroll
        for (int k = 67; k < A_STR; k++) arow[k] = __ushort_as_half(0);
    }
    __syncthreads();

    // ldmatrix lane addressing
    const int rowbase = q * 32;
    const int rr = lane & 15;
    const int ch = (lane >> 4) * 8;
    const unsigned aBase0 = smb + (unsigned)(((rowbase + rr) * A_STR + ch) * 2);
    const unsigned aBase1 = aBase0 + 16 * A_STR * 2;
    const unsigned w1Base = smb + (unsigned)((W1_OFF + rr * W1_STR + ch) * 2);
    const unsigned w2Base = smb + (unsigned)((W2_OFF + rr * W2_STR + ch) * 2);

    int* buf = cbuf + q * CAND_MAX;
    const int totwarps = NCTA * 8;
    const int gwarp = blockIdx.x * 8 + q;

    for (int gq = gwarp; gq < Bn * NP; gq += totwarps) {
        const int b = gq >> 11;              // NP = 2048
        const int s = gq & (NP - 1);

        // ================== per-warp grid ball query ==================
        const float qx = __ldg(&xyz[((size_t)b * Nn + s) * 3 + 0]);
        const float qy = __ldg(&xyz[((size_t)b * Nn + s) * 3 + 1]);
        const float qz = __ldg(&xyz[((size_t)b * Nn + s) * 3 + 2]);

        if (lane < 3) {
            float v = (lane == 0) ? qx : (lane == 1) ? qy : qz;
            out[(size_t)gq * 3 + lane] = v;
        }

        const int cx = min(GRID - 1, max(0, (int)(qx * (float)GRID)));
        const int cy = min(GRID - 1, max(0, (int)(qy * (float)GRID)));
        const int cz = min(GRID - 1, max(0, (int)(qz * (float)GRID)));

        const int x0 = max(cx - 1, 0), x1 = min(cx + 1, GRID - 1);
        const int y0 = max(cy - 1, 0), y1 = min(cy + 1, GRID - 1);
        const int z0 = max(cz - 1, 0), z1 = min(cz + 1, GRID - 1);
        const int nx = x1 - x0 + 1, ny = y1 - y0 + 1, nz = z1 - z0 + 1;
        const int ncells = nx * ny * nz;     // <= 27

        // lane-parallel descriptor prefetch: one L2 round trip for all cells
        int stL = 0, cntL = 0;
        if (lane < ncells) {
            int lx = lane % nx;
            int rem = lane / nx;
            int ly = rem % ny;
            int lz = rem / ny;
            int c = b * NCELL + (x0 + lx) + GRID * ((y0 + ly) + GRID * (z0 + lz));
            stL  = __ldg(&cellStart[c]);
            cntL = __ldg(&cellCount[c]);
        }

        int K = 0;
        const float4* pb = pts + (size_t)b * Nn;

        for (int cc = 0; cc < ncells; cc++) {
            const int st  = __shfl_sync(0xffffffffu, stL,  cc);
            const int cnt = __shfl_sync(0xffffffffu, cntL, cc);
            for (int p0 = 0; p0 < cnt; p0 += 32) {
                int p  = p0 + lane;
                int pp = min(p, cnt - 1);
                float4 pt = __ldg(&pb[st + pp]);
                float dx = pt.x - qx, dy = pt.y - qy, dz = pt.z - qz;
                float d2 = dx * dx + dy * dy + dz * dz;
                bool in = (p < cnt) && (d2 < RADIUS2);
                unsigned m = __ballot_sync(0xffffffffu, in);
                int pos = K + __popc(m & ((1u << lane) - 1u));
                if (in && pos < CAND_MAX) buf[pos] = __float_as_int(pt.w);
                K += __popc(m);
            }
        }
        __syncwarp();

        int myid;
        if (K <= NS) {
            myid = buf[(lane < K) ? lane : 0];
        } else if (K <= CAND_MAX) {
            // drop-max selection: remove the K-NS largest (expected ~2-8)
            int loc[(CAND_MAX + 31) / 32];
            #pragma unroll
            for (int j = 0; j < (CAND_MAX + 31) / 32; j++) {
                int p = lane + 32 * j;
                loc[j] = (p < K) ? buf[p] : -1;
            }
            int lmax = -1;
            #pragma unroll
            for (int j = 0; j < (CAND_MAX + 31) / 32; j++) lmax = max(lmax, loc[j]);

            const int excess = K - NS;
            for (int e = 0; e < excess; e++) {
                int m = lmax;
                m = max(m, __shfl_xor_sync(0xffffffffu, m, 16));
                m = max(m, __shfl_xor_sync(0xffffffffu, m, 8));
                m = max(m, __shfl_xor_sync(0xffffffffu, m, 4));
                m = max(m, __shfl_xor_sync(0xffffffffu, m, 2));
                m = max(m, __shfl_xor_sync(0xffffffffu, m, 1));
                unsigned own = __ballot_sync(0xffffffffu, lmax == m);
                if (lane == (__ffs(own) - 1)) {
                    #pragma unroll
                    for (int j = 0; j < (CAND_MAX + 31) / 32; j++)
                        if (loc[j] == m) loc[j] = -1;      // indices distinct
                    lmax = -1;
                    #pragma unroll
                    for (int j = 0; j < (CAND_MAX + 31) / 32; j++)
                        lmax = max(lmax, loc[j]);
                }
            }
            // compact exactly 32 survivors into buf
            int pos = 0;
            #pragma unroll
            for (int j = 0; j < (CAND_MAX + 31) / 32; j++) {
                bool alive = loc[j] >= 0;
                unsigned mm = __ballot_sync(0xffffffffu, alive);
                if (alive) buf[pos + __popc(mm & ((1u << lane) - 1u))] = loc[j];
                pos += __popc(mm);
            }
            __syncwarp();
            myid = buf[lane];
        } else {
            // exact fallback: ordered linear scan into buf
            int cnt = 0, first_idx = 0;
            const float* xb = xyz + (size_t)b * Nn * 3;
            for (int base = 0; base < Nn; base += 32) {
                int i = base + lane;
                float dx = __ldg(&xb[i * 3 + 0]) - qx;
                float dy = __ldg(&xb[i * 3 + 1]) - qy;
                float dz = __ldg(&xb[i * 3 + 2]) - qz;
                float d2 = dx * dx + dy * dy + dz * dz;
                unsigned bits = __ballot_sync(0xffffffffu, d2 < RADIUS2);
                if (bits) {
                    if (cnt == 0) first_idx = base + __ffs(bits) - 1;
                    if ((bits >> lane) & 1u) {
                        int pos = cnt + __popc(bits & ((1u << lane) - 1u));
                        if (pos < NS) buf[pos] = i;
                    }
                    cnt += __popc(bits);
                    if (cnt >= NS) break;
                }
            }
            if (cnt < NS) {
                int slot = cnt + lane;
                if (slot < NS) buf[slot] = first_idx;
            }
            __syncwarp();
            myid = buf[lane];
        }

        // ================== stage A row (this thread's row = tid) ==================
        {
            const float* xb = xyz + (size_t)b * Nn * 3;
            __half* arow = Ah + tid * A_STR;
            const ull* src = (const ull*)(g_featTh + ((size_t)b * Nn + myid) * Cn);
            ull* dst = (ull*)arow;
            #pragma unroll
            for (int j = 0; j < 16; j++) dst[j] = __ldg(&src[j]);
            arow[64] = __float2half_rn(__ldg(&xb[myid * 3 + 0]) - qx);
            arow[65] = __float2half_rn(__ldg(&xb[myid * 3 + 1]) - qy);
            arow[66] = __float2half_rn(__ldg(&xb[myid * 3 + 2]) - qz);
        }
        __syncwarp();

        // ================== Layer 1 (K=80 -> 5 k-groups) ==================
        float c1[2][8][4];
        #pragma unroll
        for (int nt = 0; nt < 8; nt++) {
            float blo = b1s[nt * 8 + 2 * kk];
            float bhi = b1s[nt * 8 + 2 * kk + 1];
            #pragma unroll
            for (int mt = 0; mt < 2; mt++) {
                c1[mt][nt][0] = blo; c1[mt][nt][1] = bhi;
                c1[mt][nt][2] = blo; c1[mt][nt][3] = bhi;
            }
        }

        #pragma unroll
        for (int kg = 0; kg < 5; kg++) {
            unsigned a0[4], a1[4];
            ldsm4(a0, aBase0 + kg * 32);
            ldsm4(a1, aBase1 + kg * 32);
            #pragma unroll
            for (int p = 0; p < 4; p++) {
                unsigned bf[4];
                ldsm4(bf, w1Base + (unsigned)(16 * p * W1_STR * 2) + kg * 32);
                mma_f16(c1[0][2 * p],     a0, bf[0], bf[2]);
                mma_f16(c1[0][2 * p + 1], a0, bf[1], bf[3]);
                mma_f16(c1[1][2 * p],     a1, bf[0], bf[2]);
                mma_f16(c1[1][2 * p + 1], a1, bf[1], bf[3]);
            }
        }
        __syncwarp();

        // store relu(h1) fp16 into warp-local A rows (cols 0..63)
        #pragma unroll
        for (int mt = 0; mt < 2; mt++)
            #pragma unroll
            for (int nt = 0; nt < 8; nt++)
                #pragma unroll
                for (int i = 0; i < 2; i++) {
                    int row = rowbase + mt * 16 + r + 8 * i;
                    unsigned pk = h2pack(fmaxf(c1[mt][nt][2 * i + 0], 0.0f),
                                         fmaxf(c1[mt][nt][2 * i + 1], 0.0f));
                    *(unsigned*)&Ah[row * A_STR + nt * 8 + 2 * kk] = pk;
                }
        __syncwarp();

        // hoist L2 A fragments (K=64 -> 4 k-groups)
        unsigned afrag[4][8];
        #pragma unroll
        for (int kg = 0; kg < 4; kg++) {
            ldsm4(&afrag[kg][0], aBase0 + kg * 32);
            ldsm4(&afrag[kg][4], aBase1 + kg * 32);
        }

        float* op_base = out + (Bn * NP * 3) + (size_t)b * H2n * NP + s;

        #pragma unroll
        for (int h = 0; h < 2; h++) {
            float c2[2][8][4];
            #pragma unroll
            for (int nt = 0; nt < 8; nt++) {
                int o = h * 64 + nt * 8;
                float blo = b2s[o + 2 * kk];
                float bhi = b2s[o + 2 * kk + 1];
                #pragma unroll
                for (int mt = 0; mt < 2; mt++) {
                    c2[mt][nt][0] = blo; c2[mt][nt][1] = bhi;
                    c2[mt][nt][2] = blo; c2[mt][nt][3] = bhi;
                }
            }

            #pragma unroll
            for (int kg = 0; kg < 4; kg++) {
                #pragma unroll
                for (int p = 0; p < 4; p++) {
                    unsigned bf[4];
                    ldsm4(bf, w2Base + (unsigned)(16 * (h * 4 + p) * W2_STR * 2) + kg * 32);
                    mma_f16(c2[0][2 * p],     &afrag[kg][0], bf[0], bf[2]);
                    mma_f16(c2[0][2 * p + 1], &afrag[kg][0], bf[1], bf[3]);
                    mma_f16(c2[1][2 * p],     &afrag[kg][4], bf[0], bf[2]);
                    mma_f16(c2[1][2 * p + 1], &afrag[kg][4], bf[1], bf[3]);
                }
            }

            #pragma unroll
            for (int nt = 0; nt < 8; nt++)
                #pragma unroll
                for (int j = 0; j < 2; j++) {
                    float v = fmaxf(fmaxf(c2[0][nt][j], c2[0][nt][j + 2]),
                                    fmaxf(c2[1][nt][j], c2[1][nt][j + 2]));
                    v = fmaxf(v, __shfl_xor_sync(0xffffffffu, v, 4));
                    v = fmaxf(v, __shfl_xor_sync(0xffffffffu, v, 8));
                    v = fmaxf(v, __shfl_xor_sync(0xffffffffu, v, 16));
                    if (r == 0) {
                        int col = h * 64 + nt * 8 + 2 * kk + j;
                        op_base[(size_t)col * NP] = fmaxf(v, 0.0f);
                    }
                }
        }
        __syncwarp();   // h1/A reads done before next iteration restages
    }
}

// ---------------------------------------------------------------------------
extern "C" void kernel_launch(void* const* d_in, const int* in_sizes, int n_in,
                              void* d_out, int out_size)
{
    const float* xyz      = (const float*)d_in[0];
    const float* features = (const float*)d_in[1];
    const float* W1       = (const float*)d_in[2];
    const float* b1       = (const float*)d_in[3];
    const float* W2       = (const float*)d_in[4];
    const float* b2       = (const float*)d_in[5];
    float* out = (float*)d_out;

    static bool init_done = false;
    static cudaStream_t s2;
    static cudaEvent_t eFork, eJoin;
    if (!init_done) {
        cudaFuncSetAttribute(fused_kernel, cudaFuncAttributeMaxDynamicSharedMemorySize,
                             SMEM_BYTES);
        cudaStreamCreateWithFlags(&s2, cudaStreamNonBlocking);
        cudaEventCreateWithFlags(&eFork, cudaEventDisableTiming);
        cudaEventCreateWithFlags(&eJoin, cudaEventDisableTiming);
        init_done = true;
    }

    __half* fthp;   cudaGetSymbolAddress((void**)&fthp, g_featTh);
    float4* ptsp;   cudaGetSymbolAddress((void**)&ptsp, g_pts);
    int*    cntp;   cudaGetSymbolAddress((void**)&cntp, g_cellCount);
    int*    stp;    cudaGetSymbolAddress((void**)&stp,  g_cellStart);
    int*    curp;   cudaGetSymbolAddress((void**)&curp, g_cursor);

    // Fork: transpose (depends only on features) on s2, parallel to binning.
    cudaEventRecord(eFork, 0);
    cudaStreamWaitEvent(s2, eFork, 0);
    {
        dim3 blk(32, 32, 1);
        dim3 grd(Nn / 32, Cn / 32, Bn);
        transpose_kernel<<<grd, blk, 0, s2>>>(features, fthp);
    }
    cudaEventRecord(eJoin, s2);

    // Main stream: binning pipeline
    bin_zero_kernel<<<(Bn * NCELL + 255) / 256, 256>>>(cntp);
    bin_count_kernel<<<(Bn * Nn + 255) / 256, 256>>>(xyz, cntp);
    bin_scan_kernel<<<Bn, NCELL>>>(cntp, stp, curp);
    bin_scatter_kernel<<<(Bn * Nn + 255) / 256, 256>>>(xyz, curp, ptsp);

    // Join, then fused persistent ball-query + MLP + max
    cudaStreamWaitEvent(0, eJoin, 0);
    fused_kernel<<<NCTA, 256, SMEM_BYTES>>>(xyz, ptsp, stp, cntp,
                                            W1, b1, W2, b2, out);
}

// round 13
// speedup vs baseline: 2.8053x; 1.1157x over previous
#include <cuda_runtime.h>
#include <cuda_fp16.h>
#include <cstdint>

// Problem constants (fixed shapes per reference setup_inputs)
#define Bn      8
#define Nn      8192
#define Cn      64
#define NP      2048
#define NS      32
#define CIN     67
#define H1n     64
#define H2n     128
#define RADIUS2 0.01f

#define GRID    8
#define NCELL   (GRID * GRID * GRID)     // 512 per batch
#define CAND_MAX 288
#define NCTA    296                      // persistent: 2 CTAs x 148 SMs

// Scratch (allocation-free rule: __device__ globals)
__device__ __half g_featTh[(size_t)Bn * Nn * Cn];      // 8 MB, (B,N,C) fp16
__device__ float4 g_pts[Bn * Nn];                      // 1 MB cell-sorted pts
__device__ int    g_cellCount[Bn * NCELL];
__device__ int    g_cellStart[Bn * NCELL];

typedef unsigned long long ull;

// ---------------------------------------------------------------------------
// fp16 mma / ldmatrix helpers
// ---------------------------------------------------------------------------
__device__ __forceinline__ void mma_f16(float c[4], const unsigned a[4],
                                        unsigned b0, unsigned b1)
{
    asm volatile(
        "mma.sync.aligned.m16n8k16.row.col.f32.f16.f16.f32 "
        "{%0,%1,%2,%3}, {%4,%5,%6,%7}, {%8,%9}, {%0,%1,%2,%3};"
        : "+f"(c[0]), "+f"(c[1]), "+f"(c[2]), "+f"(c[3])
        : "r"(a[0]), "r"(a[1]), "r"(a[2]), "r"(a[3]), "r"(b0), "r"(b1));
}

__device__ __forceinline__ void ldsm4(unsigned* r, unsigned addr)
{
    asm volatile("ldmatrix.sync.aligned.m8n8.x4.shared.b16 {%0,%1,%2,%3}, [%4];"
                 : "=r"(r[0]), "=r"(r[1]), "=r"(r[2]), "=r"(r[3]) : "r"(addr));
}

__device__ __forceinline__ unsigned h2pack(float lo, float hi)
{
    __half2 h = __floats2half2_rn(lo, hi);
    return *(unsigned*)&h;
}

__device__ __forceinline__ int cell_of(float x, float y, float z)
{
    int cx = min(GRID - 1, max(0, (int)(x * (float)GRID)));
    int cy = min(GRID - 1, max(0, (int)(y * (float)GRID)));
    int cz = min(GRID - 1, max(0, (int)(z * (float)GRID)));
    return cx + GRID * (cy + GRID * cz);
}

// ---------------------------------------------------------------------------
// Single-kernel binning: one 1024-thread CTA per batch.
// count (smem atomics) -> scan (smem) -> scatter; points kept in registers.
// ---------------------------------------------------------------------------
__global__ __launch_bounds__(1024) void bin_all_kernel(
    const float* __restrict__ xyz,
    float4* __restrict__ pts,
    int* __restrict__ cellStart, int* __restrict__ cellCount)
{
    __shared__ int sc[NCELL];
    __shared__ int scur[NCELL];

    const int b = blockIdx.x;
    const int t = threadIdx.x;          // 0..1023, 8 points per thread

    if (t < NCELL) sc[t] = 0;
    __syncthreads();

    const float* xb = xyz + (size_t)b * Nn * 3;
    float px[8], py[8], pz[8];
    int   pc[8];

    #pragma unroll
    for (int j = 0; j < 8; j++) {
        int i = t + j * 1024;
        px[j] = xb[i * 3 + 0];
        py[j] = xb[i * 3 + 1];
        pz[j] = xb[i * 3 + 2];
        pc[j] = cell_of(px[j], py[j], pz[j]);
        atomicAdd(&sc[pc[j]], 1);
    }
    __syncthreads();

    // inclusive scan over 512 cells (Hillis-Steele), barriers block-wide
    int c0 = (t < NCELL) ? sc[t] : 0;
    for (int off = 1; off < NCELL; off <<= 1) {
        int v = 0;
        if (t < NCELL && t >= off) v = sc[t - off];
        __syncthreads();
        if (t < NCELL) sc[t] += v;
        __syncthreads();
    }
    if (t < NCELL) {
        int excl = sc[t] - c0;
        cellStart[b * NCELL + t] = excl;
        cellCount[b * NCELL + t] = c0;
        scur[t] = excl;
    }
    __syncthreads();

    float4* pout = pts + (size_t)b * Nn;
    #pragma unroll
    for (int j = 0; j < 8; j++) {
        int i = t + j * 1024;
        int pos = atomicAdd(&scur[pc[j]], 1);
        pout[pos] = make_float4(px[j], py[j], pz[j], __int_as_float(i));
    }
}

// ---------------------------------------------------------------------------
// Transpose features (B,C,N) f32 -> (B,N,C) fp16. Vectorized: 256 threads,
// tile C=32 x N=64, float4 loads + ull stores, 2 tiles of work per thread.
// ---------------------------------------------------------------------------
__global__ __launch_bounds__(256) void transpose_kernel(
    const float* __restrict__ f, __half* __restrict__ ft)
{
    __shared__ float tile[64][33];      // [n][c], stride 33
    const int b  = blockIdx.z;
    const int c0 = blockIdx.y * 32;
    const int n0 = blockIdx.x * 64;
    const int t  = threadIdx.x;

    const float* fb = f + (size_t)b * Cn * Nn;

    #pragma unroll
    for (int j = 0; j < 2; j++) {
        int idx = t + j * 256;          // 0..511
        int c   = idx >> 4;             // 0..31
        int n4  = (idx & 15) * 4;       // 0..60
        float4 v = __ldg((const float4*)&fb[(size_t)(c0 + c) * Nn + n0 + n4]);
        tile[n4 + 0][c] = v.x;
        tile[n4 + 1][c] = v.y;
        tile[n4 + 2][c] = v.z;
        tile[n4 + 3][c] = v.w;
    }
    __syncthreads();

    __half* fo = ft + (size_t)b * Nn * Cn;
    #pragma unroll
    for (int j = 0; j < 2; j++) {
        int idx = t + j * 256;          // 0..511
        int n   = idx >> 3;             // 0..63
        int c4  = (idx & 7) * 4;        // 0..28
        unsigned lo = h2pack(tile[n][c4 + 0], tile[n][c4 + 1]);
        unsigned hi = h2pack(tile[n][c4 + 2], tile[n][c4 + 3]);
        ull pk = (ull)lo | ((ull)hi << 32);
        *(ull*)&fo[(size_t)(n0 + n) * Cn + c0 + c4] = pk;
    }
}

// ---------------------------------------------------------------------------
// FUSED persistent kernel: grid ball query + group + MLP + max.
// R13: register double-buffer prefetch of next cell's point chunk.
// ---------------------------------------------------------------------------
#define A_STR   88
#define W1_STR  88
#define W2_STR  72
#define A_OFF   0
#define W1_OFF  (256 * A_STR)               // 22528 halfs
#define W2_OFF  (W1_OFF + 64 * W1_STR)      // 28160
#define HALF_END (W2_OFF + 128 * W2_STR)    // 37376 halfs = 74752 B
#define BIAS_BYTES ((64 + 128) * 4)
#define CBUF_OFF_B (HALF_END * 2 + BIAS_BYTES)
#define SMEM_BYTES (CBUF_OFF_B + 8 * CAND_MAX * 4)

__global__ __launch_bounds__(256, 2) void fused_kernel(
    const float*  __restrict__ xyz,
    const float4* __restrict__ pts,
    const int*    __restrict__ cellStart,
    const int*    __restrict__ cellCount,
    const float*  __restrict__ W1,
    const float*  __restrict__ b1,
    const float*  __restrict__ W2,
    const float*  __restrict__ b2,
    float* __restrict__ out)
{
    extern __shared__ __half smh[];
    __half* Ah  = smh + A_OFF;
    __half* w1s = smh + W1_OFF;
    __half* w2s = smh + W2_OFF;
    float* b1s = (float*)(smh + HALF_END);
    float* b2s = b1s + 64;
    int*   cbuf = (int*)((char*)smh + CBUF_OFF_B);

    const unsigned smb = (unsigned)__cvta_generic_to_shared(smh);

    const int tid  = threadIdx.x;
    const int lane = tid & 31;
    const int q    = tid >> 5;
    const int kk   = lane & 3;
    const int r    = lane >> 2;

    // ---- stage weights ONCE (fp16; W1 cols permuted: feat 0..63, rel 64..66) ----
    for (int i = tid; i < 64 * W1_STR; i += 256) {
        int o = i / W1_STR, k = i - o * W1_STR;
        float w = 0.0f;
        if (k < CIN) {
            int src = (k < 64) ? (k + 3) : (k - 64);
            w = __ldg(&W1[o * CIN + src]);
        }
        w1s[i] = __float2half_rn(w);
    }
    for (int i = tid; i < 128 * W2_STR; i += 256) {
        int o = i / W2_STR, k = i - o * W2_STR;
        w2s[i] = __float2half_rn((k < H1n) ? __ldg(&W2[o * H1n + k]) : 0.0f);
    }
    if (tid < 64)  b1s[tid] = b1[tid];
    if (tid >= 128 && tid < 256) b2s[tid - 128] = b2[tid - 128];

    // zero-pad A cols 67..87 once
    {
        __half* arow = Ah + tid * A_STR;
        #pragma unroll
        for (int k = 67; k < A_STR; k++) arow[k] = __ushort_as_half(0);
    }
    __syncthreads();

    // ldmatrix lane addressing
    const int rowbase = q * 32;
    const int rr = lane & 15;
    const int ch = (lane >> 4) * 8;
    const unsigned aBase0 = smb + (unsigned)(((rowbase + rr) * A_STR + ch) * 2);
    const unsigned aBase1 = aBase0 + 16 * A_STR * 2;
    const unsigned w1Base = smb + (unsigned)((W1_OFF + rr * W1_STR + ch) * 2);
    const unsigned w2Base = smb + (unsigned)((W2_OFF + rr * W2_STR + ch) * 2);

    int* buf = cbuf + q * CAND_MAX;
    const int totwarps = NCTA * 8;
    const int gwarp = blockIdx.x * 8 + q;

    for (int gq = gwarp; gq < Bn * NP; gq += totwarps) {
        const int b = gq >> 11;              // NP = 2048
        const int s = gq & (NP - 1);

        // ================== per-warp grid ball query ==================
        const float qx = __ldg(&xyz[((size_t)b * Nn + s) * 3 + 0]);
        const float qy = __ldg(&xyz[((size_t)b * Nn + s) * 3 + 1]);
        const float qz = __ldg(&xyz[((size_t)b * Nn + s) * 3 + 2]);

        if (lane < 3) {
            float v = (lane == 0) ? qx : (lane == 1) ? qy : qz;
            out[(size_t)gq * 3 + lane] = v;
        }

        const int cx = min(GRID - 1, max(0, (int)(qx * (float)GRID)));
        const int cy = min(GRID - 1, max(0, (int)(qy * (float)GRID)));
        const int cz = min(GRID - 1, max(0, (int)(qz * (float)GRID)));

        const int x0 = max(cx - 1, 0), x1 = min(cx + 1, GRID - 1);
        const int y0 = max(cy - 1, 0), y1 = min(cy + 1, GRID - 1);
        const int z0 = max(cz - 1, 0), z1 = min(cz + 1, GRID - 1);
        const int nx = x1 - x0 + 1, ny = y1 - y0 + 1, nz = z1 - z0 + 1;
        const int ncells = nx * ny * nz;     // <= 27

        // lane-parallel descriptor prefetch: one L2 round trip for all cells
        int stL = 0, cntL = 0;
        if (lane < ncells) {
            int lx = lane % nx;
            int rem = lane / nx;
            int ly = rem % ny;
            int lz = rem / ny;
            int c = b * NCELL + (x0 + lx) + GRID * ((y0 + ly) + GRID * (z0 + lz));
            stL  = __ldg(&cellStart[c]);
            cntL = __ldg(&cellCount[c]);
        }

        int K = 0;
        const float4* pb = pts + (size_t)b * Nn;

        // register double-buffer: prefetch cell cc+1's first chunk during cc
        float4 pt = make_float4(1e9f, 1e9f, 1e9f, 0.0f);
        {
            int st0  = __shfl_sync(0xffffffffu, stL,  0);
            int cnt0 = __shfl_sync(0xffffffffu, cntL, 0);
            if (cnt0 > 0) pt = __ldg(&pb[st0 + min(lane, cnt0 - 1)]);
        }

        for (int cc = 0; cc < ncells; cc++) {
            const int st  = __shfl_sync(0xffffffffu, stL,  cc);
            const int cnt = __shfl_sync(0xffffffffu, cntL, cc);
            float4 cur = pt;

            // prefetch next cell's first chunk (independent of this ballot)
            if (cc + 1 < ncells) {
                int stn  = __shfl_sync(0xffffffffu, stL,  cc + 1);
                int cntn = __shfl_sync(0xffffffffu, cntL, cc + 1);
                if (cntn > 0) pt = __ldg(&pb[stn + min(lane, cntn - 1)]);
            }

            // first chunk of this cell
            {
                float dx = cur.x - qx, dy = cur.y - qy, dz = cur.z - qz;
                float d2 = dx * dx + dy * dy + dz * dz;
                bool in = (lane < cnt) && (d2 < RADIUS2);
                unsigned m = __ballot_sync(0xffffffffu, in);
                int pos = K + __popc(m & ((1u << lane) - 1u));
                if (in && pos < CAND_MAX) buf[pos] = __float_as_int(cur.w);
                K += __popc(m);
            }
            // rare extra chunks (cnt > 32)
            for (int p0 = 32; p0 < cnt; p0 += 32) {
                int p  = p0 + lane;
                float4 e = __ldg(&pb[st + min(p, cnt - 1)]);
                float dx = e.x - qx, dy = e.y - qy, dz = e.z - qz;
                float d2 = dx * dx + dy * dy + dz * dz;
                bool in = (p < cnt) && (d2 < RADIUS2);
                unsigned m = __ballot_sync(0xffffffffu, in);
                int pos = K + __popc(m & ((1u << lane) - 1u));
                if (in && pos < CAND_MAX) buf[pos] = __float_as_int(e.w);
                K += __popc(m);
            }
        }
        __syncwarp();

        int myid;
        if (K <= NS) {
            myid = buf[(lane < K) ? lane : 0];
        } else if (K <= CAND_MAX) {
            // drop-max selection: remove the K-NS largest (expected ~2-8)
            int loc[(CAND_MAX + 31) / 32];
            #pragma unroll
            for (int j = 0; j < (CAND_MAX + 31) / 32; j++) {
                int p = lane + 32 * j;
                loc[j] = (p < K) ? buf[p] : -1;
            }
            int lmax = -1;
            #pragma unroll
            for (int j = 0; j < (CAND_MAX + 31) / 32; j++) lmax = max(lmax, loc[j]);

            const int excess = K - NS;
            for (int e = 0; e < excess; e++) {
                int m = lmax;
                m = max(m, __shfl_xor_sync(0xffffffffu, m, 16));
                m = max(m, __shfl_xor_sync(0xffffffffu, m, 8));
                m = max(m, __shfl_xor_sync(0xffffffffu, m, 4));
                m = max(m, __shfl_xor_sync(0xffffffffu, m, 2));
                m = max(m, __shfl_xor_sync(0xffffffffu, m, 1));
                unsigned own = __ballot_sync(0xffffffffu, lmax == m);
                if (lane == (__ffs(own) - 1)) {
                    #pragma unroll
                    for (int j = 0; j < (CAND_MAX + 31) / 32; j++)
                        if (loc[j] == m) loc[j] = -1;      // indices distinct
                    lmax = -1;
                    #pragma unroll
                    for (int j = 0; j < (CAND_MAX + 31) / 32; j++)
                        lmax = max(lmax, loc[j]);
                }
            }
            // compact exactly 32 survivors into buf
            int pos = 0;
            #pragma unroll
            for (int j = 0; j < (CAND_MAX + 31) / 32; j++) {
                bool alive = loc[j] >= 0;
                unsigned mm = __ballot_sync(0xffffffffu, alive);
                if (alive) buf[pos + __popc(mm & ((1u << lane) - 1u))] = loc[j];
                pos += __popc(mm);
            }
            __syncwarp();
            myid = buf[lane];
        } else {
            // exact fallback: ordered linear scan into buf
            int cnt = 0, first_idx = 0;
            const float* xb = xyz + (size_t)b * Nn * 3;
            for (int base = 0; base < Nn; base += 32) {
                int i = base + lane;
                float dx = __ldg(&xb[i * 3 + 0]) - qx;
                float dy = __ldg(&xb[i * 3 + 1]) - qy;
                float dz = __ldg(&xb[i * 3 + 2]) - qz;
                float d2 = dx * dx + dy * dy + dz * dz;
                unsigned bits = __ballot_sync(0xffffffffu, d2 < RADIUS2);
                if (bits) {
                    if (cnt == 0) first_idx = base + __ffs(bits) - 1;
                    if ((bits >> lane) & 1u) {
                        int pos = cnt + __popc(bits & ((1u << lane) - 1u));
                        if (pos < NS) buf[pos] = i;
                    }
                    cnt += __popc(bits);
                    if (cnt >= NS) break;
                }
            }
            if (cnt < NS) {
                int slot = cnt + lane;
                if (slot < NS) buf[slot] = first_idx;
            }
            __syncwarp();
            myid = buf[lane];
        }

        // ================== stage A row (this thread's row = tid) ==================
        {
            const float* xb = xyz + (size_t)b * Nn * 3;
            __half* arow = Ah + tid * A_STR;
            const ull* src = (const ull*)(g_featTh + ((size_t)b * Nn + myid) * Cn);
            ull* dst = (ull*)arow;
            #pragma unroll
            for (int j = 0; j < 16; j++) dst[j] = __ldg(&src[j]);
            arow[64] = __float2half_rn(__ldg(&xb[myid * 3 + 0]) - qx);
            arow[65] = __float2half_rn(__ldg(&xb[myid * 3 + 1]) - qy);
            arow[66] = __float2half_rn(__ldg(&xb[myid * 3 + 2]) - qz);
        }
        __syncwarp();

        // ================== Layer 1 (K=80 -> 5 k-groups) ==================
        float c1[2][8][4];
        #pragma unroll
        for (int nt = 0; nt < 8; nt++) {
            float blo = b1s[nt * 8 + 2 * kk];
            float bhi = b1s[nt * 8 + 2 * kk + 1];
            #pragma unroll
            for (int mt = 0; mt < 2; mt++) {
                c1[mt][nt][0] = blo; c1[mt][nt][1] = bhi;
                c1[mt][nt][2] = blo; c1[mt][nt][3] = bhi;
            }
        }

        #pragma unroll
        for (int kg = 0; kg < 5; kg++) {
            unsigned a0[4], a1[4];
            ldsm4(a0, aBase0 + kg * 32);
            ldsm4(a1, aBase1 + kg * 32);
            #pragma unroll
            for (int p = 0; p < 4; p++) {
                unsigned bf[4];
                ldsm4(bf, w1Base + (unsigned)(16 * p * W1_STR * 2) + kg * 32);
                mma_f16(c1[0][2 * p],     a0, bf[0], bf[2]);
                mma_f16(c1[0][2 * p + 1], a0, bf[1], bf[3]);
                mma_f16(c1[1][2 * p],     a1, bf[0], bf[2]);
                mma_f16(c1[1][2 * p + 1], a1, bf[1], bf[3]);
            }
        }
        __syncwarp();

        // store relu(h1) fp16 into warp-local A rows (cols 0..63)
        #pragma unroll
        for (int mt = 0; mt < 2; mt++)
            #pragma unroll
            for (int nt = 0; nt < 8; nt++)
                #pragma unroll
                for (int i = 0; i < 2; i++) {
                    int row = rowbase + mt * 16 + r + 8 * i;
                    unsigned pk = h2pack(fmaxf(c1[mt][nt][2 * i + 0], 0.0f),
                                         fmaxf(c1[mt][nt][2 * i + 1], 0.0f));
                    *(unsigned*)&Ah[row * A_STR + nt * 8 + 2 * kk] = pk;
                }
        __syncwarp();

        // hoist L2 A fragments (K=64 -> 4 k-groups)
        unsigned afrag[4][8];
        #pragma unroll
        for (int kg = 0; kg < 4; kg++) {
            ldsm4(&afrag[kg][0], aBase0 + kg * 32);
            ldsm4(&afrag[kg][4], aBase1 + kg * 32);
        }

        float* op_base = out + (Bn * NP * 3) + (size_t)b * H2n * NP + s;

        #pragma unroll
        for (int h = 0; h < 2; h++) {
            float c2[2][8][4];
            #pragma unroll
            for (int nt = 0; nt < 8; nt++) {
                int o = h * 64 + nt * 8;
                float blo = b2s[o + 2 * kk];
                float bhi = b2s[o + 2 * kk + 1];
                #pragma unroll
                for (int mt = 0; mt < 2; mt++) {
                    c2[mt][nt][0] = blo; c2[mt][nt][1] = bhi;
                    c2[mt][nt][2] = blo; c2[mt][nt][3] = bhi;
                }
            }

            #pragma unroll
            for (int kg = 0; kg < 4; kg++) {
                #pragma unroll
                for (int p = 0; p < 4; p++) {
                    unsigned bf[4];
                    ldsm4(bf, w2Base + (unsigned)(16 * (h * 4 + p) * W2_STR * 2) + kg * 32);
                    mma_f16(c2[0][2 * p],     &afrag[kg][0], bf[0], bf[2]);
                    mma_f16(c2[0][2 * p + 1], &afrag[kg][0], bf[1], bf[3]);
                    mma_f16(c2[1][2 * p],     &afrag[kg][4], bf[0], bf[2]);
                    mma_f16(c2[1][2 * p + 1], &afrag[kg][4], bf[1], bf[3]);
                }
            }

            #pragma unroll
            for (int nt = 0; nt < 8; nt++)
                #pragma unroll
                for (int j = 0; j < 2; j++) {
                    float v = fmaxf(fmaxf(c2[0][nt][j], c2[0][nt][j + 2]),
                                    fmaxf(c2[1][nt][j], c2[1][nt][j + 2]));
                    v = fmaxf(v, __shfl_xor_sync(0xffffffffu, v, 4));
                    v = fmaxf(v, __shfl_xor_sync(0xffffffffu, v, 8));
                    v = fmaxf(v, __shfl_xor_sync(0xffffffffu, v, 16));
                    if (r == 0) {
                        int col = h * 64 + nt * 8 + 2 * kk + j;
                        op_base[(size_t)col * NP] = fmaxf(v, 0.0f);
                    }
                }
        }
        __syncwarp();   // h1/A reads done before next iteration restages
    }
}

// ---------------------------------------------------------------------------
extern "C" void kernel_launch(void* const* d_in, const int* in_sizes, int n_in,
                              void* d_out, int out_size)
{
    const float* xyz      = (const float*)d_in[0];
    const float* features = (const float*)d_in[1];
    const float* W1       = (const float*)d_in[2];
    const float* b1       = (const float*)d_in[3];
    const float* W2       = (const float*)d_in[4];
    const float* b2       = (const float*)d_in[5];
    float* out = (float*)d_out;

    static bool init_done = false;
    static cudaStream_t s2;
    static cudaEvent_t eFork, eJoin;
    if (!init_done) {
        cudaFuncSetAttribute(fused_kernel, cudaFuncAttributeMaxDynamicSharedMemorySize,
                             SMEM_BYTES);
        cudaStreamCreateWithFlags(&s2, cudaStreamNonBlocking);
        cudaEventCreateWithFlags(&eFork, cudaEventDisableTiming);
        cudaEventCreateWithFlags(&eJoin, cudaEventDisableTiming);
        init_done = true;
    }

    __half* fthp;   cudaGetSymbolAddress((void**)&fthp, g_featTh);
    float4* ptsp;   cudaGetSymbolAddress((void**)&ptsp, g_pts);
    int*    cntp;   cudaGetSymbolAddress((void**)&cntp, g_cellCount);
    int*    stp;    cudaGetSymbolAddress((void**)&stp,  g_cellStart);

    // Fork: transpose (depends only on features) on s2, parallel to binning.
    cudaEventRecord(eFork, 0);
    cudaStreamWaitEvent(s2, eFork, 0);
    {
        dim3 blk(256, 1, 1);
        dim3 grd(Nn / 64, Cn / 32, Bn);
        transpose_kernel<<<grd, blk, 0, s2>>>(features, fthp);
    }
    cudaEventRecord(eJoin, s2);

    // Main stream: single-kernel binning
    bin_all_kernel<<<Bn, 1024>>>(xyz, ptsp, stp, cntp);

    // Join, then fused persistent ball-query + MLP + max
    cudaStreamWaitEvent(0, eJoin, 0);
    fused_kernel<<<NCTA, 256, SMEM_BYTES>>>(xyz, ptsp, stp, cntp,
                                            W1, b1, W2, b2, out);
}

// round 14
// speedup vs baseline: 2.9900x; 1.0658x over previous
#include <cuda_runtime.h>
#include <cuda_fp16.h>
#include <cstdint>

// Problem constants (fixed shapes per reference setup_inputs)
#define Bn      8
#define Nn      8192
#define Cn      64
#define NP      2048
#define NS      32
#define CIN     67
#define H1n     64
#define H2n     128
#define RADIUS2 0.01f

#define GRID    8
#define NCELL   (GRID * GRID * GRID)     // 512 per batch
#define CAND_MAX 288
#define NCTA    296                      // persistent: 2 CTAs x 148 SMs

// Scratch (allocation-free rule: __device__ globals)
__device__ __half g_featTh[(size_t)Bn * Nn * Cn];      // 8 MB, (B,N,C) fp16
__device__ float4 g_pts[Bn * Nn];                      // 1 MB cell-sorted pts
__device__ int    g_cellCount[Bn * NCELL];
__device__ int    g_cellStart[Bn * NCELL];

typedef unsigned long long ull;

// ---------------------------------------------------------------------------
// fp16 mma / ldmatrix helpers
// ---------------------------------------------------------------------------
__device__ __forceinline__ void mma_f16(float c[4], const unsigned a[4],
                                        unsigned b0, unsigned b1)
{
    asm volatile(
        "mma.sync.aligned.m16n8k16.row.col.f32.f16.f16.f32 "
        "{%0,%1,%2,%3}, {%4,%5,%6,%7}, {%8,%9}, {%0,%1,%2,%3};"
        : "+f"(c[0]), "+f"(c[1]), "+f"(c[2]), "+f"(c[3])
        : "r"(a[0]), "r"(a[1]), "r"(a[2]), "r"(a[3]), "r"(b0), "r"(b1));
}

__device__ __forceinline__ void ldsm4(unsigned* r, unsigned addr)
{
    asm volatile("ldmatrix.sync.aligned.m8n8.x4.shared.b16 {%0,%1,%2,%3}, [%4];"
                 : "=r"(r[0]), "=r"(r[1]), "=r"(r[2]), "=r"(r[3]) : "r"(addr));
}

__device__ __forceinline__ unsigned h2pack(float lo, float hi)
{
    __half2 h = __floats2half2_rn(lo, hi);
    return *(unsigned*)&h;
}

__device__ __forceinline__ int cell_of(float x, float y, float z)
{
    int cx = min(GRID - 1, max(0, (int)(x * (float)GRID)));
    int cy = min(GRID - 1, max(0, (int)(y * (float)GRID)));
    int cz = min(GRID - 1, max(0, (int)(z * (float)GRID)));
    return cx + GRID * (cy + GRID * cz);
}

// ---------------------------------------------------------------------------
// Single-kernel binning: one 1024-thread CTA per batch.
// ---------------------------------------------------------------------------
__global__ __launch_bounds__(1024) void bin_all_kernel(
    const float* __restrict__ xyz,
    float4* __restrict__ pts,
    int* __restrict__ cellStart, int* __restrict__ cellCount)
{
    __shared__ int sc[NCELL];
    __shared__ int scur[NCELL];

    const int b = blockIdx.x;
    const int t = threadIdx.x;          // 0..1023, 8 points per thread

    if (t < NCELL) sc[t] = 0;
    __syncthreads();

    const float* xb = xyz + (size_t)b * Nn * 3;
    float px[8], py[8], pz[8];
    int   pc[8];

    #pragma unroll
    for (int j = 0; j < 8; j++) {
        int i = t + j * 1024;
        px[j] = xb[i * 3 + 0];
        py[j] = xb[i * 3 + 1];
        pz[j] = xb[i * 3 + 2];
        pc[j] = cell_of(px[j], py[j], pz[j]);
        atomicAdd(&sc[pc[j]], 1);
    }
    __syncthreads();

    int c0 = (t < NCELL) ? sc[t] : 0;
    for (int off = 1; off < NCELL; off <<= 1) {
        int v = 0;
        if (t < NCELL && t >= off) v = sc[t - off];
        __syncthreads();
        if (t < NCELL) sc[t] += v;
        __syncthreads();
    }
    if (t < NCELL) {
        int excl = sc[t] - c0;
        cellStart[b * NCELL + t] = excl;
        cellCount[b * NCELL + t] = c0;
        scur[t] = excl;
    }
    __syncthreads();

    float4* pout = pts + (size_t)b * Nn;
    #pragma unroll
    for (int j = 0; j < 8; j++) {
        int i = t + j * 1024;
        int pos = atomicAdd(&scur[pc[j]], 1);
        pout[pos] = make_float4(px[j], py[j], pz[j], __int_as_float(i));
    }
}

// ---------------------------------------------------------------------------
// Transpose features (B,C,N) f32 -> (B,N,C) fp16, vectorized.
// ---------------------------------------------------------------------------
__global__ __launch_bounds__(256) void transpose_kernel(
    const float* __restrict__ f, __half* __restrict__ ft)
{
    __shared__ float tile[64][33];
    const int b  = blockIdx.z;
    const int c0 = blockIdx.y * 32;
    const int n0 = blockIdx.x * 64;
    const int t  = threadIdx.x;

    const float* fb = f + (size_t)b * Cn * Nn;

    #pragma unroll
    for (int j = 0; j < 2; j++) {
        int idx = t + j * 256;
        int c   = idx >> 4;
        int n4  = (idx & 15) * 4;
        float4 v = __ldg((const float4*)&fb[(size_t)(c0 + c) * Nn + n0 + n4]);
        tile[n4 + 0][c] = v.x;
        tile[n4 + 1][c] = v.y;
        tile[n4 + 2][c] = v.z;
        tile[n4 + 3][c] = v.w;
    }
    __syncthreads();

    __half* fo = ft + (size_t)b * Nn * Cn;
    #pragma unroll
    for (int j = 0; j < 2; j++) {
        int idx = t + j * 256;
        int n   = idx >> 3;
        int c4  = (idx & 7) * 4;
        unsigned lo = h2pack(tile[n][c4 + 0], tile[n][c4 + 1]);
        unsigned hi = h2pack(tile[n][c4 + 2], tile[n][c4 + 3]);
        ull pk = (ull)lo | ((ull)hi << 32);
        *(ull*)&fo[(size_t)(n0 + n) * Cn + c0 + c4] = pk;
    }
}

// ---------------------------------------------------------------------------
// FUSED persistent kernel: grid ball query + group + MLP + max.
// R14: flat-position candidate enumeration — warp-scan cell counts, map flat
// index -> (cell, addr) via register binary search, batch-issue 8 independent
// LDG.128 per iteration (pipelines the former 27-deep serial L2 chain).
// ---------------------------------------------------------------------------
#define A_STR   88
#define W1_STR  88
#define W2_STR  72
#define A_OFF   0
#define W1_OFF  (256 * A_STR)               // 22528 halfs
#define W2_OFF  (W1_OFF + 64 * W1_STR)      // 28160
#define HALF_END (W2_OFF + 128 * W2_STR)    // 37376 halfs = 74752 B
#define BIAS_BYTES ((64 + 128) * 4)
#define CBUF_OFF_B (HALF_END * 2 + BIAS_BYTES)
#define SMEM_BYTES (CBUF_OFF_B + 8 * CAND_MAX * 4)

__global__ __launch_bounds__(256, 2) void fused_kernel(
    const float*  __restrict__ xyz,
    const float4* __restrict__ pts,
    const int*    __restrict__ cellStart,
    const int*    __restrict__ cellCount,
    const float*  __restrict__ W1,
    const float*  __restrict__ b1,
    const float*  __restrict__ W2,
    const float*  __restrict__ b2,
    float* __restrict__ out)
{
    extern __shared__ __half smh[];
    __half* Ah  = smh + A_OFF;
    __half* w1s = smh + W1_OFF;
    __half* w2s = smh + W2_OFF;
    float* b1s = (float*)(smh + HALF_END);
    float* b2s = b1s + 64;
    int*   cbuf = (int*)((char*)smh + CBUF_OFF_B);

    const unsigned smb = (unsigned)__cvta_generic_to_shared(smh);

    const int tid  = threadIdx.x;
    const int lane = tid & 31;
    const int q    = tid >> 5;
    const int kk   = lane & 3;
    const int r    = lane >> 2;

    // ---- stage weights ONCE (fp16; W1 cols permuted: feat 0..63, rel 64..66) ----
    for (int i = tid; i < 64 * W1_STR; i += 256) {
        int o = i / W1_STR, k = i - o * W1_STR;
        float w = 0.0f;
        if (k < CIN) {
            int src = (k < 64) ? (k + 3) : (k - 64);
            w = __ldg(&W1[o * CIN + src]);
        }
        w1s[i] = __float2half_rn(w);
    }
    for (int i = tid; i < 128 * W2_STR; i += 256) {
        int o = i / W2_STR, k = i - o * W2_STR;
        w2s[i] = __float2half_rn((k < H1n) ? __ldg(&W2[o * H1n + k]) : 0.0f);
    }
    if (tid < 64)  b1s[tid] = b1[tid];
    if (tid >= 128 && tid < 256) b2s[tid - 128] = b2[tid - 128];

    // zero-pad A cols 67..87 once
    {
        __half* arow = Ah + tid * A_STR;
        #pragma unroll
        for (int k = 67; k < A_STR; k++) arow[k] = __ushort_as_half(0);
    }
    __syncthreads();

    // ldmatrix lane addressing
    const int rowbase = q * 32;
    const int rr = lane & 15;
    const int ch = (lane >> 4) * 8;
    const unsigned aBase0 = smb + (unsigned)(((rowbase + rr) * A_STR + ch) * 2);
    const unsigned aBase1 = aBase0 + 16 * A_STR * 2;
    const unsigned w1Base = smb + (unsigned)((W1_OFF + rr * W1_STR + ch) * 2);
    const unsigned w2Base = smb + (unsigned)((W2_OFF + rr * W2_STR + ch) * 2);

    int* buf = cbuf + q * CAND_MAX;
    const int totwarps = NCTA * 8;
    const int gwarp = blockIdx.x * 8 + q;

    for (int gq = gwarp; gq < Bn * NP; gq += totwarps) {
        const int b = gq >> 11;              // NP = 2048
        const int s = gq & (NP - 1);

        // ================== per-warp grid ball query ==================
        const float qx = __ldg(&xyz[((size_t)b * Nn + s) * 3 + 0]);
        const float qy = __ldg(&xyz[((size_t)b * Nn + s) * 3 + 1]);
        const float qz = __ldg(&xyz[((size_t)b * Nn + s) * 3 + 2]);

        if (lane < 3) {
            float v = (lane == 0) ? qx : (lane == 1) ? qy : qz;
            out[(size_t)gq * 3 + lane] = v;
        }

        const int cx = min(GRID - 1, max(0, (int)(qx * (float)GRID)));
        const int cy = min(GRID - 1, max(0, (int)(qy * (float)GRID)));
        const int cz = min(GRID - 1, max(0, (int)(qz * (float)GRID)));

        const int x0 = max(cx - 1, 0), x1 = min(cx + 1, GRID - 1);
        const int y0 = max(cy - 1, 0), y1 = min(cy + 1, GRID - 1);
        const int z0 = max(cz - 1, 0), z1 = min(cz + 1, GRID - 1);
        const int nx = x1 - x0 + 1, ny = y1 - y0 + 1, nz = z1 - z0 + 1;
        const int ncells = nx * ny * nz;     // <= 27

        // lane-parallel descriptor prefetch
        int stL = 0, cntL = 0;
        if (lane < ncells) {
            int lx = lane % nx;
            int rem = lane / nx;
            int ly = rem % ny;
            int lz = rem / ny;
            int c = b * NCELL + (x0 + lx) + GRID * ((y0 + ly) + GRID * (z0 + lz));
            stL  = __ldg(&cellStart[c]);
            cntL = __ldg(&cellCount[c]);
        }

        // warp exclusive scan of counts -> flat candidate range [0, T)
        int inc = cntL;
        #pragma unroll
        for (int d = 1; d < 32; d <<= 1) {
            int t2 = __shfl_up_sync(0xffffffffu, inc, d);
            if (lane >= d) inc += t2;
        }
        const int off = inc - cntL;                       // exclusive prefix
        const int T = __shfl_sync(0xffffffffu, inc, 31);  // total candidates

        int K = 0;
        const float4* pb = pts + (size_t)b * Nn;
        const int W = (T + 31) >> 5;                      // 32-wide waves

        for (int w0 = 0; w0 < W; w0 += 8) {
            float4 p[8];
            bool   act[8];
            // batch-issue 8 independent loads (flat pos -> cell via shfl bsearch)
            #pragma unroll
            for (int j = 0; j < 8; j++) {
                int f = (w0 + j) * 32 + lane;
                act[j] = (w0 + j < W) && (f < T);
                int lo = 0, hi = ncells - 1;
                #pragma unroll
                for (int it = 0; it < 5; it++) {
                    int mid = (lo + hi + 1) >> 1;
                    int om = __shfl_sync(0xffffffffu, off, mid);
                    bool go = (om <= f) && (mid <= hi);
                    lo = go ? mid : lo;
                    hi = go ? hi : mid - 1;
                }
                int stc  = __shfl_sync(0xffffffffu, stL, lo);
                int offc = __shfl_sync(0xffffffffu, off, lo);
                if (act[j]) p[j] = __ldg(&pb[stc + (f - offc)]);
                else        p[j] = make_float4(1e9f, 1e9f, 1e9f, 0.0f);
            }
            // process batch
            #pragma unroll
            for (int j = 0; j < 8; j++) {
                float dx = p[j].x - qx, dy = p[j].y - qy, dz = p[j].z - qz;
                float d2 = dx * dx + dy * dy + dz * dz;
                bool in = act[j] && (d2 < RADIUS2);
                unsigned m = __ballot_sync(0xffffffffu, in);
                int pos = K + __popc(m & ((1u << lane) - 1u));
                if (in && pos < CAND_MAX) buf[pos] = __float_as_int(p[j].w);
                K += __popc(m);
            }
        }
        __syncwarp();

        int myid;
        if (K <= NS) {
            myid = buf[(lane < K) ? lane : 0];
        } else if (K <= CAND_MAX) {
            // drop-max selection: remove the K-NS largest (expected ~2-8)
            int loc[(CAND_MAX + 31) / 32];
            #pragma unroll
            for (int j = 0; j < (CAND_MAX + 31) / 32; j++) {
                int p = lane + 32 * j;
                loc[j] = (p < K) ? buf[p] : -1;
            }
            int lmax = -1;
            #pragma unroll
            for (int j = 0; j < (CAND_MAX + 31) / 32; j++) lmax = max(lmax, loc[j]);

            const int excess = K - NS;
            for (int e = 0; e < excess; e++) {
                int m = lmax;
                m = max(m, __shfl_xor_sync(0xffffffffu, m, 16));
                m = max(m, __shfl_xor_sync(0xffffffffu, m, 8));
                m = max(m, __shfl_xor_sync(0xffffffffu, m, 4));
                m = max(m, __shfl_xor_sync(0xffffffffu, m, 2));
                m = max(m, __shfl_xor_sync(0xffffffffu, m, 1));
                unsigned own = __ballot_sync(0xffffffffu, lmax == m);
                if (lane == (__ffs(own) - 1)) {
                    #pragma unroll
                    for (int j = 0; j < (CAND_MAX + 31) / 32; j++)
                        if (loc[j] == m) loc[j] = -1;      // indices distinct
                    lmax = -1;
                    #pragma unroll
                    for (int j = 0; j < (CAND_MAX + 31) / 32; j++)
                        lmax = max(lmax, loc[j]);
                }
            }
            // compact exactly 32 survivors into buf
            int pos = 0;
            #pragma unroll
            for (int j = 0; j < (CAND_MAX + 31) / 32; j++) {
                bool alive = loc[j] >= 0;
                unsigned mm = __ballot_sync(0xffffffffu, alive);
                if (alive) buf[pos + __popc(mm & ((1u << lane) - 1u))] = loc[j];
                pos += __popc(mm);
            }
            __syncwarp();
            myid = buf[lane];
        } else {
            // exact fallback: ordered linear scan into buf
            int cnt = 0, first_idx = 0;
            const float* xb = xyz + (size_t)b * Nn * 3;
            for (int base = 0; base < Nn; base += 32) {
                int i = base + lane;
                float dx = __ldg(&xb[i * 3 + 0]) - qx;
                float dy = __ldg(&xb[i * 3 + 1]) - qy;
                float dz = __ldg(&xb[i * 3 + 2]) - qz;
                float d2 = dx * dx + dy * dy + dz * dz;
                unsigned bits = __ballot_sync(0xffffffffu, d2 < RADIUS2);
                if (bits) {
                    if (cnt == 0) first_idx = base + __ffs(bits) - 1;
                    if ((bits >> lane) & 1u) {
                        int pos = cnt + __popc(bits & ((1u << lane) - 1u));
                        if (pos < NS) buf[pos] = i;
                    }
                    cnt += __popc(bits);
                    if (cnt >= NS) break;
                }
            }
            if (cnt < NS) {
                int slot = cnt + lane;
                if (slot < NS) buf[slot] = first_idx;
            }
            __syncwarp();
            myid = buf[lane];
        }

        // ================== stage A row (this thread's row = tid) ==================
        {
            const float* xb = xyz + (size_t)b * Nn * 3;
            __half* arow = Ah + tid * A_STR;
            const ull* src = (const ull*)(g_featTh + ((size_t)b * Nn + myid) * Cn);
            ull* dst = (ull*)arow;
            #pragma unroll
            for (int j = 0; j < 16; j++) dst[j] = __ldg(&src[j]);
            arow[64] = __float2half_rn(__ldg(&xb[myid * 3 + 0]) - qx);
            arow[65] = __float2half_rn(__ldg(&xb[myid * 3 + 1]) - qy);
            arow[66] = __float2half_rn(__ldg(&xb[myid * 3 + 2]) - qz);
        }
        __syncwarp();

        // ================== Layer 1 (K=80 -> 5 k-groups) ==================
        float c1[2][8][4];
        #pragma unroll
        for (int nt = 0; nt < 8; nt++) {
            float blo = b1s[nt * 8 + 2 * kk];
            float bhi = b1s[nt * 8 + 2 * kk + 1];
            #pragma unroll
            for (int mt = 0; mt < 2; mt++) {
                c1[mt][nt][0] = blo; c1[mt][nt][1] = bhi;
                c1[mt][nt][2] = blo; c1[mt][nt][3] = bhi;
            }
        }

        #pragma unroll
        for (int kg = 0; kg < 5; kg++) {
            unsigned a0[4], a1[4];
            ldsm4(a0, aBase0 + kg * 32);
            ldsm4(a1, aBase1 + kg * 32);
            #pragma unroll
            for (int p = 0; p < 4; p++) {
                unsigned bf[4];
                ldsm4(bf, w1Base + (unsigned)(16 * p * W1_STR * 2) + kg * 32);
                mma_f16(c1[0][2 * p],     a0, bf[0], bf[2]);
                mma_f16(c1[0][2 * p + 1], a0, bf[1], bf[3]);
                mma_f16(c1[1][2 * p],     a1, bf[0], bf[2]);
                mma_f16(c1[1][2 * p + 1], a1, bf[1], bf[3]);
            }
        }
        __syncwarp();

        // store relu(h1) fp16 into warp-local A rows (cols 0..63)
        #pragma unroll
        for (int mt = 0; mt < 2; mt++)
            #pragma unroll
            for (int nt = 0; nt < 8; nt++)
                #pragma unroll
                for (int i = 0; i < 2; i++) {
                    int row = rowbase + mt * 16 + r + 8 * i;
                    unsigned pk = h2pack(fmaxf(c1[mt][nt][2 * i + 0], 0.0f),
                                         fmaxf(c1[mt][nt][2 * i + 1], 0.0f));
                    *(unsigned*)&Ah[row * A_STR + nt * 8 + 2 * kk] = pk;
                }
        __syncwarp();

        // hoist L2 A fragments (K=64 -> 4 k-groups)
        unsigned afrag[4][8];
        #pragma unroll
        for (int kg = 0; kg < 4; kg++) {
            ldsm4(&afrag[kg][0], aBase0 + kg * 32);
            ldsm4(&afrag[kg][4], aBase1 + kg * 32);
        }

        float* op_base = out + (Bn * NP * 3) + (size_t)b * H2n * NP + s;

        #pragma unroll
        for (int h = 0; h < 2; h++) {
            float c2[2][8][4];
            #pragma unroll
            for (int nt = 0; nt < 8; nt++) {
                int o = h * 64 + nt * 8;
                float blo = b2s[o + 2 * kk];
                float bhi = b2s[o + 2 * kk + 1];
                #pragma unroll
                for (int mt = 0; mt < 2; mt++) {
                    c2[mt][nt][0] = blo; c2[mt][nt][1] = bhi;
                    c2[mt][nt][2] = blo; c2[mt][nt][3] = bhi;
                }
            }

            #pragma unroll
            for (int kg = 0; kg < 4; kg++) {
                #pragma unroll
                for (int p = 0; p < 4; p++) {
                    unsigned bf[4];
                    ldsm4(bf, w2Base + (unsigned)(16 * (h * 4 + p) * W2_STR * 2) + kg * 32);
                    mma_f16(c2[0][2 * p],     &afrag[kg][0], bf[0], bf[2]);
                    mma_f16(c2[0][2 * p + 1], &afrag[kg][0], bf[1], bf[3]);
                    mma_f16(c2[1][2 * p],     &afrag[kg][4], bf[0], bf[2]);
                    mma_f16(c2[1][2 * p + 1], &afrag[kg][4], bf[1], bf[3]);
                }
            }

            #pragma unroll
            for (int nt = 0; nt < 8; nt++)
                #pragma unroll
                for (int j = 0; j < 2; j++) {
                    float v = fmaxf(fmaxf(c2[0][nt][j], c2[0][nt][j + 2]),
                                    fmaxf(c2[1][nt][j], c2[1][nt][j + 2]));
                    v = fmaxf(v, __shfl_xor_sync(0xffffffffu, v, 4));
                    v = fmaxf(v, __shfl_xor_sync(0xffffffffu, v, 8));
                    v = fmaxf(v, __shfl_xor_sync(0xffffffffu, v, 16));
                    if (r == 0) {
                        int col = h * 64 + nt * 8 + 2 * kk + j;
                        op_base[(size_t)col * NP] = fmaxf(v, 0.0f);
                    }
                }
        }
        __syncwarp();   // h1/A reads done before next iteration restages
    }
}

// ---------------------------------------------------------------------------
extern "C" void kernel_launch(void* const* d_in, const int* in_sizes, int n_in,
                              void* d_out, int out_size)
{
    const float* xyz      = (const float*)d_in[0];
    const float* features = (const float*)d_in[1];
    const float* W1       = (const float*)d_in[2];
    const float* b1       = (const float*)d_in[3];
    const float* W2       = (const float*)d_in[4];
    const float* b2       = (const float*)d_in[5];
    float* out = (float*)d_out;

    static bool init_done = false;
    static cudaStream_t s2;
    static cudaEvent_t eFork, eJoin;
    if (!init_done) {
        cudaFuncSetAttribute(fused_kernel, cudaFuncAttributeMaxDynamicSharedMemorySize,
                             SMEM_BYTES);
        cudaStreamCreateWithFlags(&s2, cudaStreamNonBlocking);
        cudaEventCreateWithFlags(&eFork, cudaEventDisableTiming);
        cudaEventCreateWithFlags(&eJoin, cudaEventDisableTiming);
        init_done = true;
    }

    __half* fthp;   cudaGetSymbolAddress((void**)&fthp, g_featTh);
    float4* ptsp;   cudaGetSymbolAddress((void**)&ptsp, g_pts);
    int*    cntp;   cudaGetSymbolAddress((void**)&cntp, g_cellCount);
    int*    stp;    cudaGetSymbolAddress((void**)&stp,  g_cellStart);

    // Fork: transpose (depends only on features) on s2, parallel to binning.
    cudaEventRecord(eFork, 0);
    cudaStreamWaitEvent(s2, eFork, 0);
    {
        dim3 blk(256, 1, 1);
        dim3 grd(Nn / 64, Cn / 32, Bn);
        transpose_kernel<<<grd, blk, 0, s2>>>(features, fthp);
    }
    cudaEventRecord(eJoin, s2);

    // Main stream: single-kernel binning
    bin_all_kernel<<<Bn, 1024>>>(xyz, ptsp, stp, cntp);

    // Join, then fused persistent ball-query + MLP + max
    cudaStreamWaitEvent(0, eJoin, 0);
    fused_kernel<<<NCTA, 256, SMEM_BYTES>>>(xyz, ptsp, stp, cntp,
                                            W1, b1, W2, b2, out);
}

// round 15
// speedup vs baseline: 3.2538x; 1.0882x over previous
#include <cuda_runtime.h>
#include <cuda_fp16.h>
#include <cstdint>

// Problem constants (fixed shapes per reference setup_inputs)
#define Bn      8
#define Nn      8192
#define Cn      64
#define NP      2048
#define NS      32
#define CIN     67
#define H1n     64
#define H2n     128
#define RADIUS2 0.01f

#define GRID    8
#define NCELL   (GRID * GRID * GRID)     // 512 per batch
#define CAND_MAX 288
#define NCTA    296                      // persistent: 2 CTAs x 148 SMs

// Scratch (allocation-free rule: __device__ globals)
__device__ __half g_featTh[(size_t)Bn * Nn * Cn];      // 8 MB, (B,N,C) fp16
__device__ float4 g_pts[Bn * Nn];                      // 1 MB cell-sorted pts
__device__ int    g_cellCount[Bn * NCELL];
__device__ int    g_cellStart[Bn * NCELL];

typedef unsigned long long ull;

// ---------------------------------------------------------------------------
// fp16 mma / ldmatrix helpers
// ---------------------------------------------------------------------------
__device__ __forceinline__ void mma_f16(float c[4], const unsigned a[4],
                                        unsigned b0, unsigned b1)
{
    asm volatile(
        "mma.sync.aligned.m16n8k16.row.col.f32.f16.f16.f32 "
        "{%0,%1,%2,%3}, {%4,%5,%6,%7}, {%8,%9}, {%0,%1,%2,%3};"
        : "+f"(c[0]), "+f"(c[1]), "+f"(c[2]), "+f"(c[3])
        : "r"(a[0]), "r"(a[1]), "r"(a[2]), "r"(a[3]), "r"(b0), "r"(b1));
}

__device__ __forceinline__ void ldsm4(unsigned* r, unsigned addr)
{
    asm volatile("ldmatrix.sync.aligned.m8n8.x4.shared.b16 {%0,%1,%2,%3}, [%4];"
                 : "=r"(r[0]), "=r"(r[1]), "=r"(r[2]), "=r"(r[3]) : "r"(addr));
}

__device__ __forceinline__ unsigned h2pack(float lo, float hi)
{
    __half2 h = __floats2half2_rn(lo, hi);
    return *(unsigned*)&h;
}

__device__ __forceinline__ int cell_of(float x, float y, float z)
{
    int cx = min(GRID - 1, max(0, (int)(x * (float)GRID)));
    int cy = min(GRID - 1, max(0, (int)(y * (float)GRID)));
    int cz = min(GRID - 1, max(0, (int)(z * (float)GRID)));
    return cx + GRID * (cy + GRID * cz);
}

// ---------------------------------------------------------------------------
// Single-kernel binning: one 1024-thread CTA per batch.
// ---------------------------------------------------------------------------
__global__ __launch_bounds__(1024) void bin_all_kernel(
    const float* __restrict__ xyz,
    float4* __restrict__ pts,
    int* __restrict__ cellStart, int* __restrict__ cellCount)
{
    __shared__ int sc[NCELL];
    __shared__ int scur[NCELL];

    const int b = blockIdx.x;
    const int t = threadIdx.x;          // 0..1023, 8 points per thread

    if (t < NCELL) sc[t] = 0;
    __syncthreads();

    const float* xb = xyz + (size_t)b * Nn * 3;
    float px[8], py[8], pz[8];
    int   pc[8];

    #pragma unroll
    for (int j = 0; j < 8; j++) {
        int i = t + j * 1024;
        px[j] = xb[i * 3 + 0];
        py[j] = xb[i * 3 + 1];
        pz[j] = xb[i * 3 + 2];
        pc[j] = cell_of(px[j], py[j], pz[j]);
        atomicAdd(&sc[pc[j]], 1);
    }
    __syncthreads();

    int c0 = (t < NCELL) ? sc[t] : 0;
    for (int off = 1; off < NCELL; off <<= 1) {
        int v = 0;
        if (t < NCELL && t >= off) v = sc[t - off];
        __syncthreads();
        if (t < NCELL) sc[t] += v;
        __syncthreads();
    }
    if (t < NCELL) {
        int excl = sc[t] - c0;
        cellStart[b * NCELL + t] = excl;
        cellCount[b * NCELL + t] = c0;
        scur[t] = excl;
    }
    __syncthreads();

    float4* pout = pts + (size_t)b * Nn;
    #pragma unroll
    for (int j = 0; j < 8; j++) {
        int i = t + j * 1024;
        int pos = atomicAdd(&scur[pc[j]], 1);
        pout[pos] = make_float4(px[j], py[j], pz[j], __int_as_float(i));
    }
}

// ---------------------------------------------------------------------------
// Transpose features (B,C,N) f32 -> (B,N,C) fp16, vectorized.
// ---------------------------------------------------------------------------
__global__ __launch_bounds__(256) void transpose_kernel(
    const float* __restrict__ f, __half* __restrict__ ft)
{
    __shared__ float tile[64][33];
    const int b  = blockIdx.z;
    const int c0 = blockIdx.y * 32;
    const int n0 = blockIdx.x * 64;
    const int t  = threadIdx.x;

    const float* fb = f + (size_t)b * Cn * Nn;

    #pragma unroll
    for (int j = 0; j < 2; j++) {
        int idx = t + j * 256;
        int c   = idx >> 4;
        int n4  = (idx & 15) * 4;
        float4 v = __ldg((const float4*)&fb[(size_t)(c0 + c) * Nn + n0 + n4]);
        tile[n4 + 0][c] = v.x;
        tile[n4 + 1][c] = v.y;
        tile[n4 + 2][c] = v.z;
        tile[n4 + 3][c] = v.w;
    }
    __syncthreads();

    __half* fo = ft + (size_t)b * Nn * Cn;
    #pragma unroll
    for (int j = 0; j < 2; j++) {
        int idx = t + j * 256;
        int n   = idx >> 3;
        int c4  = (idx & 7) * 4;
        unsigned lo = h2pack(tile[n][c4 + 0], tile[n][c4 + 1]);
        unsigned hi = h2pack(tile[n][c4 + 2], tile[n][c4 + 3]);
        ull pk = (ull)lo | ((ull)hi << 32);
        *(ull*)&fo[(size_t)(n0 + n) * Cn + c0 + c4] = pk;
    }
}

// ---------------------------------------------------------------------------
// FUSED persistent kernel: grid ball query + group + MLP + max.
// R15: cross-iteration software pipeline — next query's point load is issued
// after selection, next query's descriptor gather after layer-1 MMAs, so both
// L2 round trips drain under tensor work. Staging uses LDG.128.
// ---------------------------------------------------------------------------
#define A_STR   88
#define W1_STR  88
#define W2_STR  72
#define A_OFF   0
#define W1_OFF  (256 * A_STR)               // 22528 halfs
#define W2_OFF  (W1_OFF + 64 * W1_STR)      // 28160
#define HALF_END (W2_OFF + 128 * W2_STR)    // 37376 halfs = 74752 B
#define BIAS_BYTES ((64 + 128) * 4)
#define CBUF_OFF_B (HALF_END * 2 + BIAS_BYTES)
#define SMEM_BYTES (CBUF_OFF_B + 8 * CAND_MAX * 4)

__global__ __launch_bounds__(256, 2) void fused_kernel(
    const float*  __restrict__ xyz,
    const float4* __restrict__ pts,
    const int*    __restrict__ cellStart,
    const int*    __restrict__ cellCount,
    const float*  __restrict__ W1,
    const float*  __restrict__ b1,
    const float*  __restrict__ W2,
    const float*  __restrict__ b2,
    float* __restrict__ out)
{
    extern __shared__ __half smh[];
    __half* Ah  = smh + A_OFF;
    __half* w1s = smh + W1_OFF;
    __half* w2s = smh + W2_OFF;
    float* b1s = (float*)(smh + HALF_END);
    float* b2s = b1s + 64;
    int*   cbuf = (int*)((char*)smh + CBUF_OFF_B);

    const unsigned smb = (unsigned)__cvta_generic_to_shared(smh);

    const int tid  = threadIdx.x;
    const int lane = tid & 31;
    const int q    = tid >> 5;
    const int kk   = lane & 3;
    const int r    = lane >> 2;

    // ---- stage weights ONCE (fp16; W1 cols permuted: feat 0..63, rel 64..66) ----
    for (int i = tid; i < 64 * W1_STR; i += 256) {
        int o = i / W1_STR, k = i - o * W1_STR;
        float w = 0.0f;
        if (k < CIN) {
            int src = (k < 64) ? (k + 3) : (k - 64);
            w = __ldg(&W1[o * CIN + src]);
        }
        w1s[i] = __float2half_rn(w);
    }
    for (int i = tid; i < 128 * W2_STR; i += 256) {
        int o = i / W2_STR, k = i - o * W2_STR;
        w2s[i] = __float2half_rn((k < H1n) ? __ldg(&W2[o * H1n + k]) : 0.0f);
    }
    if (tid < 64)  b1s[tid] = b1[tid];
    if (tid >= 128 && tid < 256) b2s[tid - 128] = b2[tid - 128];

    // zero-pad A cols 67..87 once
    {
        __half* arow = Ah + tid * A_STR;
        #pragma unroll
        for (int k = 67; k < A_STR; k++) arow[k] = __ushort_as_half(0);
    }
    __syncthreads();

    // ldmatrix lane addressing
    const int rowbase = q * 32;
    const int rr = lane & 15;
    const int ch = (lane >> 4) * 8;
    const unsigned aBase0 = smb + (unsigned)(((rowbase + rr) * A_STR + ch) * 2);
    const unsigned aBase1 = aBase0 + 16 * A_STR * 2;
    const unsigned w1Base = smb + (unsigned)((W1_OFF + rr * W1_STR + ch) * 2);
    const unsigned w2Base = smb + (unsigned)((W2_OFF + rr * W2_STR + ch) * 2);

    int* buf = cbuf + q * CAND_MAX;
    const int totwarps = NCTA * 8;
    const int gwarp = blockIdx.x * 8 + q;
    const int NQ = Bn * NP;

    // ---- pipeline prologue: load query 0's point + descriptors ----
    float qx = 0.f, qy = 0.f, qz = 0.f;
    int stL = 0, cntL = 0, ncells = 0;
    if (gwarp < NQ) {
        const int b0 = gwarp >> 11, s0 = gwarp & (NP - 1);
        qx = __ldg(&xyz[((size_t)b0 * Nn + s0) * 3 + 0]);
        qy = __ldg(&xyz[((size_t)b0 * Nn + s0) * 3 + 1]);
        qz = __ldg(&xyz[((size_t)b0 * Nn + s0) * 3 + 2]);
        const int cx = min(GRID - 1, max(0, (int)(qx * (float)GRID)));
        const int cy = min(GRID - 1, max(0, (int)(qy * (float)GRID)));
        const int cz = min(GRID - 1, max(0, (int)(qz * (float)GRID)));
        const int x0 = max(cx - 1, 0), x1 = min(cx + 1, GRID - 1);
        const int y0 = max(cy - 1, 0), y1 = min(cy + 1, GRID - 1);
        const int z0 = max(cz - 1, 0), z1 = min(cz + 1, GRID - 1);
        const int nx = x1 - x0 + 1, ny = y1 - y0 + 1, nz = z1 - z0 + 1;
        ncells = nx * ny * nz;
        if (lane < ncells) {
            int lx = lane % nx, rem = lane / nx;
            int ly = rem % ny, lz = rem / ny;
            int c = b0 * NCELL + (x0 + lx) + GRID * ((y0 + ly) + GRID * (z0 + lz));
            stL  = __ldg(&cellStart[c]);
            cntL = __ldg(&cellCount[c]);
        }
    }

    for (int gq = gwarp; gq < NQ; gq += totwarps) {
        const int b = gq >> 11;              // NP = 2048
        const int s = gq & (NP - 1);

        if (lane < 3) {
            float v = (lane == 0) ? qx : (lane == 1) ? qy : qz;
            out[(size_t)gq * 3 + lane] = v;
        }

        // warp exclusive scan of counts -> flat candidate range [0, T)
        int inc = cntL;
        #pragma unroll
        for (int d = 1; d < 32; d <<= 1) {
            int t2 = __shfl_up_sync(0xffffffffu, inc, d);
            if (lane >= d) inc += t2;
        }
        const int off = inc - cntL;                       // exclusive prefix
        const int T = __shfl_sync(0xffffffffu, inc, 31);  // total candidates

        int K = 0;
        const float4* pb = pts + (size_t)b * Nn;
        const int W = (T + 31) >> 5;                      // 32-wide waves

        for (int w0 = 0; w0 < W; w0 += 8) {
            float4 p[8];
            bool   act[8];
            #pragma unroll
            for (int j = 0; j < 8; j++) {
                int f = (w0 + j) * 32 + lane;
                act[j] = (w0 + j < W) && (f < T);
                int lo = 0, hi = ncells - 1;
                #pragma unroll
                for (int it = 0; it < 5; it++) {
                    int mid = (lo + hi + 1) >> 1;
                    int om = __shfl_sync(0xffffffffu, off, mid);
                    bool go = (om <= f) && (mid <= hi);
                    lo = go ? mid : lo;
                    hi = go ? hi : mid - 1;
                }
                int stc  = __shfl_sync(0xffffffffu, stL, lo);
                int offc = __shfl_sync(0xffffffffu, off, lo);
                if (act[j]) p[j] = __ldg(&pb[stc + (f - offc)]);
                else        p[j] = make_float4(1e9f, 1e9f, 1e9f, 0.0f);
            }
            #pragma unroll
            for (int j = 0; j < 8; j++) {
                float dx = p[j].x - qx, dy = p[j].y - qy, dz = p[j].z - qz;
                float d2 = dx * dx + dy * dy + dz * dz;
                bool in = act[j] && (d2 < RADIUS2);
                unsigned m = __ballot_sync(0xffffffffu, in);
                int pos = K + __popc(m & ((1u << lane) - 1u));
                if (in && pos < CAND_MAX) buf[pos] = __float_as_int(p[j].w);
                K += __popc(m);
            }
        }
        __syncwarp();

        int myid;
        if (K <= NS) {
            myid = buf[(lane < K) ? lane : 0];
        } else if (K <= CAND_MAX) {
            // drop-max selection: remove the K-NS largest (expected ~2-8)
            int loc[(CAND_MAX + 31) / 32];
            #pragma unroll
            for (int j = 0; j < (CAND_MAX + 31) / 32; j++) {
                int p = lane + 32 * j;
                loc[j] = (p < K) ? buf[p] : -1;
            }
            int lmax = -1;
            #pragma unroll
            for (int j = 0; j < (CAND_MAX + 31) / 32; j++) lmax = max(lmax, loc[j]);

            const int excess = K - NS;
            for (int e = 0; e < excess; e++) {
                int m = lmax;
                m = max(m, __shfl_xor_sync(0xffffffffu, m, 16));
                m = max(m, __shfl_xor_sync(0xffffffffu, m, 8));
                m = max(m, __shfl_xor_sync(0xffffffffu, m, 4));
                m = max(m, __shfl_xor_sync(0xffffffffu, m, 2));
                m = max(m, __shfl_xor_sync(0xffffffffu, m, 1));
                unsigned own = __ballot_sync(0xffffffffu, lmax == m);
                if (lane == (__ffs(own) - 1)) {
                    #pragma unroll
                    for (int j = 0; j < (CAND_MAX + 31) / 32; j++)
                        if (loc[j] == m) loc[j] = -1;      // indices distinct
                    lmax = -1;
                    #pragma unroll
                    for (int j = 0; j < (CAND_MAX + 31) / 32; j++)
                        lmax = max(lmax, loc[j]);
                }
            }
            int pos = 0;
            #pragma unroll
            for (int j = 0; j < (CAND_MAX + 31) / 32; j++) {
                bool alive = loc[j] >= 0;
                unsigned mm = __ballot_sync(0xffffffffu, alive);
                if (alive) buf[pos + __popc(mm & ((1u << lane) - 1u))] = loc[j];
                pos += __popc(mm);
            }
            __syncwarp();
            myid = buf[lane];
        } else {
            // exact fallback: ordered linear scan into buf
            int cnt = 0, first_idx = 0;
            const float* xb = xyz + (size_t)b * Nn * 3;
            for (int base = 0; base < Nn; base += 32) {
                int i = base + lane;
                float dx = __ldg(&xb[i * 3 + 0]) - qx;
                float dy = __ldg(&xb[i * 3 + 1]) - qy;
                float dz = __ldg(&xb[i * 3 + 2]) - qz;
                float d2 = dx * dx + dy * dy + dz * dz;
                unsigned bits = __ballot_sync(0xffffffffu, d2 < RADIUS2);
                if (bits) {
                    if (cnt == 0) first_idx = base + __ffs(bits) - 1;
                    if ((bits >> lane) & 1u) {
                        int pos = cnt + __popc(bits & ((1u << lane) - 1u));
                        if (pos < NS) buf[pos] = i;
                    }
                    cnt += __popc(bits);
                    if (cnt >= NS) break;
                }
            }
            if (cnt < NS) {
                int slot = cnt + lane;
                if (slot < NS) buf[slot] = first_idx;
            }
            __syncwarp();
            myid = buf[lane];
        }

        // ---- pipeline: issue NEXT query's point load (independent of MLP) ----
        const int gqn = gq + totwarps;
        float qxn = 0.f, qyn = 0.f, qzn = 0.f;
        if (gqn < NQ) {
            const int bn = gqn >> 11, sn = gqn & (NP - 1);
            qxn = __ldg(&xyz[((size_t)bn * Nn + sn) * 3 + 0]);
            qyn = __ldg(&xyz[((size_t)bn * Nn + sn) * 3 + 1]);
            qzn = __ldg(&xyz[((size_t)bn * Nn + sn) * 3 + 2]);
        }

        // ================== stage A row (LDG.128 x8) ==================
        {
            const float* xb = xyz + (size_t)b * Nn * 3;
            __half* arow = Ah + tid * A_STR;
            const uint4* src = (const uint4*)(g_featTh + ((size_t)b * Nn + myid) * Cn);
            uint4* dst = (uint4*)arow;
            #pragma unroll
            for (int j = 0; j < 8; j++) dst[j] = __ldg(&src[j]);
            arow[64] = __float2half_rn(__ldg(&xb[myid * 3 + 0]) - qx);
            arow[65] = __float2half_rn(__ldg(&xb[myid * 3 + 1]) - qy);
            arow[66] = __float2half_rn(__ldg(&xb[myid * 3 + 2]) - qz);
        }
        __syncwarp();

        // ================== Layer 1 (K=80 -> 5 k-groups) ==================
        float c1[2][8][4];
        #pragma unroll
        for (int nt = 0; nt < 8; nt++) {
            float blo = b1s[nt * 8 + 2 * kk];
            float bhi = b1s[nt * 8 + 2 * kk + 1];
            #pragma unroll
            for (int mt = 0; mt < 2; mt++) {
                c1[mt][nt][0] = blo; c1[mt][nt][1] = bhi;
                c1[mt][nt][2] = blo; c1[mt][nt][3] = bhi;
            }
        }

        #pragma unroll
        for (int kg = 0; kg < 5; kg++) {
            unsigned a0[4], a1[4];
            ldsm4(a0, aBase0 + kg * 32);
            ldsm4(a1, aBase1 + kg * 32);
            #pragma unroll
            for (int p = 0; p < 4; p++) {
                unsigned bf[4];
                ldsm4(bf, w1Base + (unsigned)(16 * p * W1_STR * 2) + kg * 32);
                mma_f16(c1[0][2 * p],     a0, bf[0], bf[2]);
                mma_f16(c1[0][2 * p + 1], a0, bf[1], bf[3]);
                mma_f16(c1[1][2 * p],     a1, bf[0], bf[2]);
                mma_f16(c1[1][2 * p + 1], a1, bf[1], bf[3]);
            }
        }
        __syncwarp();

        // ---- pipeline: issue NEXT query's descriptor gather (point arrived) ----
        int stLn = 0, cntLn = 0, ncellsn = 0;
        if (gqn < NQ) {
            const int bn = gqn >> 11;
            const int cx = min(GRID - 1, max(0, (int)(qxn * (float)GRID)));
            const int cy = min(GRID - 1, max(0, (int)(qyn * (float)GRID)));
            const int cz = min(GRID - 1, max(0, (int)(qzn * (float)GRID)));
            const int x0 = max(cx - 1, 0), x1 = min(cx + 1, GRID - 1);
            const int y0 = max(cy - 1, 0), y1 = min(cy + 1, GRID - 1);
            const int z0 = max(cz - 1, 0), z1 = min(cz + 1, GRID - 1);
            const int nx = x1 - x0 + 1, ny = y1 - y0 + 1, nz = z1 - z0 + 1;
            ncellsn = nx * ny * nz;
            if (lane < ncellsn) {
                int lx = lane % nx, rem = lane / nx;
                int ly = rem % ny, lz = rem / ny;
                int c = bn * NCELL + (x0 + lx) + GRID * ((y0 + ly) + GRID * (z0 + lz));
                stLn  = __ldg(&cellStart[c]);
                cntLn = __ldg(&cellCount[c]);
            }
        }

        // store relu(h1) fp16 into warp-local A rows (cols 0..63)
        #pragma unroll
        for (int mt = 0; mt < 2; mt++)
            #pragma unroll
            for (int nt = 0; nt < 8; nt++)
                #pragma unroll
                for (int i = 0; i < 2; i++) {
                    int row = rowbase + mt * 16 + r + 8 * i;
                    unsigned pk = h2pack(fmaxf(c1[mt][nt][2 * i + 0], 0.0f),
                                         fmaxf(c1[mt][nt][2 * i + 1], 0.0f));
                    *(unsigned*)&Ah[row * A_STR + nt * 8 + 2 * kk] = pk;
                }
        __syncwarp();

        // hoist L2 A fragments (K=64 -> 4 k-groups)
        unsigned afrag[4][8];
        #pragma unroll
        for (int kg = 0; kg < 4; kg++) {
            ldsm4(&afrag[kg][0], aBase0 + kg * 32);
            ldsm4(&afrag[kg][4], aBase1 + kg * 32);
        }

        float* op_base = out + (Bn * NP * 3) + (size_t)b * H2n * NP + s;

        #pragma unroll
        for (int h = 0; h < 2; h++) {
            float c2[2][8][4];
            #pragma unroll
            for (int nt = 0; nt < 8; nt++) {
                int o = h * 64 + nt * 8;
                float blo = b2s[o + 2 * kk];
                float bhi = b2s[o + 2 * kk + 1];
                #pragma unroll
                for (int mt = 0; mt < 2; mt++) {
                    c2[mt][nt][0] = blo; c2[mt][nt][1] = bhi;
                    c2[mt][nt][2] = blo; c2[mt][nt][3] = bhi;
                }
            }

            #pragma unroll
            for (int kg = 0; kg < 4; kg++) {
                #pragma unroll
                for (int p = 0; p < 4; p++) {
                    unsigned bf[4];
                    ldsm4(bf, w2Base + (unsigned)(16 * (h * 4 + p) * W2_STR * 2) + kg * 32);
                    mma_f16(c2[0][2 * p],     &afrag[kg][0], bf[0], bf[2]);
                    mma_f16(c2[0][2 * p + 1], &afrag[kg][0], bf[1], bf[3]);
                    mma_f16(c2[1][2 * p],     &afrag[kg][4], bf[0], bf[2]);
                    mma_f16(c2[1][2 * p + 1], &afrag[kg][4], bf[1], bf[3]);
                }
            }

            #pragma unroll
            for (int nt = 0; nt < 8; nt++)
                #pragma unroll
                for (int j = 0; j < 2; j++) {
                    float v = fmaxf(fmaxf(c2[0][nt][j], c2[0][nt][j + 2]),
                                    fmaxf(c2[1][nt][j], c2[1][nt][j + 2]));
                    v = fmaxf(v, __shfl_xor_sync(0xffffffffu, v, 4));
                    v = fmaxf(v, __shfl_xor_sync(0xffffffffu, v, 8));
                    v = fmaxf(v, __shfl_xor_sync(0xffffffffu, v, 16));
                    if (r == 0) {
                        int col = h * 64 + nt * 8 + 2 * kk + j;
                        op_base[(size_t)col * NP] = fmaxf(v, 0.0f);
                    }
                }
        }
        __syncwarp();   // h1/A reads done before next iteration restages

        // ---- rotate pipeline registers ----
        qx = qxn; qy = qyn; qz = qzn;
        stL = stLn; cntL = cntLn; ncells = ncellsn;
    }
}

// ---------------------------------------------------------------------------
extern "C" void kernel_launch(void* const* d_in, const int* in_sizes, int n_in,
                              void* d_out, int out_size)
{
    const float* xyz      = (const float*)d_in[0];
    const float* features = (const float*)d_in[1];
    const float* W1       = (const float*)d_in[2];
    const float* b1       = (const float*)d_in[3];
    const float* W2       = (const float*)d_in[4];
    const float* b2       = (const float*)d_in[5];
    float* out = (float*)d_out;

    static bool init_done = false;
    static cudaStream_t s2;
    static cudaEvent_t eFork, eJoin;
    if (!init_done) {
        cudaFuncSetAttribute(fused_kernel, cudaFuncAttributeMaxDynamicSharedMemorySize,
                             SMEM_BYTES);
        cudaStreamCreateWithFlags(&s2, cudaStreamNonBlocking);
        cudaEventCreateWithFlags(&eFork, cudaEventDisableTiming);
        cudaEventCreateWithFlags(&eJoin, cudaEventDisableTiming);
        init_done = true;
    }

    __half* fthp;   cudaGetSymbolAddress((void**)&fthp, g_featTh);
    float4* ptsp;   cudaGetSymbolAddress((void**)&ptsp, g_pts);
    int*    cntp;   cudaGetSymbolAddress((void**)&cntp, g_cellCount);
    int*    stp;    cudaGetSymbolAddress((void**)&stp,  g_cellStart);

    // Fork: transpose (depends only on features) on s2, parallel to binning.
    cudaEventRecord(eFork, 0);
    cudaStreamWaitEvent(s2, eFork, 0);
    {
        dim3 blk(256, 1, 1);
        dim3 grd(Nn / 64, Cn / 32, Bn);
        transpose_kernel<<<grd, blk, 0, s2>>>(features, fthp);
    }
    cudaEventRecord(eJoin, s2);

    // Main stream: single-kernel binning
    bin_all_kernel<<<Bn, 1024>>>(xyz, ptsp, stp, cntp);

    // Join, then fused persistent ball-query + MLP + max
    cudaStreamWaitEvent(0, eJoin, 0);
    fused_kernel<<<NCTA, 256, SMEM_BYTES>>>(xyz, ptsp, stp, cntp,
                                            W1, b1, W2, b2, out);
}